// round 3
// baseline (speedup 1.0000x reference)
#include <cuda_runtime.h>
#include <math.h>

#define DIMV 1024
#define HEADS 16
#define DHEAD 64
#define BATCH 16
#define SEQ 512
#define INNERV 1024
#define CPBD 512
#define FFH 2730
#define MROWS (BATCH*SEQ) /* 8192 */
#define EPSV 1e-5f

// ---------------- scratch (static device arrays; no allocations) ----------------
__device__ float g_bias[HEADS * 1023];
__device__ float g_xn[(size_t)MROWS * DIMV];
__device__ float g_q[(size_t)MROWS * INNERV];
__device__ float g_k[(size_t)MROWS * INNERV];
__device__ float g_v[(size_t)MROWS * INNERV];
__device__ float g_sim[(size_t)BATCH * HEADS * SEQ * SEQ];   // 268 MB
__device__ float g_o[(size_t)MROWS * INNERV];
__device__ float g_y[(size_t)MROWS * DIMV];
__device__ float g_t[(size_t)MROWS * FFH];

// ---------------- CPB: bias table over 1023 distinct relative positions ----------
__global__ void cpb_kernel(const float* __restrict__ w1, const float* __restrict__ b1,
                           const float* __restrict__ w2, const float* __restrict__ b2,
                           const float* __restrict__ w3, const float* __restrict__ b3,
                           float* __restrict__ table) {
    int ridx = blockIdx.x;                 // 0..1022
    float rf = (float)(ridx - 511);
    float sgn = (rf > 0.f) ? 1.f : ((rf < 0.f) ? -1.f : 0.f);
    float rel = sgn * logf(fabsf(rf) + 1.f);

    __shared__ float h1[CPBD];
    __shared__ float h2[CPBD];
    int t = threadIdx.x;                   // 512 threads
    {
        float z = rel * w1[t] + b1[t];
        h1[t] = z / (1.f + expf(-z));      // silu
    }
    __syncthreads();
    {
        float acc = b2[t];
        #pragma unroll 4
        for (int j = 0; j < CPBD; j++) acc += h1[j] * w2[j * CPBD + t];
        h2[t] = acc / (1.f + expf(-acc));
    }
    __syncthreads();
    int warp = t >> 5, lane = t & 31;      // warp w -> head w
    float acc = 0.f;
    for (int i = lane; i < CPBD; i += 32) acc += h2[i] * w3[i * HEADS + warp];
    #pragma unroll
    for (int off = 16; off; off >>= 1) acc += __shfl_down_sync(0xffffffffu, acc, off);
    if (lane == 0) table[warp * 1023 + ridx] = acc + b3[warp];
}

// ---------------- sequence-axis LayerNorm: stats over n for each (b,d) -----------
__global__ void seqln_kernel(const float* __restrict__ x, const float* __restrict__ g,
                             float* __restrict__ xn) {
    int d = blockIdx.x * blockDim.x + threadIdx.x;   // 0..1023
    int b = blockIdx.y;
    const float* xb = x + (size_t)b * SEQ * DIMV;
    float s = 0.f, ss = 0.f;
    for (int n = 0; n < SEQ; n++) { float v = xb[n * DIMV + d]; s += v; ss += v * v; }
    float mean = s * (1.f / SEQ);
    float var  = ss * (1.f / SEQ) - mean * mean;
    float inv  = rsqrtf(fmaxf(var, EPSV)) * g[d];
    float* ob = xn + (size_t)b * SEQ * DIMV;
    for (int n = 0; n < SEQ; n++) ob[n * DIMV + d] = (xb[n * DIMV + d] - mean) * inv;
}

// ---------------- softmax over sim row + relative bias ---------------------------
__global__ void softmax_kernel(float* __restrict__ sim, const float* __restrict__ table) {
    int i = blockIdx.x;               // query row 0..511
    int z = blockIdx.y;               // batch*head 0..255
    int h = z & (HEADS - 1);
    float* row = sim + ((size_t)z * SEQ + i) * SEQ;
    const float* tab = table + h * 1023 + (i + 511);  // tab[-j] = table[h][i-j+511]

    __shared__ float sm[SEQ];
    __shared__ float red[256];
    int t = threadIdx.x;              // 256
    float m = -1e30f;
    for (int j = t; j < SEQ; j += 256) { float v = row[j] + tab[-j]; sm[j] = v; m = fmaxf(m, v); }
    red[t] = m; __syncthreads();
    for (int s = 128; s; s >>= 1) { if (t < s) red[t] = fmaxf(red[t], red[t + s]); __syncthreads(); }
    m = red[0]; __syncthreads();
    float sum = 0.f;
    for (int j = t; j < 512; j += 256) { float e = __expf(sm[j] - m); sm[j] = e; sum += e; }
    red[t] = sum; __syncthreads();
    for (int s = 128; s; s >>= 1) { if (t < s) red[t] += red[t + s]; __syncthreads(); }
    float inv = 1.f / red[0];
    for (int j = t; j < SEQ; j += 256) row[j] = sm[j] * inv;
}

// ---------------- channel LayerNorm over FFH per token, gain ff_g ----------------
__global__ void chanln_kernel(float* __restrict__ tb, const float* __restrict__ gg) {
    int m = blockIdx.x;
    float* row = tb + (size_t)m * FFH;
    int t = threadIdx.x;              // 256
    float s = 0.f, ss = 0.f;
    for (int j = t; j < FFH; j += 256) { float v = row[j]; s += v; ss += v * v; }
    __shared__ float r1[256], r2[256];
    r1[t] = s; r2[t] = ss; __syncthreads();
    for (int k = 128; k; k >>= 1) { if (t < k) { r1[t] += r1[t + k]; r2[t] += r2[t + k]; } __syncthreads(); }
    float mean = r1[0] * (1.f / FFH);
    float var  = r2[0] * (1.f / FFH) - mean * mean;
    float inv  = rsqrtf(fmaxf(var, EPSV));
    for (int j = t; j < FFH; j += 256) row[j] = (row[j] - mean) * inv * gg[j];
}

// ---------------- templated SGEMM --------------------------------------------
// EPI: 0 = C[z*sC + m*ldc + n] = v
//      1 = C[m*ldc + n] = v + R[m*ldc + n]
//      2 = head-split store for q/k/v: out[((b*H+h)*SEQ+n)*64+d]
//      3 = attention output store:   out[(b*SEQ+m)*INNER + h*64 + n]
template<int BM, int BN, int BK, int TM, int TN, bool TRANSB, int EPI>
__global__ __launch_bounds__((BM / TM) * (BN / TN))
void sgemm(const float* __restrict__ A, const float* __restrict__ B,
           float* __restrict__ C, const float* __restrict__ R,
           int M, int Nn, int K, int lda, int ldb, int ldc,
           long long sA, long long sB, long long sC, float alpha) {
    constexpr int THREADS = (BM / TM) * (BN / TN);
    __shared__ float As[BK][BM + 1];
    __shared__ float Bs[BK][BN + 1];
    const int z = blockIdx.z;
    A += (long long)z * sA;
    B += (long long)z * sB;
    const int m0 = blockIdx.y * BM;
    const int n0 = blockIdx.x * BN;
    const int tid = threadIdx.x;
    const int trow = tid / (BN / TN);
    const int tcol = tid % (BN / TN);

    float acc[TM][TN];
    #pragma unroll
    for (int i = 0; i < TM; i++)
        #pragma unroll
        for (int j = 0; j < TN; j++) acc[i][j] = 0.f;

    for (int k0 = 0; k0 < K; k0 += BK) {
        #pragma unroll
        for (int idx = tid; idx < BM * BK; idx += THREADS) {
            int r = idx / BK, c = idx % BK;
            int gm = m0 + r, gk = k0 + c;
            As[c][r] = (gm < M && gk < K) ? A[(long long)gm * lda + gk] : 0.f;
        }
        if (!TRANSB) {
            #pragma unroll
            for (int idx = tid; idx < BK * BN; idx += THREADS) {
                int r = idx / BN, c = idx % BN;
                int gk = k0 + r, gn = n0 + c;
                Bs[r][c] = (gk < K && gn < Nn) ? B[(long long)gk * ldb + gn] : 0.f;
            }
        } else {
            #pragma unroll
            for (int idx = tid; idx < BK * BN; idx += THREADS) {
                int nn = idx / BK, kk = idx % BK;
                int gn = n0 + nn, gk = k0 + kk;
                Bs[kk][nn] = (gn < Nn && gk < K) ? B[(long long)gn * ldb + gk] : 0.f;
            }
        }
        __syncthreads();
        #pragma unroll
        for (int kk = 0; kk < BK; kk++) {
            float af[TM], bf[TN];
            #pragma unroll
            for (int i = 0; i < TM; i++) af[i] = As[kk][trow * TM + i];
            #pragma unroll
            for (int j = 0; j < TN; j++) bf[j] = Bs[kk][tcol * TN + j];
            #pragma unroll
            for (int i = 0; i < TM; i++)
                #pragma unroll
                for (int j = 0; j < TN; j++) acc[i][j] += af[i] * bf[j];
        }
        __syncthreads();
    }

    #pragma unroll
    for (int i = 0; i < TM; i++) {
        int m = m0 + trow * TM + i;
        #pragma unroll
        for (int j = 0; j < TN; j++) {
            int n = n0 + tcol * TN + j;
            if (m < M && n < Nn) {
                float v = acc[i][j] * alpha;
                if (EPI == 0) {
                    C[(long long)z * sC + (long long)m * ldc + n] = v;
                } else if (EPI == 1) {
                    C[(long long)m * ldc + n] = v + R[(long long)m * ldc + n];
                } else if (EPI == 2) {
                    int b = m >> 9, nn = m & (SEQ - 1), h = n >> 6, d = n & (DHEAD - 1);
                    C[((((long long)b * HEADS + h) * SEQ + nn) << 6) + d] = v;
                } else { // EPI == 3
                    int b = z >> 4, h = z & (HEADS - 1);
                    C[((long long)(b * SEQ + m) * INNERV) + h * DHEAD + n] = v;
                }
            }
        }
    }
}

// ---------------- FF-in GEMM with fused GEGLU (two NT B tiles) -------------------
// A is [M, K] row-major with lda == K (y buffer). B is ff_w_in [2*FFH, K] row-major,
// accessed NT: Bs1 row gn, Bs2 row gn+FFH.
template<int BM, int BN, int BK, int TM, int TN>
__global__ __launch_bounds__((BM / TM) * (BN / TN))
void sgemm_geglu(const float* __restrict__ A, const float* __restrict__ B,
                 float* __restrict__ C, int M, int Nn, int K, int ldb) {
    constexpr int THREADS = (BM / TM) * (BN / TN);
    __shared__ float As[BK][BM + 1];
    __shared__ float Bs1[BK][BN + 1];
    __shared__ float Bs2[BK][BN + 1];
    const int m0 = blockIdx.y * BM;
    const int n0 = blockIdx.x * BN;
    const int tid = threadIdx.x;
    const int trow = tid / (BN / TN);
    const int tcol = tid % (BN / TN);

    float a1[TM][TN], a2[TM][TN];
    #pragma unroll
    for (int i = 0; i < TM; i++)
        #pragma unroll
        for (int j = 0; j < TN; j++) { a1[i][j] = 0.f; a2[i][j] = 0.f; }

    for (int k0 = 0; k0 < K; k0 += BK) {
        #pragma unroll
        for (int idx = tid; idx < BM * BK; idx += THREADS) {
            int r = idx / BK, c = idx % BK;
            int gm = m0 + r, gk = k0 + c;
            As[c][r] = (gm < M && gk < K) ? A[(long long)gm * K + gk] : 0.f;
        }
        #pragma unroll
        for (int idx = tid; idx < BK * BN; idx += THREADS) {
            int nn = idx / BK, kk = idx % BK;
            int gn = n0 + nn, gk = k0 + kk;
            bool ok = (gn < Nn && gk < K);
            Bs1[kk][nn] = ok ? B[(long long)gn * ldb + gk] : 0.f;
            Bs2[kk][nn] = ok ? B[(long long)(gn + FFH) * ldb + gk] : 0.f;
        }
        __syncthreads();
        #pragma unroll
        for (int kk = 0; kk < BK; kk++) {
            float af[TM], b1f[TN], b2f[TN];
            #pragma unroll
            for (int i = 0; i < TM; i++) af[i] = As[kk][trow * TM + i];
            #pragma unroll
            for (int j = 0; j < TN; j++) { b1f[j] = Bs1[kk][tcol * TN + j]; b2f[j] = Bs2[kk][tcol * TN + j]; }
            #pragma unroll
            for (int i = 0; i < TM; i++)
                #pragma unroll
                for (int j = 0; j < TN; j++) { a1[i][j] += af[i] * b1f[j]; a2[i][j] += af[i] * b2f[j]; }
        }
        __syncthreads();
    }

    #pragma unroll
    for (int i = 0; i < TM; i++) {
        int m = m0 + trow * TM + i;
        #pragma unroll
        for (int j = 0; j < TN; j++) {
            int n = n0 + tcol * TN + j;
            if (m < M && n < Nn) {
                float g  = a2[i][j];
                float ge = 0.5f * g * (1.f + erff(g * 0.70710678118654752f));  // exact GELU
                C[(long long)m * Nn + n] = a1[i][j] * ge;
            }
        }
    }
}

// ---------------- launch ---------------------------------------------------------
extern "C" void kernel_launch(void* const* d_in, const int* in_sizes, int n_in,
                              void* d_out, int out_size) {
    const float* x      = (const float*)d_in[0];
    const float* g_ln   = (const float*)d_in[1];
    const float* Wq     = (const float*)d_in[2];
    const float* Wkv    = (const float*)d_in[3];
    const float* Wo     = (const float*)d_in[4];
    const float* cpb_w1 = (const float*)d_in[5];
    const float* cpb_b1 = (const float*)d_in[6];
    const float* cpb_w2 = (const float*)d_in[7];
    const float* cpb_b2 = (const float*)d_in[8];
    const float* cpb_w3 = (const float*)d_in[9];
    const float* cpb_b3 = (const float*)d_in[10];
    const float* ff_w_in  = (const float*)d_in[11];
    const float* ff_g     = (const float*)d_in[12];
    const float* ff_w_out = (const float*)d_in[13];
    float* out = (float*)d_out;

    float *bias, *xn, *q, *k, *v, *sim, *o, *y, *t;
    cudaGetSymbolAddress((void**)&bias, g_bias);
    cudaGetSymbolAddress((void**)&xn,  g_xn);
    cudaGetSymbolAddress((void**)&q,   g_q);
    cudaGetSymbolAddress((void**)&k,   g_k);
    cudaGetSymbolAddress((void**)&v,   g_v);
    cudaGetSymbolAddress((void**)&sim, g_sim);
    cudaGetSymbolAddress((void**)&o,   g_o);
    cudaGetSymbolAddress((void**)&y,   g_y);
    cudaGetSymbolAddress((void**)&t,   g_t);

    // 1) CPB bias table (1023 distinct relative positions)
    cpb_kernel<<<1023, 512>>>(cpb_w1, cpb_b1, cpb_w2, cpb_b2, cpb_w3, cpb_b3, bias);

    // 2) sequence-axis LayerNorm
    seqln_kernel<<<dim3(DIMV / 256, BATCH), 256>>>(x, g_ln, xn);

    // 3) Q/K/V projections, head-split stores ([b,h,n,d])
    sgemm<128,128,16,8,8,false,2><<<dim3(8,64,1),256>>>(xn, Wq,          q, nullptr,
        MROWS, INNERV, DIMV, DIMV, INNERV,     0, 0, 0, 0, 1.f);
    sgemm<128,128,16,8,8,false,2><<<dim3(8,64,1),256>>>(xn, Wkv,         k, nullptr,
        MROWS, INNERV, DIMV, DIMV, 2*INNERV,   0, 0, 0, 0, 1.f);
    sgemm<128,128,16,8,8,false,2><<<dim3(8,64,1),256>>>(xn, Wkv+INNERV,  v, nullptr,
        MROWS, INNERV, DIMV, DIMV, 2*INNERV,   0, 0, 0, 0, 1.f);

    // 4) sim = scale * Q Kᵀ  (batched NT, 256 batches)
    sgemm<128,128,16,8,8,true,0><<<dim3(4,4,BATCH*HEADS),256>>>(q, k, sim, nullptr,
        SEQ, SEQ, DHEAD, DHEAD, DHEAD, SEQ,
        (long long)SEQ*DHEAD, (long long)SEQ*DHEAD, (long long)SEQ*SEQ, 0.125f);

    // 5) softmax with relative-position bias
    softmax_kernel<<<dim3(SEQ, BATCH*HEADS), 256>>>(sim, bias);

    // 6) O = attn V (batched NN), store into [b,n,h*64+d]
    sgemm<128,64,16,8,4,false,3><<<dim3(1,4,BATCH*HEADS),256>>>(sim, v, o, nullptr,
        SEQ, DHEAD, SEQ, SEQ, DHEAD, 0,
        (long long)SEQ*SEQ, (long long)SEQ*DHEAD, 0, 1.f);

    // 7) y = O @ Wo + x
    sgemm<128,128,16,8,8,false,1><<<dim3(8,64,1),256>>>(o, Wo, y, x,
        MROWS, DIMV, INNERV, INNERV, DIMV, DIMV, 0, 0, 0, 1.f);

    // 8) FF-in + GEGLU fused: t = (y Win_x1ᵀ) * gelu(y Win_gateᵀ)
    sgemm_geglu<128,64,16,8,4><<<dim3((FFH+63)/64, 64), 256>>>(y, ff_w_in, t,
        MROWS, FFH, DIMV, DIMV);

    // 9) channel LayerNorm with gain ff_g (in place)
    chanln_kernel<<<MROWS, 256>>>(t, ff_g);

    // 10) out = t @ ff_w_outᵀ + y
    sgemm<128,128,16,8,8,true,1><<<dim3(8,64,1),256>>>(t, ff_w_out, out, y,
        MROWS, DIMV, FFH, FFH, FFH, DIMV, 0, 0, 0, 1.f);
}

// round 4
// speedup vs baseline: 4.1705x; 4.1705x over previous
#include <cuda_runtime.h>
#include <math.h>
#include <stdint.h>

#define DIMV 1024
#define HEADS 16
#define DHEAD 64
#define BATCH 16
#define SEQ 512
#define INNERV 1024
#define CPBD 512
#define FFH 2730
#define MROWS (BATCH*SEQ) /* 8192 */
#define EPSV 1e-5f

// ---------------- scratch (static device arrays; no allocations) ----------------
__device__ float g_bias[HEADS * 1023];
__device__ float g_xn[(size_t)MROWS * DIMV];
__device__ float g_q[(size_t)MROWS * INNERV];
__device__ float g_k[(size_t)MROWS * INNERV];
__device__ float g_v[(size_t)MROWS * INNERV];
__device__ float g_sim[(size_t)BATCH * HEADS * SEQ * SEQ];   // 268 MB
__device__ float g_o[(size_t)MROWS * INNERV];
__device__ float g_y[(size_t)MROWS * DIMV];
__device__ float g_t[(size_t)MROWS * FFH];

// ---------------- tf32 helpers ----------------------------------------------------
__device__ __forceinline__ float cvt_tf32(float x) {
    uint32_t u; asm("cvt.rna.tf32.f32 %0, %1;" : "=r"(u) : "f"(x));
    return __uint_as_float(u);
}
__device__ __forceinline__ void mma_tf32(float d[4], const uint32_t a[4], const uint32_t b[2]) {
    asm volatile(
        "mma.sync.aligned.m16n8k8.row.col.f32.tf32.tf32.f32 "
        "{%0,%1,%2,%3},{%4,%5,%6,%7},{%8,%9},{%0,%1,%2,%3};\n"
        : "+f"(d[0]), "+f"(d[1]), "+f"(d[2]), "+f"(d[3])
        : "r"(a[0]), "r"(a[1]), "r"(a[2]), "r"(a[3]), "r"(b[0]), "r"(b[1]));
}

// ---------------- CPB: bias table over 1023 distinct relative positions ----------
__global__ void cpb_kernel(const float* __restrict__ w1, const float* __restrict__ b1,
                           const float* __restrict__ w2, const float* __restrict__ b2,
                           const float* __restrict__ w3, const float* __restrict__ b3,
                           float* __restrict__ table) {
    int ridx = blockIdx.x;                 // 0..1022
    float rf = (float)(ridx - 511);
    float sgn = (rf > 0.f) ? 1.f : ((rf < 0.f) ? -1.f : 0.f);
    float rel = sgn * logf(fabsf(rf) + 1.f);

    __shared__ float h1[CPBD];
    __shared__ float h2[CPBD];
    int t = threadIdx.x;                   // 512 threads
    {
        float z = rel * w1[t] + b1[t];
        h1[t] = z / (1.f + expf(-z));      // silu
    }
    __syncthreads();
    {
        float acc = b2[t];
        #pragma unroll 4
        for (int j = 0; j < CPBD; j++) acc += h1[j] * w2[j * CPBD + t];
        h2[t] = acc / (1.f + expf(-acc));
    }
    __syncthreads();
    int warp = t >> 5, lane = t & 31;      // warp w -> head w
    float acc = 0.f;
    for (int i = lane; i < CPBD; i += 32) acc += h2[i] * w3[i * HEADS + warp];
    #pragma unroll
    for (int off = 16; off; off >>= 1) acc += __shfl_down_sync(0xffffffffu, acc, off);
    if (lane == 0) table[warp * 1023 + ridx] = acc + b3[warp];
}

// ---------------- sequence-axis LayerNorm: stats over n for each (b,d) -----------
__global__ void seqln_kernel(const float* __restrict__ x, const float* __restrict__ g,
                             float* __restrict__ xn) {
    int d = blockIdx.x * blockDim.x + threadIdx.x;   // 0..1023
    int b = blockIdx.y;
    const float* xb = x + (size_t)b * SEQ * DIMV;
    float s = 0.f, ss = 0.f;
    for (int n = 0; n < SEQ; n++) { float v = xb[n * DIMV + d]; s += v; ss += v * v; }
    float mean = s * (1.f / SEQ);
    float var  = ss * (1.f / SEQ) - mean * mean;
    float inv  = rsqrtf(fmaxf(var, EPSV)) * g[d];
    float* ob = xn + (size_t)b * SEQ * DIMV;
    for (int n = 0; n < SEQ; n++) ob[n * DIMV + d] = (xb[n * DIMV + d] - mean) * inv;
}

// ---------------- softmax over sim row + relative bias ---------------------------
__global__ void softmax_kernel(float* __restrict__ sim, const float* __restrict__ table) {
    int i = blockIdx.x;               // query row 0..511
    int z = blockIdx.y;               // batch*head 0..255
    int h = z & (HEADS - 1);
    float* row = sim + ((size_t)z * SEQ + i) * SEQ;
    const float* tab = table + h * 1023 + (i + 511);  // tab[-j] = table[h][i-j+511]

    __shared__ float sm[SEQ];
    __shared__ float red[256];
    int t = threadIdx.x;              // 256
    float m = -1e30f;
    for (int j = t; j < SEQ; j += 256) { float v = row[j] + tab[-j]; sm[j] = v; m = fmaxf(m, v); }
    red[t] = m; __syncthreads();
    for (int s = 128; s; s >>= 1) { if (t < s) red[t] = fmaxf(red[t], red[t + s]); __syncthreads(); }
    m = red[0]; __syncthreads();
    float sum = 0.f;
    for (int j = t; j < SEQ; j += 256) { float e = __expf(sm[j] - m); sm[j] = e; sum += e; }
    red[t] = sum; __syncthreads();
    for (int s = 128; s; s >>= 1) { if (t < s) red[t] += red[t + s]; __syncthreads(); }
    float inv = 1.f / red[0];
    for (int j = t; j < SEQ; j += 256) row[j] = sm[j] * inv;
}

// ---------------- channel LayerNorm over FFH per token, gain ff_g ----------------
__global__ void chanln_kernel(float* __restrict__ tb, const float* __restrict__ gg) {
    int m = blockIdx.x;
    float* row = tb + (size_t)m * FFH;
    int t = threadIdx.x;              // 256
    float s = 0.f, ss = 0.f;
    for (int j = t; j < FFH; j += 256) { float v = row[j]; s += v; ss += v * v; }
    __shared__ float r1[256], r2[256];
    r1[t] = s; r2[t] = ss; __syncthreads();
    for (int k = 128; k; k >>= 1) { if (t < k) { r1[t] += r1[t + k]; r2[t] += r2[t + k]; } __syncthreads(); }
    float mean = r1[0] * (1.f / FFH);
    float var  = r2[0] * (1.f / FFH) - mean * mean;
    float inv  = rsqrtf(fmaxf(var, EPSV));
    for (int j = t; j < FFH; j += 256) row[j] = (row[j] - mean) * inv * gg[j];
}

// ---------------- tf32 tensor-core GEMM -------------------------------------------
// 256 threads = 8 warps. Warp tile WM x WN, mma tiles m16n8k8.
// EPI: 0 = C[z*sC + m*ldc + n] = v
//      1 = C[m*ldc + n] = v + R[m*ldc + n]
//      2 = head-split store for q/k/v: out[((b*H+h)*SEQ+n)*64+d]
//      3 = attention output store:   out[(b*SEQ+m)*INNER + h*64 + n]
template<int BM, int BN, int BK, int WM, int WN, bool TRANSB, int EPI>
__global__ __launch_bounds__(256, 2)
void tgemm(const float* __restrict__ A, const float* __restrict__ B,
           float* __restrict__ C, const float* __restrict__ R,
           int M, int Nn, int K, int lda, int ldb, int ldc,
           long long sA, long long sB, long long sC, float alpha) {
    constexpr int WARPS_N = BN / WN;
    constexpr int MT = WM / 16;
    constexpr int NT = WN / 8;
    __shared__ float As[BK][BM + 8];
    __shared__ float Bs[BK][BN + 8];

    const int z = blockIdx.z;
    A += (long long)z * sA;
    B += (long long)z * sB;
    const int m0 = blockIdx.y * BM;
    const int n0 = blockIdx.x * BN;
    const int tid = threadIdx.x;
    const int warp = tid >> 5, lane = tid & 31;
    const int wr = warp / WARPS_N, wc = warp % WARPS_N;
    const int gid = lane >> 2, tg = lane & 3;

    float acc[MT][NT][4];
    #pragma unroll
    for (int i = 0; i < MT; i++)
        #pragma unroll
        for (int j = 0; j < NT; j++)
            #pragma unroll
            for (int e = 0; e < 4; e++) acc[i][j][e] = 0.f;

    for (int k0 = 0; k0 < K; k0 += BK) {
        #pragma unroll
        for (int idx = tid; idx < BM * BK; idx += 256) {
            int r = idx / BK, c = idx % BK;
            int gm = m0 + r, gk = k0 + c;
            As[c][r] = (gm < M && gk < K) ? cvt_tf32(A[(long long)gm * lda + gk]) : 0.f;
        }
        if (!TRANSB) {
            #pragma unroll
            for (int idx = tid; idx < BK * BN; idx += 256) {
                int r = idx / BN, c = idx % BN;
                int gk = k0 + r, gn = n0 + c;
                Bs[r][c] = (gk < K && gn < Nn) ? cvt_tf32(B[(long long)gk * ldb + gn]) : 0.f;
            }
        } else {
            #pragma unroll
            for (int idx = tid; idx < BK * BN; idx += 256) {
                int nn = idx / BK, kk = idx % BK;
                int gn = n0 + nn, gk = k0 + kk;
                Bs[kk][nn] = (gn < Nn && gk < K) ? cvt_tf32(B[(long long)gn * ldb + gk]) : 0.f;
            }
        }
        __syncthreads();

        #pragma unroll
        for (int ks = 0; ks < BK; ks += 8) {
            uint32_t af[MT][4];
            uint32_t bf[NT][2];
            #pragma unroll
            for (int i = 0; i < MT; i++) {
                int mb = wr * WM + i * 16 + gid;
                af[i][0] = __float_as_uint(As[ks + tg    ][mb    ]);
                af[i][1] = __float_as_uint(As[ks + tg    ][mb + 8]);
                af[i][2] = __float_as_uint(As[ks + tg + 4][mb    ]);
                af[i][3] = __float_as_uint(As[ks + tg + 4][mb + 8]);
            }
            #pragma unroll
            for (int j = 0; j < NT; j++) {
                int nb = wc * WN + j * 8 + gid;
                bf[j][0] = __float_as_uint(Bs[ks + tg    ][nb]);
                bf[j][1] = __float_as_uint(Bs[ks + tg + 4][nb]);
            }
            #pragma unroll
            for (int i = 0; i < MT; i++)
                #pragma unroll
                for (int j = 0; j < NT; j++)
                    mma_tf32(acc[i][j], af[i], bf[j]);
        }
        __syncthreads();
    }

    // epilogue: c0 -> (m,n), c1 -> (m,n+1), c2 -> (m+8,n), c3 -> (m+8,n+1)
    #pragma unroll
    for (int i = 0; i < MT; i++) {
        #pragma unroll
        for (int j = 0; j < NT; j++) {
            #pragma unroll
            for (int e = 0; e < 4; e++) {
                int m = m0 + wr * WM + i * 16 + gid + ((e >= 2) ? 8 : 0);
                int n = n0 + wc * WN + j * 8 + 2 * tg + (e & 1);
                if (m < M && n < Nn) {
                    float v = acc[i][j][e] * alpha;
                    if (EPI == 0) {
                        C[(long long)z * sC + (long long)m * ldc + n] = v;
                    } else if (EPI == 1) {
                        C[(long long)m * ldc + n] = v + R[(long long)m * ldc + n];
                    } else if (EPI == 2) {
                        int b = m >> 9, nn = m & (SEQ - 1), h = n >> 6, d = n & (DHEAD - 1);
                        C[((((long long)b * HEADS + h) * SEQ + nn) << 6) + d] = v;
                    } else { // EPI == 3
                        int b = z >> 4, h = z & (HEADS - 1);
                        C[((long long)(b * SEQ + m) * INNERV) + h * DHEAD + n] = v;
                    }
                }
            }
        }
    }
}

// ---------------- tf32 GEMM with fused GEGLU (two NT B tiles) ---------------------
// A [M,K] row-major, lda = K.  B = ff_w_in [2*FFH, K] row-major, NT access.
template<int BM, int BN, int BK, int WM, int WN>
__global__ __launch_bounds__(256, 2)
void tgemm_geglu(const float* __restrict__ A, const float* __restrict__ B,
                 float* __restrict__ C, int M, int Nn, int K, int ldb) {
    constexpr int WARPS_N = BN / WN;
    constexpr int MT = WM / 16;
    constexpr int NT = WN / 8;
    __shared__ float As[BK][BM + 8];
    __shared__ float Bs1[BK][BN + 8];
    __shared__ float Bs2[BK][BN + 8];

    const int m0 = blockIdx.y * BM;
    const int n0 = blockIdx.x * BN;
    const int tid = threadIdx.x;
    const int warp = tid >> 5, lane = tid & 31;
    const int wr = warp / WARPS_N, wc = warp % WARPS_N;
    const int gid = lane >> 2, tg = lane & 3;

    float a1[MT][NT][4], a2[MT][NT][4];
    #pragma unroll
    for (int i = 0; i < MT; i++)
        #pragma unroll
        for (int j = 0; j < NT; j++)
            #pragma unroll
            for (int e = 0; e < 4; e++) { a1[i][j][e] = 0.f; a2[i][j][e] = 0.f; }

    for (int k0 = 0; k0 < K; k0 += BK) {
        #pragma unroll
        for (int idx = tid; idx < BM * BK; idx += 256) {
            int r = idx / BK, c = idx % BK;
            int gm = m0 + r, gk = k0 + c;
            As[c][r] = (gm < M && gk < K) ? cvt_tf32(A[(long long)gm * K + gk]) : 0.f;
        }
        #pragma unroll
        for (int idx = tid; idx < BK * BN; idx += 256) {
            int nn = idx / BK, kk = idx % BK;
            int gn = n0 + nn, gk = k0 + kk;
            bool ok = (gn < Nn && gk < K);
            Bs1[kk][nn] = ok ? cvt_tf32(B[(long long)gn * ldb + gk]) : 0.f;
            Bs2[kk][nn] = ok ? cvt_tf32(B[(long long)(gn + FFH) * ldb + gk]) : 0.f;
        }
        __syncthreads();

        #pragma unroll
        for (int ks = 0; ks < BK; ks += 8) {
            uint32_t af[MT][4];
            uint32_t bf1[NT][2], bf2[NT][2];
            #pragma unroll
            for (int i = 0; i < MT; i++) {
                int mb = wr * WM + i * 16 + gid;
                af[i][0] = __float_as_uint(As[ks + tg    ][mb    ]);
                af[i][1] = __float_as_uint(As[ks + tg    ][mb + 8]);
                af[i][2] = __float_as_uint(As[ks + tg + 4][mb    ]);
                af[i][3] = __float_as_uint(As[ks + tg + 4][mb + 8]);
            }
            #pragma unroll
            for (int j = 0; j < NT; j++) {
                int nb = wc * WN + j * 8 + gid;
                bf1[j][0] = __float_as_uint(Bs1[ks + tg    ][nb]);
                bf1[j][1] = __float_as_uint(Bs1[ks + tg + 4][nb]);
                bf2[j][0] = __float_as_uint(Bs2[ks + tg    ][nb]);
                bf2[j][1] = __float_as_uint(Bs2[ks + tg + 4][nb]);
            }
            #pragma unroll
            for (int i = 0; i < MT; i++)
                #pragma unroll
                for (int j = 0; j < NT; j++) {
                    mma_tf32(a1[i][j], af[i], bf1[j]);
                    mma_tf32(a2[i][j], af[i], bf2[j]);
                }
        }
        __syncthreads();
    }

    #pragma unroll
    for (int i = 0; i < MT; i++) {
        #pragma unroll
        for (int j = 0; j < NT; j++) {
            #pragma unroll
            for (int e = 0; e < 4; e++) {
                int m = m0 + wr * WM + i * 16 + gid + ((e >= 2) ? 8 : 0);
                int n = n0 + wc * WN + j * 8 + 2 * tg + (e & 1);
                if (m < M && n < Nn) {
                    float g  = a2[i][j][e];
                    float ge = 0.5f * g * (1.f + erff(g * 0.70710678118654752f));  // exact GELU
                    C[(long long)m * Nn + n] = a1[i][j][e] * ge;
                }
            }
        }
    }
}

// ---------------- launch ---------------------------------------------------------
extern "C" void kernel_launch(void* const* d_in, const int* in_sizes, int n_in,
                              void* d_out, int out_size) {
    const float* x      = (const float*)d_in[0];
    const float* g_ln   = (const float*)d_in[1];
    const float* Wq     = (const float*)d_in[2];
    const float* Wkv    = (const float*)d_in[3];
    const float* Wo     = (const float*)d_in[4];
    const float* cpb_w1 = (const float*)d_in[5];
    const float* cpb_b1 = (const float*)d_in[6];
    const float* cpb_w2 = (const float*)d_in[7];
    const float* cpb_b2 = (const float*)d_in[8];
    const float* cpb_w3 = (const float*)d_in[9];
    const float* cpb_b3 = (const float*)d_in[10];
    const float* ff_w_in  = (const float*)d_in[11];
    const float* ff_g     = (const float*)d_in[12];
    const float* ff_w_out = (const float*)d_in[13];
    float* out = (float*)d_out;

    float *bias, *xn, *q, *k, *v, *sim, *o, *y, *t;
    cudaGetSymbolAddress((void**)&bias, g_bias);
    cudaGetSymbolAddress((void**)&xn,  g_xn);
    cudaGetSymbolAddress((void**)&q,   g_q);
    cudaGetSymbolAddress((void**)&k,   g_k);
    cudaGetSymbolAddress((void**)&v,   g_v);
    cudaGetSymbolAddress((void**)&sim, g_sim);
    cudaGetSymbolAddress((void**)&o,   g_o);
    cudaGetSymbolAddress((void**)&y,   g_y);
    cudaGetSymbolAddress((void**)&t,   g_t);

    // 1) CPB bias table (1023 distinct relative positions)
    cpb_kernel<<<1023, 512>>>(cpb_w1, cpb_b1, cpb_w2, cpb_b2, cpb_w3, cpb_b3, bias);

    // 2) sequence-axis LayerNorm
    seqln_kernel<<<dim3(DIMV / 256, BATCH), 256>>>(x, g_ln, xn);

    // 3) Q/K/V projections, head-split stores ([b,h,n,d])
    tgemm<128,128,16,64,32,false,2><<<dim3(8,64,1),256>>>(xn, Wq,         q, nullptr,
        MROWS, INNERV, DIMV, DIMV, INNERV,   0, 0, 0, 0, 1.f);
    tgemm<128,128,16,64,32,false,2><<<dim3(8,64,1),256>>>(xn, Wkv,        k, nullptr,
        MROWS, INNERV, DIMV, DIMV, 2*INNERV, 0, 0, 0, 0, 1.f);
    tgemm<128,128,16,64,32,false,2><<<dim3(8,64,1),256>>>(xn, Wkv+INNERV, v, nullptr,
        MROWS, INNERV, DIMV, DIMV, 2*INNERV, 0, 0, 0, 0, 1.f);

    // 4) sim = scale * Q Kᵀ  (batched NT, 256 batches)
    tgemm<128,128,16,64,32,true,0><<<dim3(4,4,BATCH*HEADS),256>>>(q, k, sim, nullptr,
        SEQ, SEQ, DHEAD, DHEAD, DHEAD, SEQ,
        (long long)SEQ*DHEAD, (long long)SEQ*DHEAD, (long long)SEQ*SEQ, 0.125f);

    // 5) softmax with relative-position bias
    softmax_kernel<<<dim3(SEQ, BATCH*HEADS), 256>>>(sim, bias);

    // 6) O = attn V (batched NN), store into [b,n,h*64+d]
    tgemm<128,64,16,32,32,false,3><<<dim3(1,4,BATCH*HEADS),256>>>(sim, v, o, nullptr,
        SEQ, DHEAD, SEQ, SEQ, DHEAD, 0,
        (long long)SEQ*SEQ, (long long)SEQ*DHEAD, 0, 1.f);

    // 7) y = O @ Wo + x
    tgemm<128,128,16,64,32,false,1><<<dim3(8,64,1),256>>>(o, Wo, y, x,
        MROWS, DIMV, INNERV, INNERV, DIMV, DIMV, 0, 0, 0, 1.f);

    // 8) FF-in + GEGLU fused: t = (y Win_x1ᵀ) * gelu(y Win_gateᵀ)
    tgemm_geglu<128,64,16,64,16><<<dim3((FFH+63)/64, 64), 256>>>(y, ff_w_in, t,
        MROWS, FFH, DIMV, DIMV);

    // 9) channel LayerNorm with gain ff_g (in place)
    chanln_kernel<<<MROWS, 256>>>(t, ff_g);

    // 10) out = t @ ff_w_outᵀ + y
    tgemm<128,128,16,64,32,true,1><<<dim3(8,64,1),256>>>(t, ff_w_out, out, y,
        MROWS, DIMV, FFH, FFH, FFH, DIMV, 0, 0, 0, 1.f);
}

// round 5
// speedup vs baseline: 8.1081x; 1.9442x over previous
#include <cuda_runtime.h>
#include <math.h>
#include <stdint.h>

#define DIMV 1024
#define HEADS 16
#define DHEAD 64
#define BATCH 16
#define SEQ 512
#define INNERV 1024
#define CPBD 512
#define FFH 2730
#define LDT 2736            /* padded leading dim for t (16B-aligned rows) */
#define MROWS (BATCH*SEQ)   /* 8192 */
#define EPSV 1e-5f

// ---------------- scratch (static device arrays; no allocations) ----------------
__device__ float g_bias[HEADS * 1023];
__device__ float g_xn[(size_t)MROWS * DIMV];
__device__ float g_q[(size_t)MROWS * INNERV];
__device__ float g_k[(size_t)MROWS * INNERV];
__device__ float g_v[(size_t)MROWS * INNERV];
__device__ float g_sim[(size_t)BATCH * HEADS * SEQ * SEQ];   // 268 MB
__device__ float g_o[(size_t)MROWS * INNERV];
__device__ float g_y[(size_t)MROWS * DIMV];
__device__ float g_t[(size_t)MROWS * LDT];

// ---------------- helpers ---------------------------------------------------------
__device__ __forceinline__ uint32_t tf32b(float x) {
    uint32_t u; asm("cvt.rna.tf32.f32 %0, %1;" : "=r"(u) : "f"(x));
    return u;
}
__device__ __forceinline__ void mma_tf32(float d[4], const uint32_t a[4], const uint32_t b[2]) {
    asm volatile(
        "mma.sync.aligned.m16n8k8.row.col.f32.tf32.tf32.f32 "
        "{%0,%1,%2,%3},{%4,%5,%6,%7},{%8,%9},{%0,%1,%2,%3};\n"
        : "+f"(d[0]), "+f"(d[1]), "+f"(d[2]), "+f"(d[3])
        : "r"(a[0]), "r"(a[1]), "r"(a[2]), "r"(a[3]), "r"(b[0]), "r"(b[1]));
}
__device__ __forceinline__ void cp16(uint32_t s, const float* g, int nb) {
    asm volatile("cp.async.cg.shared.global [%0], [%1], 16, %2;\n" :: "r"(s), "l"(g), "r"(nb));
}
__device__ __forceinline__ void cp8(uint32_t s, const float* g, int nb) {
    asm volatile("cp.async.ca.shared.global [%0], [%1], 8, %2;\n" :: "r"(s), "l"(g), "r"(nb));
}
__device__ __forceinline__ void cp_commit() { asm volatile("cp.async.commit_group;\n"); }
__device__ __forceinline__ void cp_wait1()  { asm volatile("cp.async.wait_group 1;\n"); }
__device__ __forceinline__ void cp_wait0()  { asm volatile("cp.async.wait_group 0;\n"); }

// ---------------- CPB: bias table over 1023 distinct relative positions ----------
__global__ void cpb_kernel(const float* __restrict__ w1, const float* __restrict__ b1,
                           const float* __restrict__ w2, const float* __restrict__ b2,
                           const float* __restrict__ w3, const float* __restrict__ b3,
                           float* __restrict__ table) {
    int ridx = blockIdx.x;                 // 0..1022
    float rf = (float)(ridx - 511);
    float sgn = (rf > 0.f) ? 1.f : ((rf < 0.f) ? -1.f : 0.f);
    float rel = sgn * logf(fabsf(rf) + 1.f);

    __shared__ float h1[CPBD];
    __shared__ float h2[CPBD];
    int t = threadIdx.x;                   // 512 threads
    {
        float z = rel * w1[t] + b1[t];
        h1[t] = z / (1.f + expf(-z));      // silu
    }
    __syncthreads();
    {
        float acc = b2[t];
        #pragma unroll 4
        for (int j = 0; j < CPBD; j++) acc += h1[j] * w2[j * CPBD + t];
        h2[t] = acc / (1.f + expf(-acc));
    }
    __syncthreads();
    int warp = t >> 5, lane = t & 31;      // warp w -> head w
    float acc = 0.f;
    for (int i = lane; i < CPBD; i += 32) acc += h2[i] * w3[i * HEADS + warp];
    #pragma unroll
    for (int off = 16; off; off >>= 1) acc += __shfl_down_sync(0xffffffffu, acc, off);
    if (lane == 0) table[warp * 1023 + ridx] = acc + b3[warp];
}

// ---------------- sequence-axis LayerNorm ----------------------------------------
__global__ void seqln_kernel(const float* __restrict__ x, const float* __restrict__ g,
                             float* __restrict__ xn) {
    int d = blockIdx.x * blockDim.x + threadIdx.x;
    int b = blockIdx.y;
    const float* xb = x + (size_t)b * SEQ * DIMV;
    float s = 0.f, ss = 0.f;
    for (int n = 0; n < SEQ; n++) { float v = xb[n * DIMV + d]; s += v; ss += v * v; }
    float mean = s * (1.f / SEQ);
    float var  = ss * (1.f / SEQ) - mean * mean;
    float inv  = rsqrtf(fmaxf(var, EPSV)) * g[d];
    float* ob = xn + (size_t)b * SEQ * DIMV;
    for (int n = 0; n < SEQ; n++) ob[n * DIMV + d] = (xb[n * DIMV + d] - mean) * inv;
}

// ---------------- softmax over sim row + relative bias ---------------------------
__global__ void softmax_kernel(float* __restrict__ sim, const float* __restrict__ table) {
    int i = blockIdx.x;
    int z = blockIdx.y;
    int h = z & (HEADS - 1);
    float* row = sim + ((size_t)z * SEQ + i) * SEQ;
    const float* tab = table + h * 1023 + (i + 511);

    __shared__ float sm[SEQ];
    __shared__ float red[256];
    int t = threadIdx.x;
    float m = -1e30f;
    for (int j = t; j < SEQ; j += 256) { float v = row[j] + tab[-j]; sm[j] = v; m = fmaxf(m, v); }
    red[t] = m; __syncthreads();
    for (int s = 128; s; s >>= 1) { if (t < s) red[t] = fmaxf(red[t], red[t + s]); __syncthreads(); }
    m = red[0]; __syncthreads();
    float sum = 0.f;
    for (int j = t; j < SEQ; j += 256) { float e = __expf(sm[j] - m); sm[j] = e; sum += e; }
    red[t] = sum; __syncthreads();
    for (int s = 128; s; s >>= 1) { if (t < s) red[t] += red[t + s]; __syncthreads(); }
    float inv = 1.f / red[0];
    for (int j = t; j < SEQ; j += 256) row[j] = sm[j] * inv;
}

// ---------------- channel LayerNorm over FFH per token (stride LDT) --------------
__global__ void chanln_kernel(float* __restrict__ tb, const float* __restrict__ gg) {
    int m = blockIdx.x;
    float* row = tb + (size_t)m * LDT;
    int t = threadIdx.x;
    float s = 0.f, ss = 0.f;
    for (int j = t; j < FFH; j += 256) { float v = row[j]; s += v; ss += v * v; }
    __shared__ float r1[256], r2[256];
    r1[t] = s; r2[t] = ss; __syncthreads();
    for (int k = 128; k; k >>= 1) { if (t < k) { r1[t] += r1[t + k]; r2[t] += r2[t + k]; } __syncthreads(); }
    float mean = r1[0] * (1.f / FFH);
    float var  = r2[0] * (1.f / FFH) - mean * mean;
    float inv  = rsqrtf(fmaxf(var, EPSV));
    for (int j = t; j < FFH; j += 256) row[j] = (row[j] - mean) * inv * gg[j];
}

// ---------------- tf32 tensor-core GEMM, cp.async double-buffered -----------------
// Layouts: As[m][k] stride BK+4; Bs trans: [n][k] stride BK+4; no-trans: [k][n] stride BN+4.
// EPI: 0 = C[z*sC + m*ldc + n]; 1 = +R residual; 2 = q/k/v head-split; 3 = attn-out merge
// RAGK: K not multiple of BK -> cp.async src-size zero-fill. BCP: B chunk bytes (16 or 8).
template<int BM, int BN, int BK, int WM, int WN, bool TRANSB, int EPI, bool RAGK, int BCP>
__global__ __launch_bounds__(256, 2)
void tgemm(const float* __restrict__ A, const float* __restrict__ B,
           float* __restrict__ C, const float* __restrict__ R,
           int M, int Nn, int K, int lda, int ldb, int ldc,
           long long sA, long long sB, long long sC, float alpha) {
    constexpr int WARPS_N = BN / WN;
    constexpr int MT = WM / 16, NT = WN / 8;
    constexpr int AST = BK + 4;
    constexpr int BST = TRANSB ? (BK + 4) : (BN + 4);
    constexpr int ABUF = BM * AST;
    constexpr int BBUF = TRANSB ? BN * BST : BK * BST;

    extern __shared__ float smem[];
    float* Asm = smem;
    float* Bsm = smem + 2 * ABUF;

    const int z = blockIdx.z;
    A += (long long)z * sA;
    B += (long long)z * sB;
    const int m0 = blockIdx.y * BM;
    const int n0 = blockIdx.x * BN;
    const int tid = threadIdx.x;
    const int warp = tid >> 5, lane = tid & 31;
    const int wr = warp / WARPS_N, wc = warp % WARPS_N;
    const int gid = lane >> 2, tg = lane & 3;

    const uint32_t sAb = (uint32_t)__cvta_generic_to_shared(Asm);
    const uint32_t sBb = (uint32_t)__cvta_generic_to_shared(Bsm);

    float acc[MT][NT][4];
    #pragma unroll
    for (int i = 0; i < MT; i++)
        #pragma unroll
        for (int j = 0; j < NT; j++)
            #pragma unroll
            for (int e = 0; e < 4; e++) acc[i][j][e] = 0.f;

    const int NIT = (K + BK - 1) / BK;

    auto stage = [&](int b, int k0) {
        // ---- A: 16B chunks ----
        constexpr int ACH = BK / 4;
        #pragma unroll
        for (int c = tid; c < BM * ACH; c += 256) {
            int m = c / ACH, kc = c % ACH;
            int kk = k0 + kc * 4;
            int nb = 16;
            if (RAGK) { int rem = (K - kk) * 4; nb = rem >= 16 ? 16 : (rem > 0 ? rem : 0); if (nb == 0) kk = k0; }
            uint32_t sp = sAb + (uint32_t)((b * ABUF + m * AST + kc * 4) << 2);
            cp16(sp, A + (long long)(m0 + m) * lda + kk, nb);
        }
        // ---- B ----
        if (TRANSB) {
            if (BCP == 16) {
                constexpr int BCH = BK / 4;
                #pragma unroll
                for (int c = tid; c < BN * BCH; c += 256) {
                    int n = c / BCH, kc = c % BCH;
                    int kk = k0 + kc * 4;
                    int nb = 16;
                    if (RAGK) { int rem = (K - kk) * 4; nb = rem >= 16 ? 16 : (rem > 0 ? rem : 0); if (nb == 0) kk = k0; }
                    uint32_t sp = sBb + (uint32_t)((b * BBUF + n * BST + kc * 4) << 2);
                    cp16(sp, B + (long long)(n0 + n) * ldb + kk, nb);
                }
            } else {
                constexpr int BCH = BK / 2;
                #pragma unroll
                for (int c = tid; c < BN * BCH; c += 256) {
                    int n = c / BCH, kc = c % BCH;
                    int kk = k0 + kc * 2;
                    int nb = 8;
                    if (RAGK) { int rem = (K - kk) * 4; nb = rem >= 8 ? 8 : (rem > 0 ? rem : 0); if (nb == 0) kk = k0; }
                    uint32_t sp = sBb + (uint32_t)((b * BBUF + n * BST + kc * 2) << 2);
                    cp8(sp, B + (long long)(n0 + n) * ldb + kk, nb);
                }
            }
        } else {
            constexpr int BCH = BN / 4;
            #pragma unroll
            for (int c = tid; c < BK * BCH; c += 256) {
                int kk = c / BCH, nc = c % BCH;
                int nb = 16;
                if (RAGK) nb = (k0 + kk < K) ? 16 : 0;
                uint32_t sp = sBb + (uint32_t)((b * BBUF + kk * BST + nc * 4) << 2);
                cp16(sp, B + (long long)(k0 + (nb ? kk : 0)) * ldb + n0 + nc * 4, nb);
            }
        }
    };

    stage(0, 0);
    cp_commit();
    int buf = 0;
    for (int it = 0; it < NIT; it++) {
        if (it + 1 < NIT) {
            stage(buf ^ 1, (it + 1) * BK);
            cp_commit();
            cp_wait1();
        } else {
            cp_wait0();
        }
        __syncthreads();

        const float* Ab = Asm + buf * ABUF;
        const float* Bb = Bsm + buf * BBUF;
        #pragma unroll
        for (int ks = 0; ks < BK; ks += 8) {
            uint32_t af[MT][4];
            uint32_t bf[NT][2];
            #pragma unroll
            for (int i = 0; i < MT; i++) {
                int mb = wr * WM + i * 16 + gid;
                af[i][0] = tf32b(Ab[mb * AST + ks + tg]);
                af[i][1] = tf32b(Ab[(mb + 8) * AST + ks + tg]);
                af[i][2] = tf32b(Ab[mb * AST + ks + tg + 4]);
                af[i][3] = tf32b(Ab[(mb + 8) * AST + ks + tg + 4]);
            }
            #pragma unroll
            for (int j = 0; j < NT; j++) {
                int nb = wc * WN + j * 8 + gid;
                if (TRANSB) {
                    bf[j][0] = tf32b(Bb[nb * BST + ks + tg]);
                    bf[j][1] = tf32b(Bb[nb * BST + ks + tg + 4]);
                } else {
                    bf[j][0] = tf32b(Bb[(ks + tg) * BST + nb]);
                    bf[j][1] = tf32b(Bb[(ks + tg + 4) * BST + nb]);
                }
            }
            #pragma unroll
            for (int i = 0; i < MT; i++)
                #pragma unroll
                for (int j = 0; j < NT; j++)
                    mma_tf32(acc[i][j], af[i], bf[j]);
        }
        __syncthreads();
        buf ^= 1;
    }

    // epilogue: c0 -> (m,n), c1 -> (m,n+1), c2 -> (m+8,n), c3 -> (m+8,n+1)
    #pragma unroll
    for (int i = 0; i < MT; i++) {
        #pragma unroll
        for (int j = 0; j < NT; j++) {
            #pragma unroll
            for (int e = 0; e < 4; e++) {
                int m = m0 + wr * WM + i * 16 + gid + ((e >= 2) ? 8 : 0);
                int n = n0 + wc * WN + j * 8 + 2 * tg + (e & 1);
                if (m < M && n < Nn) {
                    float v = acc[i][j][e] * alpha;
                    if (EPI == 0) {
                        C[(long long)z * sC + (long long)m * ldc + n] = v;
                    } else if (EPI == 1) {
                        C[(long long)m * ldc + n] = v + R[(long long)m * ldc + n];
                    } else if (EPI == 2) {
                        int b = m >> 9, nn = m & (SEQ - 1), h = n >> 6, d = n & (DHEAD - 1);
                        C[((((long long)b * HEADS + h) * SEQ + nn) << 6) + d] = v;
                    } else { // EPI == 3
                        int b = z >> 4, h = z & (HEADS - 1);
                        C[((long long)(b * SEQ + m) * INNERV) + h * DHEAD + n] = v;
                    }
                }
            }
        }
    }
}

// ---------------- tf32 GEGLU GEMM (two NT B tiles), cp.async double-buffered ------
// A [M,K] row-major lda=K. B = ff_w_in [2*FFH, K] row-major, NT access. C stride ldc.
template<int BM, int BN, int BK, int WM, int WN>
__global__ __launch_bounds__(256, 2)
void tgemm_geglu(const float* __restrict__ A, const float* __restrict__ B,
                 float* __restrict__ C, int M, int Nn, int K, int ldb, int ldc) {
    constexpr int WARPS_N = BN / WN;
    constexpr int MT = WM / 16, NT = WN / 8;
    constexpr int AST = BK + 4;
    constexpr int BST = BK + 4;
    constexpr int ABUF = BM * AST;
    constexpr int BBUF = BN * BST;

    extern __shared__ float smem[];
    float* Asm = smem;
    float* B1m = smem + 2 * ABUF;
    float* B2m = B1m + 2 * BBUF;

    const int m0 = blockIdx.y * BM;
    const int n0 = blockIdx.x * BN;
    const int tid = threadIdx.x;
    const int warp = tid >> 5, lane = tid & 31;
    const int wr = warp / WARPS_N, wc = warp % WARPS_N;
    const int gid = lane >> 2, tg = lane & 3;

    const uint32_t sAb = (uint32_t)__cvta_generic_to_shared(Asm);
    const uint32_t sB1 = (uint32_t)__cvta_generic_to_shared(B1m);
    const uint32_t sB2 = (uint32_t)__cvta_generic_to_shared(B2m);

    float a1[MT][NT][4], a2[MT][NT][4];
    #pragma unroll
    for (int i = 0; i < MT; i++)
        #pragma unroll
        for (int j = 0; j < NT; j++)
            #pragma unroll
            for (int e = 0; e < 4; e++) { a1[i][j][e] = 0.f; a2[i][j][e] = 0.f; }

    const int NIT = K / BK;

    auto stage = [&](int b, int k0) {
        constexpr int ACH = BK / 4;
        #pragma unroll
        for (int c = tid; c < BM * ACH; c += 256) {
            int m = c / ACH, kc = c % ACH;
            uint32_t sp = sAb + (uint32_t)((b * ABUF + m * AST + kc * 4) << 2);
            cp16(sp, A + (long long)(m0 + m) * K + k0 + kc * 4, 16);
        }
        constexpr int BCH = BK / 4;
        #pragma unroll
        for (int c = tid; c < BN * BCH; c += 256) {
            int n = c / BCH, kc = c % BCH;
            int gn = n0 + n; if (gn > FFH - 1) gn = FFH - 1;   // clamp ragged N (cols discarded)
            uint32_t o = (uint32_t)((b * BBUF + n * BST + kc * 4) << 2);
            cp16(sB1 + o, B + (long long)gn * ldb + k0 + kc * 4, 16);
            cp16(sB2 + o, B + (long long)(gn + FFH) * ldb + k0 + kc * 4, 16);
        }
    };

    stage(0, 0);
    cp_commit();
    int buf = 0;
    for (int it = 0; it < NIT; it++) {
        if (it + 1 < NIT) { stage(buf ^ 1, (it + 1) * BK); cp_commit(); cp_wait1(); }
        else cp_wait0();
        __syncthreads();

        const float* Ab  = Asm + buf * ABUF;
        const float* Bb1 = B1m + buf * BBUF;
        const float* Bb2 = B2m + buf * BBUF;
        #pragma unroll
        for (int ks = 0; ks < BK; ks += 8) {
            uint32_t af[MT][4];
            uint32_t bf1[NT][2], bf2[NT][2];
            #pragma unroll
            for (int i = 0; i < MT; i++) {
                int mb = wr * WM + i * 16 + gid;
                af[i][0] = tf32b(Ab[mb * AST + ks + tg]);
                af[i][1] = tf32b(Ab[(mb + 8) * AST + ks + tg]);
                af[i][2] = tf32b(Ab[mb * AST + ks + tg + 4]);
                af[i][3] = tf32b(Ab[(mb + 8) * AST + ks + tg + 4]);
            }
            #pragma unroll
            for (int j = 0; j < NT; j++) {
                int nb = wc * WN + j * 8 + gid;
                bf1[j][0] = tf32b(Bb1[nb * BST + ks + tg]);
                bf1[j][1] = tf32b(Bb1[nb * BST + ks + tg + 4]);
                bf2[j][0] = tf32b(Bb2[nb * BST + ks + tg]);
                bf2[j][1] = tf32b(Bb2[nb * BST + ks + tg + 4]);
            }
            #pragma unroll
            for (int i = 0; i < MT; i++)
                #pragma unroll
                for (int j = 0; j < NT; j++) {
                    mma_tf32(a1[i][j], af[i], bf1[j]);
                    mma_tf32(a2[i][j], af[i], bf2[j]);
                }
        }
        __syncthreads();
        buf ^= 1;
    }

    #pragma unroll
    for (int i = 0; i < MT; i++) {
        #pragma unroll
        for (int j = 0; j < NT; j++) {
            #pragma unroll
            for (int e = 0; e < 4; e++) {
                int m = m0 + wr * WM + i * 16 + gid + ((e >= 2) ? 8 : 0);
                int n = n0 + wc * WN + j * 8 + 2 * tg + (e & 1);
                if (m < M && n < Nn) {
                    float g  = a2[i][j][e];
                    float ge = 0.5f * g * (1.f + erff(g * 0.70710678118654752f));
                    C[(long long)m * ldc + n] = a1[i][j][e] * ge;
                }
            }
        }
    }
}

// ---------------- launch ---------------------------------------------------------
extern "C" void kernel_launch(void* const* d_in, const int* in_sizes, int n_in,
                              void* d_out, int out_size) {
    const float* x      = (const float*)d_in[0];
    const float* g_ln   = (const float*)d_in[1];
    const float* Wq     = (const float*)d_in[2];
    const float* Wkv    = (const float*)d_in[3];
    const float* Wo     = (const float*)d_in[4];
    const float* cpb_w1 = (const float*)d_in[5];
    const float* cpb_b1 = (const float*)d_in[6];
    const float* cpb_w2 = (const float*)d_in[7];
    const float* cpb_b2 = (const float*)d_in[8];
    const float* cpb_w3 = (const float*)d_in[9];
    const float* cpb_b3 = (const float*)d_in[10];
    const float* ff_w_in  = (const float*)d_in[11];
    const float* ff_g     = (const float*)d_in[12];
    const float* ff_w_out = (const float*)d_in[13];
    float* out = (float*)d_out;

    float *bias, *xn, *q, *k, *v, *sim, *o, *y, *t;
    cudaGetSymbolAddress((void**)&bias, g_bias);
    cudaGetSymbolAddress((void**)&xn,  g_xn);
    cudaGetSymbolAddress((void**)&q,   g_q);
    cudaGetSymbolAddress((void**)&k,   g_k);
    cudaGetSymbolAddress((void**)&v,   g_v);
    cudaGetSymbolAddress((void**)&sim, g_sim);
    cudaGetSymbolAddress((void**)&o,   g_o);
    cudaGetSymbolAddress((void**)&y,   g_y);
    cudaGetSymbolAddress((void**)&t,   g_t);

    // kernel aliases
    auto T_QKV = tgemm<128,128,32,64,32,false,2,false,16>;
    auto T_QKT = tgemm<128,128,32,64,32,true, 0,false,16>;
    auto T_AV  = tgemm<128, 64,32,32,32,false,3,false,16>;
    auto T_OP  = tgemm<128,128,32,64,32,false,1,false,16>;
    auto T_FFO = tgemm<128,128,32,64,32,true, 1,true,  8>;
    auto T_GG  = tgemm_geglu<128,64,32,64,16>;

    // dynamic smem sizes (bytes)
    const int SM_NT128 = (2*128*36 + 2*32*132) * 4;   // 70656
    const int SM_T128  = (2*128*36 + 2*128*36) * 4;   // 73728
    const int SM_NT64  = (2*128*36 + 2*32*68)  * 4;   // 54272
    const int SM_GG    = (2*128*36 + 4*64*36)  * 4;   // 73728

    cudaFuncSetAttribute(T_QKV, cudaFuncAttributeMaxDynamicSharedMemorySize, SM_NT128);
    cudaFuncSetAttribute(T_QKT, cudaFuncAttributeMaxDynamicSharedMemorySize, SM_T128);
    cudaFuncSetAttribute(T_AV,  cudaFuncAttributeMaxDynamicSharedMemorySize, SM_NT64);
    cudaFuncSetAttribute(T_OP,  cudaFuncAttributeMaxDynamicSharedMemorySize, SM_NT128);
    cudaFuncSetAttribute(T_FFO, cudaFuncAttributeMaxDynamicSharedMemorySize, SM_T128);
    cudaFuncSetAttribute(T_GG,  cudaFuncAttributeMaxDynamicSharedMemorySize, SM_GG);

    // 1) CPB bias table
    cpb_kernel<<<1023, 512>>>(cpb_w1, cpb_b1, cpb_w2, cpb_b2, cpb_w3, cpb_b3, bias);

    // 2) sequence-axis LayerNorm
    seqln_kernel<<<dim3(DIMV / 256, BATCH), 256>>>(x, g_ln, xn);

    // 3) Q/K/V projections, head-split stores
    T_QKV<<<dim3(8,64,1),256,SM_NT128>>>(xn, Wq,         q, nullptr,
        MROWS, INNERV, DIMV, DIMV, INNERV,   0, 0, 0, 0, 1.f);
    T_QKV<<<dim3(8,64,1),256,SM_NT128>>>(xn, Wkv,        k, nullptr,
        MROWS, INNERV, DIMV, DIMV, 2*INNERV, 0, 0, 0, 0, 1.f);
    T_QKV<<<dim3(8,64,1),256,SM_NT128>>>(xn, Wkv+INNERV, v, nullptr,
        MROWS, INNERV, DIMV, DIMV, 2*INNERV, 0, 0, 0, 0, 1.f);

    // 4) sim = scale * Q Kᵀ (batched NT)
    T_QKT<<<dim3(4,4,BATCH*HEADS),256,SM_T128>>>(q, k, sim, nullptr,
        SEQ, SEQ, DHEAD, DHEAD, DHEAD, SEQ,
        (long long)SEQ*DHEAD, (long long)SEQ*DHEAD, (long long)SEQ*SEQ, 0.125f);

    // 5) softmax + relative bias
    softmax_kernel<<<dim3(SEQ, BATCH*HEADS), 256>>>(sim, bias);

    // 6) O = attn V (batched NN)
    T_AV<<<dim3(1,4,BATCH*HEADS),256,SM_NT64>>>(sim, v, o, nullptr,
        SEQ, DHEAD, SEQ, SEQ, DHEAD, 0,
        (long long)SEQ*SEQ, (long long)SEQ*DHEAD, 0, 1.f);

    // 7) y = O @ Wo + x
    T_OP<<<dim3(8,64,1),256,SM_NT128>>>(o, Wo, y, x,
        MROWS, DIMV, INNERV, INNERV, DIMV, DIMV, 0, 0, 0, 1.f);

    // 8) FF-in + fused GEGLU
    T_GG<<<dim3((FFH+63)/64, 64),256,SM_GG>>>(y, ff_w_in, t,
        MROWS, FFH, DIMV, DIMV, LDT);

    // 9) channel LayerNorm (stride LDT)
    chanln_kernel<<<MROWS, 256>>>(t, ff_g);

    // 10) out = t @ ff_w_outᵀ + y  (K=2730 ragged, B rows only 8B-aligned)
    T_FFO<<<dim3(8,64,1),256,SM_T128>>>(t, ff_w_out, out, y,
        MROWS, DIMV, FFH, LDT, FFH, DIMV, 0, 0, 0, 1.f);
}

// round 6
// speedup vs baseline: 8.1638x; 1.0069x over previous
#include <cuda_runtime.h>
#include <math.h>
#include <stdint.h>

#define DIMV 1024
#define HEADS 16
#define DHEAD 64
#define BATCH 16
#define SEQ 512
#define INNERV 1024
#define CPBD 512
#define FFH 2730
#define LDT 2752            /* padded leading dim for t / cWout: 86*32, 16B aligned */
#define MROWS (BATCH*SEQ)   /* 8192 */
#define EPSV 1e-5f

// ---------------- scratch (static device arrays; no allocations) ----------------
__device__ float g_bias[HEADS * 1023];
__device__ float g_xn[(size_t)MROWS * DIMV];
__device__ float g_q[(size_t)MROWS * INNERV];
__device__ float g_k[(size_t)MROWS * INNERV];
__device__ float g_v[(size_t)MROWS * INNERV];
__device__ float g_sim[(size_t)BATCH * HEADS * SEQ * SEQ];   // 268 MB
__device__ float g_o[(size_t)MROWS * INNERV];
__device__ float g_y[(size_t)MROWS * DIMV];
__device__ float g_t[(size_t)MROWS * LDT];                   // zero-init padding
// tf32-preconverted weight copies
__device__ float g_cWq[(size_t)DIMV * INNERV];
__device__ float g_cWkv[(size_t)DIMV * 2 * INNERV];
__device__ float g_cWo[(size_t)INNERV * DIMV];
__device__ float g_cWin[(size_t)2 * FFH * DIMV];
__device__ float g_cWoutP[(size_t)DIMV * LDT];

// ---------------- helpers ---------------------------------------------------------
__device__ __forceinline__ uint32_t tf32b(float x) {
    uint32_t u; asm("cvt.rna.tf32.f32 %0, %1;" : "=r"(u) : "f"(x));
    return u;
}
__device__ __forceinline__ float cvtf(float x) { return __uint_as_float(tf32b(x)); }
__device__ __forceinline__ void mma_tf32(float d[4], const uint32_t a[4], const uint32_t b[2]) {
    asm volatile(
        "mma.sync.aligned.m16n8k8.row.col.f32.tf32.tf32.f32 "
        "{%0,%1,%2,%3},{%4,%5,%6,%7},{%8,%9},{%0,%1,%2,%3};\n"
        : "+f"(d[0]), "+f"(d[1]), "+f"(d[2]), "+f"(d[3])
        : "r"(a[0]), "r"(a[1]), "r"(a[2]), "r"(a[3]), "r"(b[0]), "r"(b[1]));
}
__device__ __forceinline__ void cp16(uint32_t s, const float* g, int nb) {
    asm volatile("cp.async.cg.shared.global [%0], [%1], 16, %2;\n" :: "r"(s), "l"(g), "r"(nb));
}
__device__ __forceinline__ void cp8(uint32_t s, const float* g, int nb) {
    asm volatile("cp.async.ca.shared.global [%0], [%1], 8, %2;\n" :: "r"(s), "l"(g), "r"(nb));
}
__device__ __forceinline__ void cp_commit() { asm volatile("cp.async.commit_group;\n"); }
__device__ __forceinline__ void cp_wait1()  { asm volatile("cp.async.wait_group 1;\n"); }
__device__ __forceinline__ void cp_wait0()  { asm volatile("cp.async.wait_group 0;\n"); }

// ---------------- weight preconvert kernels ---------------------------------------
__global__ void cvt4_kernel(const float4* __restrict__ in, float4* __restrict__ out, int n4) {
    int i = blockIdx.x * blockDim.x + threadIdx.x;
    int stride = gridDim.x * blockDim.x;
    for (; i < n4; i += stride) {
        float4 v = in[i];
        v.x = cvtf(v.x); v.y = cvtf(v.y); v.z = cvtf(v.z); v.w = cvtf(v.w);
        out[i] = v;
    }
}
// ff_w_out [DIMV][FFH] -> padded [DIMV][LDT] (tail zeros)
__global__ void cvt_pad_kernel(const float* __restrict__ in, float* __restrict__ out) {
    int r = blockIdx.y;
    int c = blockIdx.x * 256 + threadIdx.x;
    if (c < LDT) out[(size_t)r * LDT + c] = (c < FFH) ? cvtf(in[(size_t)r * FFH + c]) : 0.f;
}

// ---------------- CPB: bias table over 1023 distinct relative positions ----------
__global__ void cpb_kernel(const float* __restrict__ w1, const float* __restrict__ b1,
                           const float* __restrict__ w2, const float* __restrict__ b2,
                           const float* __restrict__ w3, const float* __restrict__ b3,
                           float* __restrict__ table) {
    int ridx = blockIdx.x;                 // 0..1022
    float rf = (float)(ridx - 511);
    float sgn = (rf > 0.f) ? 1.f : ((rf < 0.f) ? -1.f : 0.f);
    float rel = sgn * logf(fabsf(rf) + 1.f);

    __shared__ float h1[CPBD];
    __shared__ float h2[CPBD];
    int t = threadIdx.x;                   // 512 threads
    {
        float z = rel * w1[t] + b1[t];
        h1[t] = z / (1.f + expf(-z));      // silu
    }
    __syncthreads();
    {
        float acc = b2[t];
        #pragma unroll 4
        for (int j = 0; j < CPBD; j++) acc += h1[j] * w2[j * CPBD + t];
        h2[t] = acc / (1.f + expf(-acc));
    }
    __syncthreads();
    int warp = t >> 5, lane = t & 31;      // warp w -> head w
    float acc = 0.f;
    for (int i = lane; i < CPBD; i += 32) acc += h2[i] * w3[i * HEADS + warp];
    #pragma unroll
    for (int off = 16; off; off >>= 1) acc += __shfl_down_sync(0xffffffffu, acc, off);
    if (lane == 0) table[warp * 1023 + ridx] = acc + b3[warp];
}

// ---------------- sequence-axis LayerNorm (writes tf32-rounded) -------------------
__global__ void seqln_kernel(const float* __restrict__ x, const float* __restrict__ g,
                             float* __restrict__ xn) {
    int d = blockIdx.x * blockDim.x + threadIdx.x;
    int b = blockIdx.y;
    const float* xb = x + (size_t)b * SEQ * DIMV;
    float s = 0.f, ss = 0.f;
    for (int n = 0; n < SEQ; n++) { float v = xb[n * DIMV + d]; s += v; ss += v * v; }
    float mean = s * (1.f / SEQ);
    float var  = ss * (1.f / SEQ) - mean * mean;
    float inv  = rsqrtf(fmaxf(var, EPSV)) * g[d];
    float* ob = xn + (size_t)b * SEQ * DIMV;
    for (int n = 0; n < SEQ; n++) ob[n * DIMV + d] = cvtf((xb[n * DIMV + d] - mean) * inv);
}

// ---------------- softmax over sim row + relative bias (writes tf32) --------------
__global__ void softmax_kernel(float* __restrict__ sim, const float* __restrict__ table) {
    int i = blockIdx.x;
    int z = blockIdx.y;
    int h = z & (HEADS - 1);
    float* row = sim + ((size_t)z * SEQ + i) * SEQ;
    const float* tab = table + h * 1023 + (i + 511);

    __shared__ float sm[SEQ];
    __shared__ float red[256];
    int t = threadIdx.x;
    float m = -1e30f;
    for (int j = t; j < SEQ; j += 256) { float v = row[j] + tab[-j]; sm[j] = v; m = fmaxf(m, v); }
    red[t] = m; __syncthreads();
    for (int s = 128; s; s >>= 1) { if (t < s) red[t] = fmaxf(red[t], red[t + s]); __syncthreads(); }
    m = red[0]; __syncthreads();
    float sum = 0.f;
    for (int j = t; j < SEQ; j += 256) { float e = __expf(sm[j] - m); sm[j] = e; sum += e; }
    red[t] = sum; __syncthreads();
    for (int s = 128; s; s >>= 1) { if (t < s) red[t] += red[t + s]; __syncthreads(); }
    float inv = 1.f / red[0];
    for (int j = t; j < SEQ; j += 256) row[j] = cvtf(sm[j] * inv);
}

// ---------------- channel LayerNorm over FFH per token (stride LDT, writes tf32) --
__global__ void chanln_kernel(float* __restrict__ tb, const float* __restrict__ gg) {
    int m = blockIdx.x;
    float* row = tb + (size_t)m * LDT;
    int t = threadIdx.x;
    float s = 0.f, ss = 0.f;
    for (int j = t; j < FFH; j += 256) { float v = row[j]; s += v; ss += v * v; }
    __shared__ float r1[256], r2[256];
    r1[t] = s; r2[t] = ss; __syncthreads();
    for (int k = 128; k; k >>= 1) { if (t < k) { r1[t] += r1[t + k]; r2[t] += r2[t + k]; } __syncthreads(); }
    float mean = r1[0] * (1.f / FFH);
    float var  = r2[0] * (1.f / FFH) - mean * mean;
    float inv  = rsqrtf(fmaxf(var, EPSV));
    for (int j = t; j < FFH; j += 256) row[j] = cvtf((row[j] - mean) * inv * gg[j]);
    if (t < LDT - FFH) row[FFH + t] = 0.f;      // keep padding zero
}

// ---------------- tf32 tensor-core GEMM, cp.async double-buffered -----------------
// Operands MUST already be tf32-valued fp32 (raw-bit feed, no cvt in inner loop).
// Layouts: As[m][k] stride BK+4; Bs trans: [n][k] stride BK+4; no-trans: [k][n] stride BN+4.
// EPI: 0 = batched store (raw); 1 = +R residual (raw); 2 = q/k/v head-split (cvt);
//      3 = attn-out merge (cvt); 4 = +R residual (cvt)
template<int BM, int BN, int BK, int WM, int WN, bool TRANSB, int EPI, int BCP, int MINB>
__global__ __launch_bounds__(256, MINB)
void tgemm(const float* __restrict__ A, const float* __restrict__ B,
           float* __restrict__ C, const float* __restrict__ R,
           int M, int Nn, int K, int lda, int ldb, int ldc,
           long long sA, long long sB, long long sC, float alpha) {
    constexpr int WARPS_N = BN / WN;
    constexpr int MT = WM / 16, NT = WN / 8;
    constexpr int AST = BK + 4;
    constexpr int BST = TRANSB ? (BK + 4) : (BN + 4);
    constexpr int ABUF = BM * AST;
    constexpr int BBUF = TRANSB ? BN * BST : BK * BST;

    extern __shared__ float smem[];
    float* Asm = smem;
    float* Bsm = smem + 2 * ABUF;

    const int z = blockIdx.z;
    A += (long long)z * sA;
    B += (long long)z * sB;
    const int m0 = blockIdx.y * BM;
    const int n0 = blockIdx.x * BN;
    const int tid = threadIdx.x;
    const int warp = tid >> 5, lane = tid & 31;
    const int wr = warp / WARPS_N, wc = warp % WARPS_N;
    const int gid = lane >> 2, tg = lane & 3;

    const uint32_t sAb = (uint32_t)__cvta_generic_to_shared(Asm);
    const uint32_t sBb = (uint32_t)__cvta_generic_to_shared(Bsm);

    float acc[MT][NT][4];
    #pragma unroll
    for (int i = 0; i < MT; i++)
        #pragma unroll
        for (int j = 0; j < NT; j++)
            #pragma unroll
            for (int e = 0; e < 4; e++) acc[i][j][e] = 0.f;

    const int NIT = K / BK;

    auto stage = [&](int b, int k0) {
        constexpr int ACH = BK / 4;
        #pragma unroll
        for (int c = tid; c < BM * ACH; c += 256) {
            int m = c / ACH, kc = c % ACH;
            uint32_t sp = sAb + (uint32_t)((b * ABUF + m * AST + kc * 4) << 2);
            cp16(sp, A + (long long)(m0 + m) * lda + k0 + kc * 4, 16);
        }
        if (TRANSB) {
            if (BCP == 16) {
                constexpr int BCH = BK / 4;
                #pragma unroll
                for (int c = tid; c < BN * BCH; c += 256) {
                    int n = c / BCH, kc = c % BCH;
                    uint32_t sp = sBb + (uint32_t)((b * BBUF + n * BST + kc * 4) << 2);
                    cp16(sp, B + (long long)(n0 + n) * ldb + k0 + kc * 4, 16);
                }
            } else {
                constexpr int BCH = BK / 2;
                #pragma unroll
                for (int c = tid; c < BN * BCH; c += 256) {
                    int n = c / BCH, kc = c % BCH;
                    uint32_t sp = sBb + (uint32_t)((b * BBUF + n * BST + kc * 2) << 2);
                    cp8(sp, B + (long long)(n0 + n) * ldb + k0 + kc * 2, 8);
                }
            }
        } else {
            constexpr int BCH = BN / 4;
            #pragma unroll
            for (int c = tid; c < BK * BCH; c += 256) {
                int kk = c / BCH, nc = c % BCH;
                uint32_t sp = sBb + (uint32_t)((b * BBUF + kk * BST + nc * 4) << 2);
                cp16(sp, B + (long long)(k0 + kk) * ldb + n0 + nc * 4, 16);
            }
        }
    };

    stage(0, 0);
    cp_commit();
    int buf = 0;
    for (int it = 0; it < NIT; it++) {
        if (it + 1 < NIT) {
            stage(buf ^ 1, (it + 1) * BK);
            cp_commit();
            cp_wait1();
        } else {
            cp_wait0();
        }
        __syncthreads();

        const float* Ab = Asm + buf * ABUF;
        const float* Bb = Bsm + buf * BBUF;
        #pragma unroll
        for (int ks = 0; ks < BK; ks += 8) {
            uint32_t af[MT][4];
            uint32_t bf[NT][2];
            #pragma unroll
            for (int i = 0; i < MT; i++) {
                int mb = wr * WM + i * 16 + gid;
                af[i][0] = __float_as_uint(Ab[mb * AST + ks + tg]);
                af[i][1] = __float_as_uint(Ab[(mb + 8) * AST + ks + tg]);
                af[i][2] = __float_as_uint(Ab[mb * AST + ks + tg + 4]);
                af[i][3] = __float_as_uint(Ab[(mb + 8) * AST + ks + tg + 4]);
            }
            #pragma unroll
            for (int j = 0; j < NT; j++) {
                int nb = wc * WN + j * 8 + gid;
                if (TRANSB) {
                    bf[j][0] = __float_as_uint(Bb[nb * BST + ks + tg]);
                    bf[j][1] = __float_as_uint(Bb[nb * BST + ks + tg + 4]);
                } else {
                    bf[j][0] = __float_as_uint(Bb[(ks + tg) * BST + nb]);
                    bf[j][1] = __float_as_uint(Bb[(ks + tg + 4) * BST + nb]);
                }
            }
            #pragma unroll
            for (int i = 0; i < MT; i++)
                #pragma unroll
                for (int j = 0; j < NT; j++)
                    mma_tf32(acc[i][j], af[i], bf[j]);
        }
        __syncthreads();
        buf ^= 1;
    }

    #pragma unroll
    for (int i = 0; i < MT; i++) {
        #pragma unroll
        for (int j = 0; j < NT; j++) {
            #pragma unroll
            for (int e = 0; e < 4; e++) {
                int m = m0 + wr * WM + i * 16 + gid + ((e >= 2) ? 8 : 0);
                int n = n0 + wc * WN + j * 8 + 2 * tg + (e & 1);
                if (m < M && n < Nn) {
                    float v = acc[i][j][e] * alpha;
                    if (EPI == 0) {
                        C[(long long)z * sC + (long long)m * ldc + n] = v;
                    } else if (EPI == 1) {
                        C[(long long)m * ldc + n] = v + R[(long long)m * ldc + n];
                    } else if (EPI == 2) {
                        int b = m >> 9, nn = m & (SEQ - 1), h = n >> 6, d = n & (DHEAD - 1);
                        C[((((long long)b * HEADS + h) * SEQ + nn) << 6) + d] = cvtf(v);
                    } else if (EPI == 3) {
                        int b = z >> 4, h = z & (HEADS - 1);
                        C[((long long)(b * SEQ + m) * INNERV) + h * DHEAD + n] = cvtf(v);
                    } else { // EPI == 4
                        C[(long long)m * ldc + n] = cvtf(v + R[(long long)m * ldc + n]);
                    }
                }
            }
        }
    }
}

// ---------------- tf32 GEGLU GEMM (two NT B tiles), cp.async double-buffered ------
// A [M,K] tf32-valued, lda=K. B = converted ff_w_in copy [2*FFH, K], NT. C stride ldc (raw out).
template<int BM, int BN, int BK, int WM, int WN>
__global__ __launch_bounds__(256, 1)
void tgemm_geglu(const float* __restrict__ A, const float* __restrict__ B,
                 float* __restrict__ C, int M, int Nn, int K, int ldb, int ldc) {
    constexpr int WARPS_N = BN / WN;
    constexpr int MT = WM / 16, NT = WN / 8;
    constexpr int AST = BK + 4;
    constexpr int BST = BK + 4;
    constexpr int ABUF = BM * AST;
    constexpr int BBUF = BN * BST;

    extern __shared__ float smem[];
    float* Asm = smem;
    float* B1m = smem + 2 * ABUF;
    float* B2m = B1m + 2 * BBUF;

    const int m0 = blockIdx.y * BM;
    const int n0 = blockIdx.x * BN;
    const int tid = threadIdx.x;
    const int warp = tid >> 5, lane = tid & 31;
    const int wr = warp / WARPS_N, wc = warp % WARPS_N;
    const int gid = lane >> 2, tg = lane & 3;

    const uint32_t sAb = (uint32_t)__cvta_generic_to_shared(Asm);
    const uint32_t sB1 = (uint32_t)__cvta_generic_to_shared(B1m);
    const uint32_t sB2 = (uint32_t)__cvta_generic_to_shared(B2m);

    float a1[MT][NT][4], a2[MT][NT][4];
    #pragma unroll
    for (int i = 0; i < MT; i++)
        #pragma unroll
        for (int j = 0; j < NT; j++)
            #pragma unroll
            for (int e = 0; e < 4; e++) { a1[i][j][e] = 0.f; a2[i][j][e] = 0.f; }

    const int NIT = K / BK;

    auto stage = [&](int b, int k0) {
        constexpr int ACH = BK / 4;
        #pragma unroll
        for (int c = tid; c < BM * ACH; c += 256) {
            int m = c / ACH, kc = c % ACH;
            uint32_t sp = sAb + (uint32_t)((b * ABUF + m * AST + kc * 4) << 2);
            cp16(sp, A + (long long)(m0 + m) * K + k0 + kc * 4, 16);
        }
        constexpr int BCH = BK / 4;
        #pragma unroll
        for (int c = tid; c < BN * BCH; c += 256) {
            int n = c / BCH, kc = c % BCH;
            int gn = n0 + n; if (gn > FFH - 1) gn = FFH - 1;   // clamp ragged N (cols discarded)
            uint32_t o = (uint32_t)((b * BBUF + n * BST + kc * 4) << 2);
            cp16(sB1 + o, B + (long long)gn * ldb + k0 + kc * 4, 16);
            cp16(sB2 + o, B + (long long)(gn + FFH) * ldb + k0 + kc * 4, 16);
        }
    };

    stage(0, 0);
    cp_commit();
    int buf = 0;
    for (int it = 0; it < NIT; it++) {
        if (it + 1 < NIT) { stage(buf ^ 1, (it + 1) * BK); cp_commit(); cp_wait1(); }
        else cp_wait0();
        __syncthreads();

        const float* Ab  = Asm + buf * ABUF;
        const float* Bb1 = B1m + buf * BBUF;
        const float* Bb2 = B2m + buf * BBUF;
        #pragma unroll
        for (int ks = 0; ks < BK; ks += 8) {
            uint32_t af[MT][4];
            uint32_t bf1[NT][2], bf2[NT][2];
            #pragma unroll
            for (int i = 0; i < MT; i++) {
                int mb = wr * WM + i * 16 + gid;
                af[i][0] = __float_as_uint(Ab[mb * AST + ks + tg]);
                af[i][1] = __float_as_uint(Ab[(mb + 8) * AST + ks + tg]);
                af[i][2] = __float_as_uint(Ab[mb * AST + ks + tg + 4]);
                af[i][3] = __float_as_uint(Ab[(mb + 8) * AST + ks + tg + 4]);
            }
            #pragma unroll
            for (int j = 0; j < NT; j++) {
                int nb = wc * WN + j * 8 + gid;
                bf1[j][0] = __float_as_uint(Bb1[nb * BST + ks + tg]);
                bf1[j][1] = __float_as_uint(Bb1[nb * BST + ks + tg + 4]);
                bf2[j][0] = __float_as_uint(Bb2[nb * BST + ks + tg]);
                bf2[j][1] = __float_as_uint(Bb2[nb * BST + ks + tg + 4]);
            }
            #pragma unroll
            for (int i = 0; i < MT; i++)
                #pragma unroll
                for (int j = 0; j < NT; j++) {
                    mma_tf32(a1[i][j], af[i], bf1[j]);
                    mma_tf32(a2[i][j], af[i], bf2[j]);
                }
        }
        __syncthreads();
        buf ^= 1;
    }

    #pragma unroll
    for (int i = 0; i < MT; i++) {
        #pragma unroll
        for (int j = 0; j < NT; j++) {
            #pragma unroll
            for (int e = 0; e < 4; e++) {
                int m = m0 + wr * WM + i * 16 + gid + ((e >= 2) ? 8 : 0);
                int n = n0 + wc * WN + j * 8 + 2 * tg + (e & 1);
                if (m < M && n < Nn) {
                    float g  = a2[i][j][e];
                    float ge = 0.5f * g * (1.f + erff(g * 0.70710678118654752f));
                    C[(long long)m * ldc + n] = a1[i][j][e] * ge;
                }
            }
        }
    }
}

// ---------------- launch ---------------------------------------------------------
extern "C" void kernel_launch(void* const* d_in, const int* in_sizes, int n_in,
                              void* d_out, int out_size) {
    const float* x      = (const float*)d_in[0];
    const float* g_ln   = (const float*)d_in[1];
    const float* Wq     = (const float*)d_in[2];
    const float* Wkv    = (const float*)d_in[3];
    const float* Wo     = (const float*)d_in[4];
    const float* cpb_w1 = (const float*)d_in[5];
    const float* cpb_b1 = (const float*)d_in[6];
    const float* cpb_w2 = (const float*)d_in[7];
    const float* cpb_b2 = (const float*)d_in[8];
    const float* cpb_w3 = (const float*)d_in[9];
    const float* cpb_b3 = (const float*)d_in[10];
    const float* ff_w_in  = (const float*)d_in[11];
    const float* ff_g     = (const float*)d_in[12];
    const float* ff_w_out = (const float*)d_in[13];
    float* out = (float*)d_out;

    float *bias, *xn, *q, *k, *v, *sim, *o, *y, *t;
    float *cWq, *cWkv, *cWo, *cWin, *cWoutP;
    cudaGetSymbolAddress((void**)&bias, g_bias);
    cudaGetSymbolAddress((void**)&xn,  g_xn);
    cudaGetSymbolAddress((void**)&q,   g_q);
    cudaGetSymbolAddress((void**)&k,   g_k);
    cudaGetSymbolAddress((void**)&v,   g_v);
    cudaGetSymbolAddress((void**)&sim, g_sim);
    cudaGetSymbolAddress((void**)&o,   g_o);
    cudaGetSymbolAddress((void**)&y,   g_y);
    cudaGetSymbolAddress((void**)&t,   g_t);
    cudaGetSymbolAddress((void**)&cWq,    g_cWq);
    cudaGetSymbolAddress((void**)&cWkv,   g_cWkv);
    cudaGetSymbolAddress((void**)&cWo,    g_cWo);
    cudaGetSymbolAddress((void**)&cWin,   g_cWin);
    cudaGetSymbolAddress((void**)&cWoutP, g_cWoutP);

    // kernel aliases
    auto T_QKV = tgemm<256,128,32,64,64,false,2,16,1>;
    auto T_QKT = tgemm<128,128,32,64,32,true, 0,16,2>;
    auto T_AV  = tgemm<128, 64,32,32,32,false,3,16,2>;
    auto T_OP  = tgemm<256,128,32,64,64,false,4,16,1>;
    auto T_FFO = tgemm<256,128,32,64,64,true, 1,16,1>;
    auto T_GG  = tgemm_geglu<256,64,32,64,32>;

    // dynamic smem sizes (bytes)
    const int SM_BIG_NN = (2*256*36 + 2*32*132) * 4;   // 107520
    const int SM_BIG_TT = (2*256*36 + 2*128*36) * 4;   // 110592
    const int SM_QKT    = (2*128*36 + 2*128*36) * 4;   // 73728
    const int SM_AV     = (2*128*36 + 2*32*68)  * 4;   // 54272
    const int SM_GG     = (2*256*36 + 4*64*36)  * 4;   // 110592

    cudaFuncSetAttribute(T_QKV, cudaFuncAttributeMaxDynamicSharedMemorySize, SM_BIG_NN);
    cudaFuncSetAttribute(T_QKT, cudaFuncAttributeMaxDynamicSharedMemorySize, SM_QKT);
    cudaFuncSetAttribute(T_AV,  cudaFuncAttributeMaxDynamicSharedMemorySize, SM_AV);
    cudaFuncSetAttribute(T_OP,  cudaFuncAttributeMaxDynamicSharedMemorySize, SM_BIG_NN);
    cudaFuncSetAttribute(T_FFO, cudaFuncAttributeMaxDynamicSharedMemorySize, SM_BIG_TT);
    cudaFuncSetAttribute(T_GG,  cudaFuncAttributeMaxDynamicSharedMemorySize, SM_GG);

    // 0) weight preconversion (tf32-rna into scratch copies)
    cvt4_kernel<<<512, 256>>>((const float4*)Wq,      (float4*)cWq,   DIMV*INNERV/4);
    cvt4_kernel<<<512, 256>>>((const float4*)Wkv,     (float4*)cWkv,  DIMV*2*INNERV/4);
    cvt4_kernel<<<512, 256>>>((const float4*)Wo,      (float4*)cWo,   INNERV*DIMV/4);
    cvt4_kernel<<<512, 256>>>((const float4*)ff_w_in, (float4*)cWin,  2*FFH*DIMV/4);
    cvt_pad_kernel<<<dim3((LDT+255)/256, DIMV), 256>>>(ff_w_out, cWoutP);

    // 1) CPB bias table
    cpb_kernel<<<1023, 512>>>(cpb_w1, cpb_b1, cpb_w2, cpb_b2, cpb_w3, cpb_b3, bias);

    // 2) sequence-axis LayerNorm (tf32 out)
    seqln_kernel<<<dim3(DIMV / 256, BATCH), 256>>>(x, g_ln, xn);

    // 3) Q/K/V projections, head-split stores (tf32 out)
    T_QKV<<<dim3(8,32,1),256,SM_BIG_NN>>>(xn, cWq,         q, nullptr,
        MROWS, INNERV, DIMV, DIMV, INNERV,   0, 0, 0, 0, 1.f);
    T_QKV<<<dim3(8,32,1),256,SM_BIG_NN>>>(xn, cWkv,        k, nullptr,
        MROWS, INNERV, DIMV, DIMV, 2*INNERV, 0, 0, 0, 0, 1.f);
    T_QKV<<<dim3(8,32,1),256,SM_BIG_NN>>>(xn, cWkv+INNERV, v, nullptr,
        MROWS, INNERV, DIMV, DIMV, 2*INNERV, 0, 0, 0, 0, 1.f);

    // 4) sim = scale * Q Kᵀ (batched NT, raw out)
    T_QKT<<<dim3(4,4,BATCH*HEADS),256,SM_QKT>>>(q, k, sim, nullptr,
        SEQ, SEQ, DHEAD, DHEAD, DHEAD, SEQ,
        (long long)SEQ*DHEAD, (long long)SEQ*DHEAD, (long long)SEQ*SEQ, 0.125f);

    // 5) softmax + relative bias (tf32 out)
    softmax_kernel<<<dim3(SEQ, BATCH*HEADS), 256>>>(sim, bias);

    // 6) O = attn V (batched NN, tf32 out)
    T_AV<<<dim3(1,4,BATCH*HEADS),256,SM_AV>>>(sim, v, o, nullptr,
        SEQ, DHEAD, SEQ, SEQ, DHEAD, 0,
        (long long)SEQ*SEQ, (long long)SEQ*DHEAD, 0, 1.f);

    // 7) y = O @ Wo + x (tf32 out)
    T_OP<<<dim3(8,32,1),256,SM_BIG_NN>>>(o, cWo, y, x,
        MROWS, DIMV, INNERV, INNERV, DIMV, DIMV, 0, 0, 0, 1.f);

    // 8) FF-in + fused GEGLU (raw out; chanln re-rounds)
    T_GG<<<dim3((FFH+63)/64, 32),256,SM_GG>>>(y, cWin, t,
        MROWS, FFH, DIMV, DIMV, LDT);

    // 9) channel LayerNorm (stride LDT, tf32 out + zero padding)
    chanln_kernel<<<MROWS, 256>>>(t, ff_g);

    // 10) out = t @ cWoutPᵀ + y  (K padded to 2752 with zeros; raw out)
    T_FFO<<<dim3(8,32,1),256,SM_BIG_TT>>>(t, cWoutP, out, y,
        MROWS, DIMV, LDT, LDT, LDT, DIMV, 0, 0, 0, 1.f);
}

// round 8
// speedup vs baseline: 9.6281x; 1.1794x over previous
#include <cuda_runtime.h>
#include <math.h>
#include <stdint.h>

#define DIMV 1024
#define HEADS 16
#define DHEAD 64
#define BATCH 16
#define SEQ 512
#define INNERV 1024
#define CPBD 512
#define FFH 2730
#define LDT 2752            /* padded leading dim for t / cWout: 86*32, 16B aligned */
#define MROWS (BATCH*SEQ)   /* 8192 */
#define EPSV 1e-5f

// ---------------- scratch (static device arrays; no allocations) ----------------
__device__ float g_bias[HEADS * 1023];
__device__ float g_xn[(size_t)MROWS * DIMV];
__device__ float g_q[(size_t)MROWS * INNERV];
__device__ float g_k[(size_t)MROWS * INNERV];
__device__ float g_v[(size_t)MROWS * INNERV];
__device__ float g_o[(size_t)MROWS * INNERV];
__device__ float g_y[(size_t)MROWS * DIMV];
__device__ float g_t[(size_t)MROWS * LDT];
// tf32-preconverted weight copies
__device__ float g_cWq[(size_t)DIMV * INNERV];
__device__ float g_cWkv[(size_t)DIMV * 2 * INNERV];
__device__ float g_cWo[(size_t)INNERV * DIMV];
__device__ float g_cWin[(size_t)2 * FFH * DIMV];
__device__ float g_cWoutP[(size_t)DIMV * LDT];

// ---------------- helpers ---------------------------------------------------------
__device__ __forceinline__ uint32_t tf32b(float x) {
    uint32_t u; asm("cvt.rna.tf32.f32 %0, %1;" : "=r"(u) : "f"(x));
    return u;
}
__device__ __forceinline__ float cvtf(float x) { return __uint_as_float(tf32b(x)); }
__device__ __forceinline__ void mma_tf32(float d[4], const uint32_t a[4], const uint32_t b[2]) {
    asm volatile(
        "mma.sync.aligned.m16n8k8.row.col.f32.tf32.tf32.f32 "
        "{%0,%1,%2,%3},{%4,%5,%6,%7},{%8,%9},{%0,%1,%2,%3};\n"
        : "+f"(d[0]), "+f"(d[1]), "+f"(d[2]), "+f"(d[3])
        : "r"(a[0]), "r"(a[1]), "r"(a[2]), "r"(a[3]), "r"(b[0]), "r"(b[1]));
}
__device__ __forceinline__ void cp16(uint32_t s, const float* g, int nb) {
    asm volatile("cp.async.cg.shared.global [%0], [%1], 16, %2;\n" :: "r"(s), "l"(g), "r"(nb));
}
__device__ __forceinline__ void cp_commit() { asm volatile("cp.async.commit_group;\n"); }
__device__ __forceinline__ void cp_wait1()  { asm volatile("cp.async.wait_group 1;\n"); }
__device__ __forceinline__ void cp_wait0()  { asm volatile("cp.async.wait_group 0;\n"); }
__device__ __forceinline__ float qmax2(float v) {
    v = fmaxf(v, __shfl_xor_sync(0xffffffffu, v, 1));
    v = fmaxf(v, __shfl_xor_sync(0xffffffffu, v, 2));
    return v;
}
__device__ __forceinline__ float qsum2(float v) {
    v += __shfl_xor_sync(0xffffffffu, v, 1);
    v += __shfl_xor_sync(0xffffffffu, v, 2);
    return v;
}

// ---------------- weight preconvert kernels ---------------------------------------
__global__ void cvt4_kernel(const float4* __restrict__ in, float4* __restrict__ out, int n4) {
    int i = blockIdx.x * blockDim.x + threadIdx.x;
    int stride = gridDim.x * blockDim.x;
    for (; i < n4; i += stride) {
        float4 v = in[i];
        v.x = cvtf(v.x); v.y = cvtf(v.y); v.z = cvtf(v.z); v.w = cvtf(v.w);
        out[i] = v;
    }
}
__global__ void cvt_pad_kernel(const float* __restrict__ in, float* __restrict__ out) {
    int r = blockIdx.y;
    int c = blockIdx.x * 256 + threadIdx.x;
    if (c < LDT) out[(size_t)r * LDT + c] = (c < FFH) ? cvtf(in[(size_t)r * FFH + c]) : 0.f;
}

// ---------------- CPB: bias table over 1023 distinct relative positions ----------
__global__ void cpb_kernel(const float* __restrict__ w1, const float* __restrict__ b1,
                           const float* __restrict__ w2, const float* __restrict__ b2,
                           const float* __restrict__ w3, const float* __restrict__ b3,
                           float* __restrict__ table) {
    int ridx = blockIdx.x;
    float rf = (float)(ridx - 511);
    float sgn = (rf > 0.f) ? 1.f : ((rf < 0.f) ? -1.f : 0.f);
    float rel = sgn * logf(fabsf(rf) + 1.f);

    __shared__ float h1[CPBD];
    __shared__ float h2[CPBD];
    int t = threadIdx.x;
    {
        float z = rel * w1[t] + b1[t];
        h1[t] = z / (1.f + expf(-z));
    }
    __syncthreads();
    {
        float acc = b2[t];
        #pragma unroll 4
        for (int j = 0; j < CPBD; j++) acc += h1[j] * w2[j * CPBD + t];
        h2[t] = acc / (1.f + expf(-acc));
    }
    __syncthreads();
    int warp = t >> 5, lane = t & 31;
    float acc = 0.f;
    for (int i = lane; i < CPBD; i += 32) acc += h2[i] * w3[i * HEADS + warp];
    #pragma unroll
    for (int off = 16; off; off >>= 1) acc += __shfl_down_sync(0xffffffffu, acc, off);
    if (lane == 0) table[warp * 1023 + ridx] = acc + b3[warp];
}

// ---------------- sequence-axis LayerNorm (writes tf32-rounded) -------------------
__global__ void seqln_kernel(const float* __restrict__ x, const float* __restrict__ g,
                             float* __restrict__ xn) {
    int d = blockIdx.x * blockDim.x + threadIdx.x;
    int b = blockIdx.y;
    const float* xb = x + (size_t)b * SEQ * DIMV;
    float s = 0.f, ss = 0.f;
    for (int n = 0; n < SEQ; n++) { float v = xb[n * DIMV + d]; s += v; ss += v * v; }
    float mean = s * (1.f / SEQ);
    float var  = ss * (1.f / SEQ) - mean * mean;
    float inv  = rsqrtf(fmaxf(var, EPSV)) * g[d];
    float* ob = xn + (size_t)b * SEQ * DIMV;
    for (int n = 0; n < SEQ; n++) ob[n * DIMV + d] = cvtf((xb[n * DIMV + d] - mean) * inv);
}

// ---------------- fused flash attention (tf32 mma, fp32 online softmax) -----------
// grid: (SEQ/128, BATCH*HEADS). 256 threads = 8 warps; warp w owns q rows [16w,16w+16).
// q/k/v in [b,h,n,d] layout, tf32-valued. Writes o into [b,n,h*64+d] (tf32).
#define FA_QST 68
#define FA_KST 68
#define FA_VST 72
#define FA_PST 68
#define FA_QS  0
#define FA_KS  (FA_QS + 128*FA_QST)                 /* 8704  */
#define FA_VS  (FA_KS + 2*64*FA_KST)                /* 17408 */
#define FA_PS  (FA_VS + 2*64*FA_VST)                /* 26624 */
#define FA_BI  (FA_PS + 8*16*FA_PST)                /* 35328 */
#define FA_TOT (FA_BI + 1024)                       /* 36352 floats = 145408 B */

__global__ __launch_bounds__(256, 1)
void flash_kernel(const float* __restrict__ q, const float* __restrict__ k,
                  const float* __restrict__ v, const float* __restrict__ table,
                  float* __restrict__ o) {
    extern __shared__ float smem[];
    const int qt = blockIdx.x;              // q tile 0..3
    const int z  = blockIdx.y;              // b*HEADS + h
    const int h  = z & (HEADS - 1);
    const int b  = z >> 4;
    const int qbase = qt * 128;
    const int tid = threadIdx.x;
    const int w = tid >> 5, lane = tid & 31;
    const int gid = lane >> 2, tg = lane & 3;

    const float* qz = q + (size_t)z * SEQ * DHEAD;
    const float* kz = k + (size_t)z * SEQ * DHEAD;
    const float* vz = v + (size_t)z * SEQ * DHEAD;

    const uint32_t sbase = (uint32_t)__cvta_generic_to_shared(smem);

    // stage Q (once): 128 rows x 16 16B-chunks
    #pragma unroll
    for (int c = tid; c < 128 * 16; c += 256) {
        int m = c >> 4, kc = c & 15;
        cp16(sbase + (uint32_t)((FA_QS + m * FA_QST + kc * 4) << 2),
             qz + (qbase + m) * DHEAD + kc * 4, 16);
    }
    // bias table row for this head
    for (int i = tid; i < 1023; i += 256) smem[FA_BI + i] = table[h * 1023 + i];

    auto stage_kv = [&](int buf, int jt) {
        int kb = jt * 64;
        #pragma unroll
        for (int c = tid; c < 64 * 16; c += 256) {
            int r = c >> 4, kc = c & 15;
            cp16(sbase + (uint32_t)((FA_KS + buf * 64 * FA_KST + r * FA_KST + kc * 4) << 2),
                 kz + (kb + r) * DHEAD + kc * 4, 16);
            cp16(sbase + (uint32_t)((FA_VS + buf * 64 * FA_VST + r * FA_VST + kc * 4) << 2),
                 vz + (kb + r) * DHEAD + kc * 4, 16);
        }
    };

    stage_kv(0, 0);
    cp_commit();

    float m_row[2] = {-1e30f, -1e30f};
    float l_row[2] = {0.f, 0.f};
    float oacc[8][4];
    #pragma unroll
    for (int j = 0; j < 8; j++)
        #pragma unroll
        for (int e = 0; e < 4; e++) oacc[j][e] = 0.f;

    const float* Qs = smem + FA_QS;
    float* Ps = smem + FA_PS + w * 16 * FA_PST;
    const float* Bi = smem + FA_BI;

    int buf = 0;
    for (int jt = 0; jt < 8; jt++) {
        if (jt + 1 < 8) { stage_kv(buf ^ 1, jt + 1); cp_commit(); cp_wait1(); }
        else cp_wait0();
        __syncthreads();

        const float* Ks = smem + FA_KS + buf * 64 * FA_KST;
        const float* Vs = smem + FA_VS + buf * 64 * FA_VST;
        const int kb = jt * 64;

        // ---- S = Q K^T (warp: 16 rows x 64 cols) ----
        float s[8][4];
        #pragma unroll
        for (int j = 0; j < 8; j++)
            #pragma unroll
            for (int e = 0; e < 4; e++) s[j][e] = 0.f;
        #pragma unroll
        for (int ks = 0; ks < 64; ks += 8) {
            uint32_t a[4];
            int mb = w * 16 + gid;
            a[0] = __float_as_uint(Qs[mb * FA_QST + ks + tg]);
            a[1] = __float_as_uint(Qs[(mb + 8) * FA_QST + ks + tg]);
            a[2] = __float_as_uint(Qs[mb * FA_QST + ks + tg + 4]);
            a[3] = __float_as_uint(Qs[(mb + 8) * FA_QST + ks + tg + 4]);
            #pragma unroll
            for (int j = 0; j < 8; j++) {
                uint32_t bfr[2];
                int nb = j * 8 + gid;
                bfr[0] = __float_as_uint(Ks[nb * FA_KST + ks + tg]);
                bfr[1] = __float_as_uint(Ks[nb * FA_KST + ks + tg + 4]);
                mma_tf32(s[j], a, bfr);
            }
        }

        // ---- scale + bias, online softmax ----
        int qi0 = qbase + w * 16 + gid;          // row for e<2; +8 for e>=2
        float mx0 = -1e30f, mx1 = -1e30f;
        #pragma unroll
        for (int j = 0; j < 8; j++) {
            int kj = kb + j * 8 + 2 * tg;
            float b0 = Bi[qi0 - kj + 511];
            float b1 = Bi[qi0 - kj + 510];
            float b2 = Bi[qi0 + 8 - kj + 511];
            float b3 = Bi[qi0 + 8 - kj + 510];
            s[j][0] = s[j][0] * 0.125f + b0;
            s[j][1] = s[j][1] * 0.125f + b1;
            s[j][2] = s[j][2] * 0.125f + b2;
            s[j][3] = s[j][3] * 0.125f + b3;
            mx0 = fmaxf(mx0, fmaxf(s[j][0], s[j][1]));
            mx1 = fmaxf(mx1, fmaxf(s[j][2], s[j][3]));
        }
        mx0 = qmax2(mx0); mx1 = qmax2(mx1);
        float mn0 = fmaxf(m_row[0], mx0), mn1 = fmaxf(m_row[1], mx1);
        float sc0 = __expf(m_row[0] - mn0), sc1 = __expf(m_row[1] - mn1);
        float rs0 = 0.f, rs1 = 0.f;
        #pragma unroll
        for (int j = 0; j < 8; j++) {
            s[j][0] = __expf(s[j][0] - mn0);
            s[j][1] = __expf(s[j][1] - mn0);
            s[j][2] = __expf(s[j][2] - mn1);
            s[j][3] = __expf(s[j][3] - mn1);
            rs0 += s[j][0] + s[j][1];
            rs1 += s[j][2] + s[j][3];
        }
        rs0 = qsum2(rs0); rs1 = qsum2(rs1);
        l_row[0] = l_row[0] * sc0 + rs0;
        l_row[1] = l_row[1] * sc1 + rs1;
        m_row[0] = mn0; m_row[1] = mn1;
        #pragma unroll
        for (int j = 0; j < 8; j++) {
            oacc[j][0] *= sc0; oacc[j][1] *= sc0;
            oacc[j][2] *= sc1; oacc[j][3] *= sc1;
        }

        // ---- store P (tf32) to warp-private smem ----
        #pragma unroll
        for (int j = 0; j < 8; j++) {
            float2 p0 = make_float2(cvtf(s[j][0]), cvtf(s[j][1]));
            float2 p1 = make_float2(cvtf(s[j][2]), cvtf(s[j][3]));
            *(float2*)&Ps[gid * FA_PST + j * 8 + 2 * tg] = p0;
            *(float2*)&Ps[(gid + 8) * FA_PST + j * 8 + 2 * tg] = p1;
        }
        __syncwarp();

        // ---- O += P V ----
        #pragma unroll
        for (int ks = 0; ks < 64; ks += 8) {
            uint32_t a[4];
            a[0] = __float_as_uint(Ps[gid * FA_PST + ks + tg]);
            a[1] = __float_as_uint(Ps[(gid + 8) * FA_PST + ks + tg]);
            a[2] = __float_as_uint(Ps[gid * FA_PST + ks + tg + 4]);
            a[3] = __float_as_uint(Ps[(gid + 8) * FA_PST + ks + tg + 4]);
            #pragma unroll
            for (int j = 0; j < 8; j++) {
                uint32_t bfr[2];
                int nb = j * 8 + gid;
                bfr[0] = __float_as_uint(Vs[(ks + tg) * FA_VST + nb]);
                bfr[1] = __float_as_uint(Vs[(ks + tg + 4) * FA_VST + nb]);
                mma_tf32(oacc[j], a, bfr);
            }
        }
        __syncwarp();
        __syncthreads();       // done reading buf before next stage overwrites it
        buf ^= 1;
    }

    // ---- epilogue: O / l, store [b, n, h*64+d] tf32 ----
    float inv0 = 1.f / l_row[0], inv1 = 1.f / l_row[1];
    int qi = qbase + w * 16 + gid;
    #pragma unroll
    for (int j = 0; j < 8; j++) {
        int d = j * 8 + 2 * tg;
        size_t r0 = ((size_t)(b * SEQ + qi) * INNERV) + h * DHEAD + d;
        size_t r1 = ((size_t)(b * SEQ + qi + 8) * INNERV) + h * DHEAD + d;
        o[r0]     = cvtf(oacc[j][0] * inv0);
        o[r0 + 1] = cvtf(oacc[j][1] * inv0);
        o[r1]     = cvtf(oacc[j][2] * inv1);
        o[r1 + 1] = cvtf(oacc[j][3] * inv1);
    }
}

// ---------------- channel LayerNorm over FFH per token (stride LDT, writes tf32) --
__global__ void chanln_kernel(float* __restrict__ tb, const float* __restrict__ gg) {
    int m = blockIdx.x;
    float* row = tb + (size_t)m * LDT;
    int t = threadIdx.x;
    float s = 0.f, ss = 0.f;
    for (int j = t; j < FFH; j += 256) { float v = row[j]; s += v; ss += v * v; }
    __shared__ float r1[256], r2[256];
    r1[t] = s; r2[t] = ss; __syncthreads();
    for (int k = 128; k; k >>= 1) { if (t < k) { r1[t] += r1[t + k]; r2[t] += r2[t + k]; } __syncthreads(); }
    float mean = r1[0] * (1.f / FFH);
    float var  = r2[0] * (1.f / FFH) - mean * mean;
    float inv  = rsqrtf(fmaxf(var, EPSV));
    for (int j = t; j < FFH; j += 256) row[j] = cvtf((row[j] - mean) * inv * gg[j]);
    if (t < LDT - FFH) row[FFH + t] = 0.f;
}

// ---------------- tf32 tensor-core GEMM, cp.async double-buffered -----------------
// EPI: 0 = batched store (raw); 1 = +R residual (raw); 2 = q/k/v head-split (cvt);
//      4 = +R residual (cvt)
template<int BM, int BN, int BK, int WM, int WN, bool TRANSB, int EPI, int MINB>
__global__ __launch_bounds__(256, MINB)
void tgemm(const float* __restrict__ A, const float* __restrict__ B,
           float* __restrict__ C, const float* __restrict__ R,
           int M, int Nn, int K, int lda, int ldb, int ldc,
           long long sA, long long sB, long long sC, float alpha) {
    constexpr int WARPS_N = BN / WN;
    constexpr int MT = WM / 16, NT = WN / 8;
    constexpr int AST = BK + 4;
    constexpr int BST = TRANSB ? (BK + 4) : (BN + 4);
    constexpr int ABUF = BM * AST;
    constexpr int BBUF = TRANSB ? BN * BST : BK * BST;

    extern __shared__ float smem[];
    float* Asm = smem;
    float* Bsm = smem + 2 * ABUF;

    const int z = blockIdx.z;
    A += (long long)z * sA;
    B += (long long)z * sB;
    const int m0 = blockIdx.y * BM;
    const int n0 = blockIdx.x * BN;
    const int tid = threadIdx.x;
    const int warp = tid >> 5, lane = tid & 31;
    const int wr = warp / WARPS_N, wc = warp % WARPS_N;
    const int gid = lane >> 2, tg = lane & 3;

    const uint32_t sAb = (uint32_t)__cvta_generic_to_shared(Asm);
    const uint32_t sBb = (uint32_t)__cvta_generic_to_shared(Bsm);

    float acc[MT][NT][4];
    #pragma unroll
    for (int i = 0; i < MT; i++)
        #pragma unroll
        for (int j = 0; j < NT; j++)
            #pragma unroll
            for (int e = 0; e < 4; e++) acc[i][j][e] = 0.f;

    const int NIT = K / BK;

    auto stage = [&](int b, int k0) {
        constexpr int ACH = BK / 4;
        #pragma unroll
        for (int c = tid; c < BM * ACH; c += 256) {
            int m = c / ACH, kc = c % ACH;
            uint32_t sp = sAb + (uint32_t)((b * ABUF + m * AST + kc * 4) << 2);
            cp16(sp, A + (long long)(m0 + m) * lda + k0 + kc * 4, 16);
        }
        if (TRANSB) {
            constexpr int BCH = BK / 4;
            #pragma unroll
            for (int c = tid; c < BN * BCH; c += 256) {
                int n = c / BCH, kc = c % BCH;
                uint32_t sp = sBb + (uint32_t)((b * BBUF + n * BST + kc * 4) << 2);
                cp16(sp, B + (long long)(n0 + n) * ldb + k0 + kc * 4, 16);
            }
        } else {
            constexpr int BCH = BN / 4;
            #pragma unroll
            for (int c = tid; c < BK * BCH; c += 256) {
                int kk = c / BCH, nc = c % BCH;
                uint32_t sp = sBb + (uint32_t)((b * BBUF + kk * BST + nc * 4) << 2);
                cp16(sp, B + (long long)(k0 + kk) * ldb + n0 + nc * 4, 16);
            }
        }
    };

    stage(0, 0);
    cp_commit();
    int buf = 0;
    for (int it = 0; it < NIT; it++) {
        if (it + 1 < NIT) {
            stage(buf ^ 1, (it + 1) * BK);
            cp_commit();
            cp_wait1();
        } else {
            cp_wait0();
        }
        __syncthreads();

        const float* Ab = Asm + buf * ABUF;
        const float* Bb = Bsm + buf * BBUF;
        #pragma unroll
        for (int ks = 0; ks < BK; ks += 8) {
            uint32_t af[MT][4];
            uint32_t bf[NT][2];
            #pragma unroll
            for (int i = 0; i < MT; i++) {
                int mb = wr * WM + i * 16 + gid;
                af[i][0] = __float_as_uint(Ab[mb * AST + ks + tg]);
                af[i][1] = __float_as_uint(Ab[(mb + 8) * AST + ks + tg]);
                af[i][2] = __float_as_uint(Ab[mb * AST + ks + tg + 4]);
                af[i][3] = __float_as_uint(Ab[(mb + 8) * AST + ks + tg + 4]);
            }
            #pragma unroll
            for (int j = 0; j < NT; j++) {
                int nb = wc * WN + j * 8 + gid;
                if (TRANSB) {
                    bf[j][0] = __float_as_uint(Bb[nb * BST + ks + tg]);
                    bf[j][1] = __float_as_uint(Bb[nb * BST + ks + tg + 4]);
                } else {
                    bf[j][0] = __float_as_uint(Bb[(ks + tg) * BST + nb]);
                    bf[j][1] = __float_as_uint(Bb[(ks + tg + 4) * BST + nb]);
                }
            }
            #pragma unroll
            for (int i = 0; i < MT; i++)
                #pragma unroll
                for (int j = 0; j < NT; j++)
                    mma_tf32(acc[i][j], af[i], bf[j]);
        }
        __syncthreads();
        buf ^= 1;
    }

    #pragma unroll
    for (int i = 0; i < MT; i++) {
        #pragma unroll
        for (int j = 0; j < NT; j++) {
            #pragma unroll
            for (int e = 0; e < 4; e++) {
                int m = m0 + wr * WM + i * 16 + gid + ((e >= 2) ? 8 : 0);
                int n = n0 + wc * WN + j * 8 + 2 * tg + (e & 1);
                if (m < M && n < Nn) {
                    float v = acc[i][j][e] * alpha;
                    if (EPI == 0) {
                        C[(long long)z * sC + (long long)m * ldc + n] = v;
                    } else if (EPI == 1) {
                        C[(long long)m * ldc + n] = v + R[(long long)m * ldc + n];
                    } else if (EPI == 2) {
                        int b = m >> 9, nn = m & (SEQ - 1), h = n >> 6, d = n & (DHEAD - 1);
                        C[((((long long)b * HEADS + h) * SEQ + nn) << 6) + d] = cvtf(v);
                    } else { // EPI == 4
                        C[(long long)m * ldc + n] = cvtf(v + R[(long long)m * ldc + n]);
                    }
                }
            }
        }
    }
}

// ---------------- tf32 GEGLU GEMM (two NT B tiles), cp.async double-buffered ------
template<int BM, int BN, int BK, int WM, int WN>
__global__ __launch_bounds__(256, 1)
void tgemm_geglu(const float* __restrict__ A, const float* __restrict__ B,
                 float* __restrict__ C, int M, int Nn, int K, int ldb, int ldc) {
    constexpr int WARPS_N = BN / WN;
    constexpr int MT = WM / 16, NT = WN / 8;
    constexpr int AST = BK + 4;
    constexpr int BST = BK + 4;
    constexpr int ABUF = BM * AST;
    constexpr int BBUF = BN * BST;

    extern __shared__ float smem[];
    float* Asm = smem;
    float* B1m = smem + 2 * ABUF;
    float* B2m = B1m + 2 * BBUF;

    const int m0 = blockIdx.y * BM;
    const int n0 = blockIdx.x * BN;
    const int tid = threadIdx.x;
    const int warp = tid >> 5, lane = tid & 31;
    const int wr = warp / WARPS_N, wc = warp % WARPS_N;
    const int gid = lane >> 2, tg = lane & 3;

    const uint32_t sAb = (uint32_t)__cvta_generic_to_shared(Asm);
    const uint32_t sB1 = (uint32_t)__cvta_generic_to_shared(B1m);
    const uint32_t sB2 = (uint32_t)__cvta_generic_to_shared(B2m);

    float a1[MT][NT][4], a2[MT][NT][4];
    #pragma unroll
    for (int i = 0; i < MT; i++)
        #pragma unroll
        for (int j = 0; j < NT; j++)
            #pragma unroll
            for (int e = 0; e < 4; e++) { a1[i][j][e] = 0.f; a2[i][j][e] = 0.f; }

    const int NIT = K / BK;

    auto stage = [&](int b, int k0) {
        constexpr int ACH = BK / 4;
        #pragma unroll
        for (int c = tid; c < BM * ACH; c += 256) {
            int m = c / ACH, kc = c % ACH;
            uint32_t sp = sAb + (uint32_t)((b * ABUF + m * AST + kc * 4) << 2);
            cp16(sp, A + (long long)(m0 + m) * K + k0 + kc * 4, 16);
        }
        constexpr int BCH = BK / 4;
        #pragma unroll
        for (int c = tid; c < BN * BCH; c += 256) {
            int n = c / BCH, kc = c % BCH;
            int gn = n0 + n; if (gn > FFH - 1) gn = FFH - 1;
            uint32_t o = (uint32_t)((b * BBUF + n * BST + kc * 4) << 2);
            cp16(sB1 + o, B + (long long)gn * ldb + k0 + kc * 4, 16);
            cp16(sB2 + o, B + (long long)(gn + FFH) * ldb + k0 + kc * 4, 16);
        }
    };

    stage(0, 0);
    cp_commit();
    int buf = 0;
    for (int it = 0; it < NIT; it++) {
        if (it + 1 < NIT) { stage(buf ^ 1, (it + 1) * BK); cp_commit(); cp_wait1(); }
        else cp_wait0();
        __syncthreads();

        const float* Ab  = Asm + buf * ABUF;
        const float* Bb1 = B1m + buf * BBUF;
        const float* Bb2 = B2m + buf * BBUF;
        #pragma unroll
        for (int ks = 0; ks < BK; ks += 8) {
            uint32_t af[MT][4];
            uint32_t bf1[NT][2], bf2[NT][2];
            #pragma unroll
            for (int i = 0; i < MT; i++) {
                int mb = wr * WM + i * 16 + gid;
                af[i][0] = __float_as_uint(Ab[mb * AST + ks + tg]);
                af[i][1] = __float_as_uint(Ab[(mb + 8) * AST + ks + tg]);
                af[i][2] = __float_as_uint(Ab[mb * AST + ks + tg + 4]);
                af[i][3] = __float_as_uint(Ab[(mb + 8) * AST + ks + tg + 4]);
            }
            #pragma unroll
            for (int j = 0; j < NT; j++) {
                int nb = wc * WN + j * 8 + gid;
                bf1[j][0] = __float_as_uint(Bb1[nb * BST + ks + tg]);
                bf1[j][1] = __float_as_uint(Bb1[nb * BST + ks + tg + 4]);
                bf2[j][0] = __float_as_uint(Bb2[nb * BST + ks + tg]);
                bf2[j][1] = __float_as_uint(Bb2[nb * BST + ks + tg + 4]);
            }
            #pragma unroll
            for (int i = 0; i < MT; i++)
                #pragma unroll
                for (int j = 0; j < NT; j++) {
                    mma_tf32(a1[i][j], af[i], bf1[j]);
                    mma_tf32(a2[i][j], af[i], bf2[j]);
                }
        }
        __syncthreads();
        buf ^= 1;
    }

    #pragma unroll
    for (int i = 0; i < MT; i++) {
        #pragma unroll
        for (int j = 0; j < NT; j++) {
            #pragma unroll
            for (int e = 0; e < 4; e++) {
                int m = m0 + wr * WM + i * 16 + gid + ((e >= 2) ? 8 : 0);
                int n = n0 + wc * WN + j * 8 + 2 * tg + (e & 1);
                if (m < M && n < Nn) {
                    float g  = a2[i][j][e];
                    float ge = 0.5f * g * (1.f + erff(g * 0.70710678118654752f));
                    C[(long long)m * ldc + n] = a1[i][j][e] * ge;
                }
            }
        }
    }
}

// ---------------- launch ---------------------------------------------------------
extern "C" void kernel_launch(void* const* d_in, const int* in_sizes, int n_in,
                              void* d_out, int out_size) {
    const float* x      = (const float*)d_in[0];
    const float* g_ln   = (const float*)d_in[1];
    const float* Wq     = (const float*)d_in[2];
    const float* Wkv    = (const float*)d_in[3];
    const float* Wo     = (const float*)d_in[4];
    const float* cpb_w1 = (const float*)d_in[5];
    const float* cpb_b1 = (const float*)d_in[6];
    const float* cpb_w2 = (const float*)d_in[7];
    const float* cpb_b2 = (const float*)d_in[8];
    const float* cpb_w3 = (const float*)d_in[9];
    const float* cpb_b3 = (const float*)d_in[10];
    const float* ff_w_in  = (const float*)d_in[11];
    const float* ff_g     = (const float*)d_in[12];
    const float* ff_w_out = (const float*)d_in[13];
    float* out = (float*)d_out;

    float *bias, *xn, *q, *k, *v, *o, *y, *t;
    float *cWq, *cWkv, *cWo, *cWin, *cWoutP;
    cudaGetSymbolAddress((void**)&bias, g_bias);
    cudaGetSymbolAddress((void**)&xn,  g_xn);
    cudaGetSymbolAddress((void**)&q,   g_q);
    cudaGetSymbolAddress((void**)&k,   g_k);
    cudaGetSymbolAddress((void**)&v,   g_v);
    cudaGetSymbolAddress((void**)&o,   g_o);
    cudaGetSymbolAddress((void**)&y,   g_y);
    cudaGetSymbolAddress((void**)&t,   g_t);
    cudaGetSymbolAddress((void**)&cWq,    g_cWq);
    cudaGetSymbolAddress((void**)&cWkv,   g_cWkv);
    cudaGetSymbolAddress((void**)&cWo,    g_cWo);
    cudaGetSymbolAddress((void**)&cWin,   g_cWin);
    cudaGetSymbolAddress((void**)&cWoutP, g_cWoutP);

    auto T_QKV = tgemm<256,128,32,64,64,false,2,1>;
    auto T_OP  = tgemm<256,128,32,64,64,false,4,1>;
    auto T_FFO = tgemm<256,128,32,64,64,true, 1,1>;
    auto T_GG  = tgemm_geglu<256,64,32,64,32>;

    const int SM_BIG_NN = (2*256*36 + 2*32*132) * 4;
    const int SM_BIG_TT = (2*256*36 + 2*128*36) * 4;
    const int SM_GG     = (2*256*36 + 4*64*36)  * 4;
    const int SM_FA     = FA_TOT * 4;

    cudaFuncSetAttribute(T_QKV, cudaFuncAttributeMaxDynamicSharedMemorySize, SM_BIG_NN);
    cudaFuncSetAttribute(T_OP,  cudaFuncAttributeMaxDynamicSharedMemorySize, SM_BIG_NN);
    cudaFuncSetAttribute(T_FFO, cudaFuncAttributeMaxDynamicSharedMemorySize, SM_BIG_TT);
    cudaFuncSetAttribute(T_GG,  cudaFuncAttributeMaxDynamicSharedMemorySize, SM_GG);
    cudaFuncSetAttribute(flash_kernel, cudaFuncAttributeMaxDynamicSharedMemorySize, SM_FA);

    // 0) weight preconversion (tf32-rna into scratch copies)
    cvt4_kernel<<<512, 256>>>((const float4*)Wq,      (float4*)cWq,   DIMV*INNERV/4);
    cvt4_kernel<<<512, 256>>>((const float4*)Wkv,     (float4*)cWkv,  DIMV*2*INNERV/4);
    cvt4_kernel<<<512, 256>>>((const float4*)Wo,      (float4*)cWo,   INNERV*DIMV/4);
    cvt4_kernel<<<512, 256>>>((const float4*)ff_w_in, (float4*)cWin,  2*FFH*DIMV/4);
    cvt_pad_kernel<<<dim3((LDT+255)/256, DIMV), 256>>>(ff_w_out, cWoutP);

    // 1) CPB bias table
    cpb_kernel<<<1023, 512>>>(cpb_w1, cpb_b1, cpb_w2, cpb_b2, cpb_w3, cpb_b3, bias);

    // 2) sequence-axis LayerNorm (tf32 out)
    seqln_kernel<<<dim3(DIMV / 256, BATCH), 256>>>(x, g_ln, xn);

    // 3) Q/K/V projections, head-split stores (tf32 out)
    T_QKV<<<dim3(8,32,1),256,SM_BIG_NN>>>(xn, cWq,         q, nullptr,
        MROWS, INNERV, DIMV, DIMV, INNERV,   0, 0, 0, 0, 1.f);
    T_QKV<<<dim3(8,32,1),256,SM_BIG_NN>>>(xn, cWkv,        k, nullptr,
        MROWS, INNERV, DIMV, DIMV, 2*INNERV, 0, 0, 0, 0, 1.f);
    T_QKV<<<dim3(8,32,1),256,SM_BIG_NN>>>(xn, cWkv+INNERV, v, nullptr,
        MROWS, INNERV, DIMV, DIMV, 2*INNERV, 0, 0, 0, 0, 1.f);

    // 4-6) fused flash attention (QK^T + bias + softmax + PV)
    flash_kernel<<<dim3(SEQ/128, BATCH*HEADS), 256, SM_FA>>>(q, k, v, bias, o);

    // 7) y = O @ Wo + x (tf32 out)
    T_OP<<<dim3(8,32,1),256,SM_BIG_NN>>>(o, cWo, y, x,
        MROWS, DIMV, INNERV, INNERV, DIMV, DIMV, 0, 0, 0, 1.f);

    // 8) FF-in + fused GEGLU
    T_GG<<<dim3((FFH+63)/64, 32),256,SM_GG>>>(y, cWin, t,
        MROWS, FFH, DIMV, DIMV, LDT);

    // 9) channel LayerNorm (stride LDT, tf32 out + zero padding)
    chanln_kernel<<<MROWS, 256>>>(t, ff_g);

    // 10) out = t @ cWoutP^T + y  (K padded to 2752 with zeros)
    T_FFO<<<dim3(8,32,1),256,SM_BIG_TT>>>(t, cWoutP, out, y,
        MROWS, DIMV, LDT, LDT, LDT, DIMV, 0, 0, 0, 1.f);
}

// round 9
// speedup vs baseline: 14.0656x; 1.4609x over previous
#include <cuda_runtime.h>
#include <cuda_fp16.h>
#include <math.h>
#include <stdint.h>

#define DIMV 1024
#define HEADS 16
#define DHEAD 64
#define BATCH 16
#define SEQ 512
#define INNERV 1024
#define CPBD 512
#define FFH 2730
#define LDT 2752            /* padded leading dim for t / cWout (halfs): 86*32 */
#define MROWS (BATCH*SEQ)   /* 8192 */
#define EPSV 1e-5f

// ---------------- scratch (static device arrays; no allocations) ----------------
__device__ float  g_bias[HEADS * 1023];
__device__ __half g_xn[(size_t)MROWS * DIMV];
__device__ __half g_q[(size_t)MROWS * INNERV];
__device__ __half g_k[(size_t)MROWS * INNERV];
__device__ __half g_v[(size_t)MROWS * INNERV];
__device__ __half g_o[(size_t)MROWS * INNERV];
__device__ float  g_y[(size_t)MROWS * DIMV];      // fp32 residual copy
__device__ __half g_yh[(size_t)MROWS * DIMV];     // half mirror (GEMM A operand)
__device__ __half g_t[(size_t)MROWS * LDT];
// half-preconverted weights (QKV/O transposed to [n][k])
__device__ __half g_cWqT[(size_t)INNERV * DIMV];
__device__ __half g_cWkvT[(size_t)2 * INNERV * DIMV];
__device__ __half g_cWoT[(size_t)DIMV * INNERV];
__device__ __half g_cWin[(size_t)2 * FFH * DIMV];
__device__ __half g_cWoutP[(size_t)DIMV * LDT];

// ---------------- helpers ---------------------------------------------------------
__device__ __forceinline__ void mma_f16(float d[4], const uint32_t a[4], const uint32_t b[2]) {
    asm volatile(
        "mma.sync.aligned.m16n8k16.row.col.f32.f16.f16.f32 "
        "{%0,%1,%2,%3},{%4,%5,%6,%7},{%8,%9},{%0,%1,%2,%3};\n"
        : "+f"(d[0]), "+f"(d[1]), "+f"(d[2]), "+f"(d[3])
        : "r"(a[0]), "r"(a[1]), "r"(a[2]), "r"(a[3]), "r"(b[0]), "r"(b[1]));
}
__device__ __forceinline__ void cp16(uint32_t s, const void* g) {
    asm volatile("cp.async.cg.shared.global [%0], [%1], 16;\n" :: "r"(s), "l"(g));
}
__device__ __forceinline__ void cp_commit() { asm volatile("cp.async.commit_group;\n"); }
__device__ __forceinline__ void cp_wait1()  { asm volatile("cp.async.wait_group 1;\n"); }
__device__ __forceinline__ void cp_wait0()  { asm volatile("cp.async.wait_group 0;\n"); }
__device__ __forceinline__ float qmax2(float v) {
    v = fmaxf(v, __shfl_xor_sync(0xffffffffu, v, 1));
    v = fmaxf(v, __shfl_xor_sync(0xffffffffu, v, 2));
    return v;
}
__device__ __forceinline__ float qsum2(float v) {
    v += __shfl_xor_sync(0xffffffffu, v, 1);
    v += __shfl_xor_sync(0xffffffffu, v, 2);
    return v;
}
__device__ __forceinline__ uint32_t ldh2(const __half* p) { return *(const uint32_t*)p; }

// ---------------- weight preconvert kernels ---------------------------------------
// transpose + cvt: in [K][N] float -> out [N][K] half
__global__ void cvtT_kernel(const float* __restrict__ in, __half* __restrict__ out,
                            int K, int N) {
    __shared__ float tile[32][33];
    int n0 = blockIdx.x * 32, k0 = blockIdx.y * 32;
    int tx = threadIdx.x, ty0 = threadIdx.y;
    #pragma unroll
    for (int ty = ty0; ty < 32; ty += 8)
        tile[ty][tx] = in[(size_t)(k0 + ty) * N + n0 + tx];
    __syncthreads();
    #pragma unroll
    for (int ty = ty0; ty < 32; ty += 8)
        out[(size_t)(n0 + ty) * K + k0 + tx] = __float2half(tile[tx][ty]);
}
// elementwise cvt float -> half (n multiple of 4)
__global__ void cvtH_kernel(const float4* __restrict__ in, __half2* __restrict__ out, int n4) {
    int i = blockIdx.x * blockDim.x + threadIdx.x;
    int stride = gridDim.x * blockDim.x;
    for (; i < n4; i += stride) {
        float4 v = in[i];
        out[2 * i]     = __floats2half2_rn(v.x, v.y);
        out[2 * i + 1] = __floats2half2_rn(v.z, v.w);
    }
}
// ff_w_out [DIMV][FFH] float -> [DIMV][LDT] half (tail zeros)
__global__ void cvt_pad_kernel(const float* __restrict__ in, __half* __restrict__ out) {
    int r = blockIdx.y;
    int c = blockIdx.x * 256 + threadIdx.x;
    if (c < LDT) out[(size_t)r * LDT + c] =
        (c < FFH) ? __float2half(in[(size_t)r * FFH + c]) : __half(0.f);
}

// ---------------- CPB: bias table over 1023 distinct relative positions ----------
__global__ void cpb_kernel(const float* __restrict__ w1, const float* __restrict__ b1,
                           const float* __restrict__ w2, const float* __restrict__ b2,
                           const float* __restrict__ w3, const float* __restrict__ b3,
                           float* __restrict__ table) {
    int ridx = blockIdx.x;
    float rf = (float)(ridx - 511);
    float sgn = (rf > 0.f) ? 1.f : ((rf < 0.f) ? -1.f : 0.f);
    float rel = sgn * logf(fabsf(rf) + 1.f);

    __shared__ float h1[CPBD];
    __shared__ float h2[CPBD];
    int t = threadIdx.x;
    {
        float z = rel * w1[t] + b1[t];
        h1[t] = z / (1.f + expf(-z));
    }
    __syncthreads();
    {
        float acc = b2[t];
        #pragma unroll 4
        for (int j = 0; j < CPBD; j++) acc += h1[j] * w2[j * CPBD + t];
        h2[t] = acc / (1.f + expf(-acc));
    }
    __syncthreads();
    int warp = t >> 5, lane = t & 31;
    float acc = 0.f;
    for (int i = lane; i < CPBD; i += 32) acc += h2[i] * w3[i * HEADS + warp];
    #pragma unroll
    for (int off = 16; off; off >>= 1) acc += __shfl_down_sync(0xffffffffu, acc, off);
    if (lane == 0) table[warp * 1023 + ridx] = acc + b3[warp];
}

// ---------------- sequence-axis LayerNorm (fp32 stats, half out) ------------------
__global__ void seqln_kernel(const float* __restrict__ x, const float* __restrict__ g,
                             __half* __restrict__ xn) {
    int d = blockIdx.x * blockDim.x + threadIdx.x;
    int b = blockIdx.y;
    const float* xb = x + (size_t)b * SEQ * DIMV;
    float s = 0.f, ss = 0.f;
    for (int n = 0; n < SEQ; n++) { float v = xb[n * DIMV + d]; s += v; ss += v * v; }
    float mean = s * (1.f / SEQ);
    float var  = ss * (1.f / SEQ) - mean * mean;
    float inv  = rsqrtf(fmaxf(var, EPSV)) * g[d];
    __half* ob = xn + (size_t)b * SEQ * DIMV;
    for (int n = 0; n < SEQ; n++) ob[n * DIMV + d] = __float2half((xb[n * DIMV + d] - mean) * inv);
}

// ---------------- fused flash attention (fp16 mma, fp32 online softmax) -----------
// grid: (SEQ/128, BATCH*HEADS). 256 threads = 8 warps; warp w owns q rows [16w,16w+16).
// q/k/v half [b,h,n,d]. Writes o half into [b,n,h*64+d].
#define FA_ST  72                                    /* stride in halfs */
#define FA_QS  0
#define FA_KS  (FA_QS + 128*FA_ST)                   /* 9216  halfs */
#define FA_VS  (FA_KS + 2*64*FA_ST)                  /* 18432 */
#define FA_PS  (FA_VS + 2*64*FA_ST)                  /* 27648 */
#define FA_HEND (FA_PS + 8*16*FA_ST)                 /* 36864 halfs = 73728 B */
#define FA_BYTES (FA_HEND*2 + 1024*4)                /* + bias floats = 77824 B */

__global__ __launch_bounds__(256, 1)
void flash_kernel(const __half* __restrict__ q, const __half* __restrict__ k,
                  const __half* __restrict__ v, const float* __restrict__ table,
                  __half* __restrict__ o) {
    extern __shared__ char smraw[];
    __half* smh = (__half*)smraw;
    float*  Bi  = (float*)(smraw + FA_HEND * 2);

    const int qt = blockIdx.x;
    const int z  = blockIdx.y;
    const int h  = z & (HEADS - 1);
    const int b  = z >> 4;
    const int qbase = qt * 128;
    const int tid = threadIdx.x;
    const int w = tid >> 5, lane = tid & 31;
    const int gid = lane >> 2, tg = lane & 3;

    const __half* qz = q + (size_t)z * SEQ * DHEAD;
    const __half* kz = k + (size_t)z * SEQ * DHEAD;
    const __half* vz = v + (size_t)z * SEQ * DHEAD;

    const uint32_t sbase = (uint32_t)__cvta_generic_to_shared(smh);

    // stage Q (once): 128 rows x 8 chunks of 8 halfs
    #pragma unroll
    for (int c = tid; c < 128 * 8; c += 256) {
        int m = c >> 3, kc = c & 7;
        cp16(sbase + (uint32_t)((FA_QS + m * FA_ST + kc * 8) * 2),
             qz + (qbase + m) * DHEAD + kc * 8);
    }
    for (int i = tid; i < 1023; i += 256) Bi[i] = table[h * 1023 + i];

    auto stage_kv = [&](int buf, int jt) {
        int kb = jt * 64;
        #pragma unroll
        for (int c = tid; c < 64 * 8; c += 256) {
            int r = c >> 3, kc = c & 7;
            cp16(sbase + (uint32_t)((FA_KS + buf * 64 * FA_ST + r * FA_ST + kc * 8) * 2),
                 kz + (kb + r) * DHEAD + kc * 8);
            cp16(sbase + (uint32_t)((FA_VS + buf * 64 * FA_ST + r * FA_ST + kc * 8) * 2),
                 vz + (kb + r) * DHEAD + kc * 8);
        }
    };

    stage_kv(0, 0);
    cp_commit();

    float m_row[2] = {-1e30f, -1e30f};
    float l_row[2] = {0.f, 0.f};
    float oacc[8][4];
    #pragma unroll
    for (int j = 0; j < 8; j++)
        #pragma unroll
        for (int e = 0; e < 4; e++) oacc[j][e] = 0.f;

    const __half* Qs = smh + FA_QS;
    __half* Ps = smh + FA_PS + w * 16 * FA_ST;

    int buf = 0;
    for (int jt = 0; jt < 8; jt++) {
        if (jt + 1 < 8) { stage_kv(buf ^ 1, jt + 1); cp_commit(); cp_wait1(); }
        else cp_wait0();
        __syncthreads();

        const __half* Ks = smh + FA_KS + buf * 64 * FA_ST;
        const __half* Vs = smh + FA_VS + buf * 64 * FA_ST;
        const int kb = jt * 64;

        // ---- S = Q K^T : 4 ksteps of 16 ----
        float s[8][4];
        #pragma unroll
        for (int j = 0; j < 8; j++)
            #pragma unroll
            for (int e = 0; e < 4; e++) s[j][e] = 0.f;
        #pragma unroll
        for (int ks = 0; ks < 64; ks += 16) {
            uint32_t a[4];
            int mb = w * 16 + gid;
            a[0] = ldh2(&Qs[mb * FA_ST + ks + 2 * tg]);
            a[1] = ldh2(&Qs[(mb + 8) * FA_ST + ks + 2 * tg]);
            a[2] = ldh2(&Qs[mb * FA_ST + ks + 2 * tg + 8]);
            a[3] = ldh2(&Qs[(mb + 8) * FA_ST + ks + 2 * tg + 8]);
            #pragma unroll
            for (int j = 0; j < 8; j++) {
                uint32_t bfr[2];
                int nb = j * 8 + gid;
                bfr[0] = ldh2(&Ks[nb * FA_ST + ks + 2 * tg]);
                bfr[1] = ldh2(&Ks[nb * FA_ST + ks + 2 * tg + 8]);
                mma_f16(s[j], a, bfr);
            }
        }

        // ---- scale + bias, online softmax ----
        int qi0 = qbase + w * 16 + gid;
        float mx0 = -1e30f, mx1 = -1e30f;
        #pragma unroll
        for (int j = 0; j < 8; j++) {
            int kj = kb + j * 8 + 2 * tg;
            s[j][0] = s[j][0] * 0.125f + Bi[qi0 - kj + 511];
            s[j][1] = s[j][1] * 0.125f + Bi[qi0 - kj + 510];
            s[j][2] = s[j][2] * 0.125f + Bi[qi0 + 8 - kj + 511];
            s[j][3] = s[j][3] * 0.125f + Bi[qi0 + 8 - kj + 510];
            mx0 = fmaxf(mx0, fmaxf(s[j][0], s[j][1]));
            mx1 = fmaxf(mx1, fmaxf(s[j][2], s[j][3]));
        }
        mx0 = qmax2(mx0); mx1 = qmax2(mx1);
        float mn0 = fmaxf(m_row[0], mx0), mn1 = fmaxf(m_row[1], mx1);
        float sc0 = __expf(m_row[0] - mn0), sc1 = __expf(m_row[1] - mn1);
        float rs0 = 0.f, rs1 = 0.f;
        #pragma unroll
        for (int j = 0; j < 8; j++) {
            s[j][0] = __expf(s[j][0] - mn0);
            s[j][1] = __expf(s[j][1] - mn0);
            s[j][2] = __expf(s[j][2] - mn1);
            s[j][3] = __expf(s[j][3] - mn1);
            rs0 += s[j][0] + s[j][1];
            rs1 += s[j][2] + s[j][3];
        }
        rs0 = qsum2(rs0); rs1 = qsum2(rs1);
        l_row[0] = l_row[0] * sc0 + rs0;
        l_row[1] = l_row[1] * sc1 + rs1;
        m_row[0] = mn0; m_row[1] = mn1;
        #pragma unroll
        for (int j = 0; j < 8; j++) {
            oacc[j][0] *= sc0; oacc[j][1] *= sc0;
            oacc[j][2] *= sc1; oacc[j][3] *= sc1;
        }

        // ---- store P (half) to warp-private smem ----
        #pragma unroll
        for (int j = 0; j < 8; j++) {
            *(__half2*)&Ps[gid * FA_ST + j * 8 + 2 * tg]       = __floats2half2_rn(s[j][0], s[j][1]);
            *(__half2*)&Ps[(gid + 8) * FA_ST + j * 8 + 2 * tg] = __floats2half2_rn(s[j][2], s[j][3]);
        }
        __syncwarp();

        // ---- O += P V : key dim 64, 4 ksteps of 16 ----
        #pragma unroll
        for (int ks = 0; ks < 64; ks += 16) {
            uint32_t a[4];
            a[0] = ldh2(&Ps[gid * FA_ST + ks + 2 * tg]);
            a[1] = ldh2(&Ps[(gid + 8) * FA_ST + ks + 2 * tg]);
            a[2] = ldh2(&Ps[gid * FA_ST + ks + 2 * tg + 8]);
            a[3] = ldh2(&Ps[(gid + 8) * FA_ST + ks + 2 * tg + 8]);
            #pragma unroll
            for (int j = 0; j < 8; j++) {
                int nb = j * 8 + gid;
                __half2 b0, b1;
                b0.x = Vs[(ks + 2 * tg) * FA_ST + nb];
                b0.y = Vs[(ks + 2 * tg + 1) * FA_ST + nb];
                b1.x = Vs[(ks + 2 * tg + 8) * FA_ST + nb];
                b1.y = Vs[(ks + 2 * tg + 9) * FA_ST + nb];
                uint32_t bfr[2] = { *(uint32_t*)&b0, *(uint32_t*)&b1 };
                mma_f16(oacc[j], a, bfr);
            }
        }
        __syncwarp();
        __syncthreads();
        buf ^= 1;
    }

    // ---- epilogue: O / l, store half [b, n, h*64+d] ----
    float inv0 = 1.f / l_row[0], inv1 = 1.f / l_row[1];
    int qi = qbase + w * 16 + gid;
    #pragma unroll
    for (int j = 0; j < 8; j++) {
        int d = j * 8 + 2 * tg;
        size_t r0 = ((size_t)(b * SEQ + qi) * INNERV) + h * DHEAD + d;
        size_t r1 = ((size_t)(b * SEQ + qi + 8) * INNERV) + h * DHEAD + d;
        *(__half2*)&o[r0] = __floats2half2_rn(oacc[j][0] * inv0, oacc[j][1] * inv0);
        *(__half2*)&o[r1] = __floats2half2_rn(oacc[j][2] * inv1, oacc[j][3] * inv1);
    }
}

// ---------------- channel LayerNorm over FFH per token (half in/out, fp32 stats) --
__global__ void chanln_kernel(__half* __restrict__ tb, const float* __restrict__ gg) {
    int m = blockIdx.x;
    __half* row = tb + (size_t)m * LDT;
    int t = threadIdx.x;
    float s = 0.f, ss = 0.f;
    for (int j = t; j < FFH; j += 256) { float v = __half2float(row[j]); s += v; ss += v * v; }
    __shared__ float r1[256], r2[256];
    r1[t] = s; r2[t] = ss; __syncthreads();
    for (int k = 128; k; k >>= 1) { if (t < k) { r1[t] += r1[t + k]; r2[t] += r2[t + k]; } __syncthreads(); }
    float mean = r1[0] * (1.f / FFH);
    float var  = r2[0] * (1.f / FFH) - mean * mean;
    float inv  = rsqrtf(fmaxf(var, EPSV));
    for (int j = t; j < FFH; j += 256)
        row[j] = __float2half((__half2float(row[j]) - mean) * inv * gg[j]);
    if (t < LDT - FFH) row[FFH + t] = __half(0.f);
}

// ---------------- fp16 tensor-core GEMM, all-NT, cp.async double-buffered ---------
// A [M][K] half row-major; B [N][K] half row-major. Accum fp32.
// EPI: 1 = Cf[m*ldc+n] = v + R (float out); 2 = head-split half store;
//      4 = y float + yh half
template<int BM, int BN, int BK, int WM, int WN, int EPI>
__global__ __launch_bounds__(256, 1)
void hgemm(const __half* __restrict__ A, const __half* __restrict__ B,
           float* __restrict__ Cf, __half* __restrict__ Ch, const float* __restrict__ R,
           int M, int Nn, int K, int lda, int ldb, int ldc) {
    constexpr int WARPS_N = BN / WN;
    constexpr int MT = WM / 16, NT = WN / 8;
    constexpr int AST = BK + 8;             // halfs
    constexpr int BST = BK + 8;
    constexpr int ABUF = BM * AST;
    constexpr int BBUF = BN * BST;

    extern __shared__ char smraw[];
    __half* Asm = (__half*)smraw;
    __half* Bsm = Asm + 2 * ABUF;

    const int m0 = blockIdx.y * BM;
    const int n0 = blockIdx.x * BN;
    const int tid = threadIdx.x;
    const int warp = tid >> 5, lane = tid & 31;
    const int wr = warp / WARPS_N, wc = warp % WARPS_N;
    const int gid = lane >> 2, tg = lane & 3;

    const uint32_t sAb = (uint32_t)__cvta_generic_to_shared(Asm);
    const uint32_t sBb = (uint32_t)__cvta_generic_to_shared(Bsm);

    float acc[MT][NT][4];
    #pragma unroll
    for (int i = 0; i < MT; i++)
        #pragma unroll
        for (int j = 0; j < NT; j++)
            #pragma unroll
            for (int e = 0; e < 4; e++) acc[i][j][e] = 0.f;

    const int NIT = K / BK;

    auto stage = [&](int b, int k0) {
        constexpr int ACH = BK / 8;         // 16B = 8 halfs
        #pragma unroll
        for (int c = tid; c < BM * ACH; c += 256) {
            int m = c / ACH, kc = c % ACH;
            cp16(sAb + (uint32_t)((b * ABUF + m * AST + kc * 8) * 2),
                 A + (size_t)(m0 + m) * lda + k0 + kc * 8);
        }
        constexpr int BCH = BK / 8;
        #pragma unroll
        for (int c = tid; c < BN * BCH; c += 256) {
            int n = c / BCH, kc = c % BCH;
            cp16(sBb + (uint32_t)((b * BBUF + n * BST + kc * 8) * 2),
                 B + (size_t)(n0 + n) * ldb + k0 + kc * 8);
        }
    };

    stage(0, 0);
    cp_commit();
    int buf = 0;
    for (int it = 0; it < NIT; it++) {
        if (it + 1 < NIT) { stage(buf ^ 1, (it + 1) * BK); cp_commit(); cp_wait1(); }
        else cp_wait0();
        __syncthreads();

        const __half* Ab = Asm + buf * ABUF;
        const __half* Bb = Bsm + buf * BBUF;
        #pragma unroll
        for (int ks = 0; ks < BK; ks += 16) {
            uint32_t af[MT][4];
            uint32_t bf[NT][2];
            #pragma unroll
            for (int i = 0; i < MT; i++) {
                int mb = wr * WM + i * 16 + gid;
                af[i][0] = ldh2(&Ab[mb * AST + ks + 2 * tg]);
                af[i][1] = ldh2(&Ab[(mb + 8) * AST + ks + 2 * tg]);
                af[i][2] = ldh2(&Ab[mb * AST + ks + 2 * tg + 8]);
                af[i][3] = ldh2(&Ab[(mb + 8) * AST + ks + 2 * tg + 8]);
            }
            #pragma unroll
            for (int j = 0; j < NT; j++) {
                int nb = wc * WN + j * 8 + gid;
                bf[j][0] = ldh2(&Bb[nb * BST + ks + 2 * tg]);
                bf[j][1] = ldh2(&Bb[nb * BST + ks + 2 * tg + 8]);
            }
            #pragma unroll
            for (int i = 0; i < MT; i++)
                #pragma unroll
                for (int j = 0; j < NT; j++)
                    mma_f16(acc[i][j], af[i], bf[j]);
        }
        __syncthreads();
        buf ^= 1;
    }

    #pragma unroll
    for (int i = 0; i < MT; i++) {
        #pragma unroll
        for (int j = 0; j < NT; j++) {
            #pragma unroll
            for (int e = 0; e < 4; e++) {
                int m = m0 + wr * WM + i * 16 + gid + ((e >= 2) ? 8 : 0);
                int n = n0 + wc * WN + j * 8 + 2 * tg + (e & 1);
                if (m < M && n < Nn) {
                    float v = acc[i][j][e];
                    if (EPI == 1) {
                        Cf[(size_t)m * ldc + n] = v + R[(size_t)m * ldc + n];
                    } else if (EPI == 2) {
                        int b = m >> 9, nn = m & (SEQ - 1), h = n >> 6, d = n & (DHEAD - 1);
                        Ch[((((size_t)b * HEADS + h) * SEQ + nn) << 6) + d] = __float2half(v);
                    } else { // EPI == 4
                        float r = v + R[(size_t)m * ldc + n];
                        Cf[(size_t)m * ldc + n] = r;
                        Ch[(size_t)m * ldc + n] = __float2half(r);
                    }
                }
            }
        }
    }
}

// ---------------- fp16 GEGLU GEMM (two NT B tiles) --------------------------------
// A [M][K] half (yh); B = cWin [2*FFH][K] half NT; C half stride ldc.
template<int BM, int BN, int BK, int WM, int WN>
__global__ __launch_bounds__(256, 1)
void hgemm_geglu(const __half* __restrict__ A, const __half* __restrict__ B,
                 __half* __restrict__ C, int M, int Nn, int K, int ldb, int ldc) {
    constexpr int WARPS_N = BN / WN;
    constexpr int MT = WM / 16, NT = WN / 8;
    constexpr int AST = BK + 8;
    constexpr int BST = BK + 8;
    constexpr int ABUF = BM * AST;
    constexpr int BBUF = BN * BST;

    extern __shared__ char smraw[];
    __half* Asm = (__half*)smraw;
    __half* B1m = Asm + 2 * ABUF;
    __half* B2m = B1m + 2 * BBUF;

    const int m0 = blockIdx.y * BM;
    const int n0 = blockIdx.x * BN;
    const int tid = threadIdx.x;
    const int warp = tid >> 5, lane = tid & 31;
    const int wr = warp / WARPS_N, wc = warp % WARPS_N;
    const int gid = lane >> 2, tg = lane & 3;

    const uint32_t sAb = (uint32_t)__cvta_generic_to_shared(Asm);
    const uint32_t sB1 = (uint32_t)__cvta_generic_to_shared(B1m);
    const uint32_t sB2 = (uint32_t)__cvta_generic_to_shared(B2m);

    float a1[MT][NT][4], a2[MT][NT][4];
    #pragma unroll
    for (int i = 0; i < MT; i++)
        #pragma unroll
        for (int j = 0; j < NT; j++)
            #pragma unroll
            for (int e = 0; e < 4; e++) { a1[i][j][e] = 0.f; a2[i][j][e] = 0.f; }

    const int NIT = K / BK;

    auto stage = [&](int b, int k0) {
        constexpr int ACH = BK / 8;
        #pragma unroll
        for (int c = tid; c < BM * ACH; c += 256) {
            int m = c / ACH, kc = c % ACH;
            cp16(sAb + (uint32_t)((b * ABUF + m * AST + kc * 8) * 2),
                 A + (size_t)(m0 + m) * K + k0 + kc * 8);
        }
        constexpr int BCH = BK / 8;
        #pragma unroll
        for (int c = tid; c < BN * BCH; c += 256) {
            int n = c / BCH, kc = c % BCH;
            int gn = n0 + n; if (gn > FFH - 1) gn = FFH - 1;
            uint32_t off = (uint32_t)((b * BBUF + n * BST + kc * 8) * 2);
            cp16(sB1 + off, B + (size_t)gn * ldb + k0 + kc * 8);
            cp16(sB2 + off, B + (size_t)(gn + FFH) * ldb + k0 + kc * 8);
        }
    };

    stage(0, 0);
    cp_commit();
    int buf = 0;
    for (int it = 0; it < NIT; it++) {
        if (it + 1 < NIT) { stage(buf ^ 1, (it + 1) * BK); cp_commit(); cp_wait1(); }
        else cp_wait0();
        __syncthreads();

        const __half* Ab  = Asm + buf * ABUF;
        const __half* Bb1 = B1m + buf * BBUF;
        const __half* Bb2 = B2m + buf * BBUF;
        #pragma unroll
        for (int ks = 0; ks < BK; ks += 16) {
            uint32_t af[MT][4];
            uint32_t bf1[NT][2], bf2[NT][2];
            #pragma unroll
            for (int i = 0; i < MT; i++) {
                int mb = wr * WM + i * 16 + gid;
                af[i][0] = ldh2(&Ab[mb * AST + ks + 2 * tg]);
                af[i][1] = ldh2(&Ab[(mb + 8) * AST + ks + 2 * tg]);
                af[i][2] = ldh2(&Ab[mb * AST + ks + 2 * tg + 8]);
                af[i][3] = ldh2(&Ab[(mb + 8) * AST + ks + 2 * tg + 8]);
            }
            #pragma unroll
            for (int j = 0; j < NT; j++) {
                int nb = wc * WN + j * 8 + gid;
                bf1[j][0] = ldh2(&Bb1[nb * BST + ks + 2 * tg]);
                bf1[j][1] = ldh2(&Bb1[nb * BST + ks + 2 * tg + 8]);
                bf2[j][0] = ldh2(&Bb2[nb * BST + ks + 2 * tg]);
                bf2[j][1] = ldh2(&Bb2[nb * BST + ks + 2 * tg + 8]);
            }
            #pragma unroll
            for (int i = 0; i < MT; i++)
                #pragma unroll
                for (int j = 0; j < NT; j++) {
                    mma_f16(a1[i][j], af[i], bf1[j]);
                    mma_f16(a2[i][j], af[i], bf2[j]);
                }
        }
        __syncthreads();
        buf ^= 1;
    }

    #pragma unroll
    for (int i = 0; i < MT; i++) {
        #pragma unroll
        for (int j = 0; j < NT; j++) {
            #pragma unroll
            for (int e = 0; e < 4; e++) {
                int m = m0 + wr * WM + i * 16 + gid + ((e >= 2) ? 8 : 0);
                int n = n0 + wc * WN + j * 8 + 2 * tg + (e & 1);
                if (m < M && n < Nn) {
                    float g  = a2[i][j][e];
                    float ge = 0.5f * g * (1.f + erff(g * 0.70710678118654752f));
                    C[(size_t)m * ldc + n] = __float2half(a1[i][j][e] * ge);
                }
            }
        }
    }
}

// ---------------- launch ---------------------------------------------------------
extern "C" void kernel_launch(void* const* d_in, const int* in_sizes, int n_in,
                              void* d_out, int out_size) {
    const float* x      = (const float*)d_in[0];
    const float* g_ln   = (const float*)d_in[1];
    const float* Wq     = (const float*)d_in[2];
    const float* Wkv    = (const float*)d_in[3];
    const float* Wo     = (const float*)d_in[4];
    const float* cpb_w1 = (const float*)d_in[5];
    const float* cpb_b1 = (const float*)d_in[6];
    const float* cpb_w2 = (const float*)d_in[7];
    const float* cpb_b2 = (const float*)d_in[8];
    const float* cpb_w3 = (const float*)d_in[9];
    const float* cpb_b3 = (const float*)d_in[10];
    const float* ff_w_in  = (const float*)d_in[11];
    const float* ff_g     = (const float*)d_in[12];
    const float* ff_w_out = (const float*)d_in[13];
    float* out = (float*)d_out;

    float *bias, *y;
    __half *xn, *q, *k, *v, *o, *yh, *t;
    __half *cWqT, *cWkvT, *cWoT, *cWin, *cWoutP;
    cudaGetSymbolAddress((void**)&bias, g_bias);
    cudaGetSymbolAddress((void**)&xn,  g_xn);
    cudaGetSymbolAddress((void**)&q,   g_q);
    cudaGetSymbolAddress((void**)&k,   g_k);
    cudaGetSymbolAddress((void**)&v,   g_v);
    cudaGetSymbolAddress((void**)&o,   g_o);
    cudaGetSymbolAddress((void**)&y,   g_y);
    cudaGetSymbolAddress((void**)&yh,  g_yh);
    cudaGetSymbolAddress((void**)&t,   g_t);
    cudaGetSymbolAddress((void**)&cWqT,   g_cWqT);
    cudaGetSymbolAddress((void**)&cWkvT,  g_cWkvT);
    cudaGetSymbolAddress((void**)&cWoT,   g_cWoT);
    cudaGetSymbolAddress((void**)&cWin,   g_cWin);
    cudaGetSymbolAddress((void**)&cWoutP, g_cWoutP);

    auto T_QKV = hgemm<256,128,32,64,64,2>;
    auto T_OP  = hgemm<256,128,32,64,64,4>;
    auto T_FFO = hgemm<256,128,32,64,64,1>;
    auto T_GG  = hgemm_geglu<256,64,32,64,32>;

    const int SM_G  = (2*256*40 + 2*128*40) * 2;   // 61440 B
    const int SM_GG = (2*256*40 + 4*64*40)  * 2;   // 61440 B

    cudaFuncSetAttribute(T_QKV, cudaFuncAttributeMaxDynamicSharedMemorySize, SM_G);
    cudaFuncSetAttribute(T_OP,  cudaFuncAttributeMaxDynamicSharedMemorySize, SM_G);
    cudaFuncSetAttribute(T_FFO, cudaFuncAttributeMaxDynamicSharedMemorySize, SM_G);
    cudaFuncSetAttribute(T_GG,  cudaFuncAttributeMaxDynamicSharedMemorySize, SM_GG);
    cudaFuncSetAttribute(flash_kernel, cudaFuncAttributeMaxDynamicSharedMemorySize, FA_BYTES);

    // 0) weight preconversion: transpose+cvt for QKV/O weights; cvt for FF weights
    cvtT_kernel<<<dim3(32,32), dim3(32,8)>>>(Wq,  cWqT,  DIMV, INNERV);
    cvtT_kernel<<<dim3(64,32), dim3(32,8)>>>(Wkv, cWkvT, DIMV, 2*INNERV);
    cvtT_kernel<<<dim3(32,32), dim3(32,8)>>>(Wo,  cWoT,  INNERV, DIMV);
    cvtH_kernel<<<512, 256>>>((const float4*)ff_w_in, (__half2*)cWin, 2*FFH*DIMV/4);
    cvt_pad_kernel<<<dim3((LDT+255)/256, DIMV), 256>>>(ff_w_out, cWoutP);

    // 1) CPB bias table
    cpb_kernel<<<1023, 512>>>(cpb_w1, cpb_b1, cpb_w2, cpb_b2, cpb_w3, cpb_b3, bias);

    // 2) sequence-axis LayerNorm (half out)
    seqln_kernel<<<dim3(DIMV / 256, BATCH), 256>>>(x, g_ln, xn);

    // 3) Q/K/V projections, head-split half stores
    T_QKV<<<dim3(8,32),256,SM_G>>>(xn, cWqT,         nullptr, q, nullptr,
        MROWS, INNERV, DIMV, DIMV, DIMV, 0);
    T_QKV<<<dim3(8,32),256,SM_G>>>(xn, cWkvT,        nullptr, k, nullptr,
        MROWS, INNERV, DIMV, DIMV, DIMV, 0);
    T_QKV<<<dim3(8,32),256,SM_G>>>(xn, cWkvT + (size_t)INNERV*DIMV, nullptr, v, nullptr,
        MROWS, INNERV, DIMV, DIMV, DIMV, 0);

    // 4-6) fused flash attention
    flash_kernel<<<dim3(SEQ/128, BATCH*HEADS), 256, FA_BYTES>>>(q, k, v, bias, o);

    // 7) y = O @ Wo + x  (float y + half mirror)
    T_OP<<<dim3(8,32),256,SM_G>>>(o, cWoT, y, yh, x,
        MROWS, DIMV, INNERV, INNERV, INNERV, DIMV);

    // 8) FF-in + fused GEGLU (half out)
    T_GG<<<dim3((FFH+63)/64, 32),256,SM_GG>>>(yh, cWin, t,
        MROWS, FFH, DIMV, DIMV, LDT);

    // 9) channel LayerNorm (half, fp32 stats)
    chanln_kernel<<<MROWS, 256>>>(t, ff_g);

    // 10) out = t @ cWoutP^T + y  (fp32 residual add)
    T_FFO<<<dim3(8,32),256,SM_G>>>(t, cWoutP, out, nullptr, y,
        MROWS, DIMV, LDT, LDT, LDT, DIMV);
}

// round 11
// speedup vs baseline: 14.4632x; 1.0283x over previous
#include <cuda_runtime.h>
#include <cuda_fp16.h>
#include <math.h>
#include <stdint.h>

#define DIMV 1024
#define HEADS 16
#define DHEAD 64
#define BATCH 16
#define SEQ 512
#define INNERV 1024
#define CPBD 512
#define FFH 2730
#define LDT 2752            /* padded leading dim for t / cWout (halfs) */
#define MROWS (BATCH*SEQ)   /* 8192 */
#define EPSV 1e-5f

// ---------------- scratch (static device arrays; no allocations) ----------------
__device__ float  g_bias[HEADS * 1023];
__device__ __half g_xn[(size_t)MROWS * DIMV];
__device__ __half g_qkv[(size_t)3 * MROWS * INNERV];   // q | k | v  ([b,h,n,d] each)
__device__ __half g_o[(size_t)MROWS * INNERV];
__device__ float  g_y[(size_t)MROWS * DIMV];           // fp32 residual copy
__device__ __half g_yh[(size_t)MROWS * DIMV];          // half mirror
__device__ __half g_t[(size_t)MROWS * LDT];
// half-preconverted weights ([n][k] layouts)
__device__ __half g_cWqkvT[(size_t)3 * INNERV * DIMV];
__device__ __half g_cWoT[(size_t)DIMV * INNERV];
__device__ __half g_cWin[(size_t)2 * FFH * DIMV];
__device__ __half g_cWoutP[(size_t)DIMV * LDT];

// ---------------- helpers ---------------------------------------------------------
__device__ __forceinline__ void mma_f16(float d[4], const uint32_t a[4], const uint32_t b[2]) {
    asm volatile(
        "mma.sync.aligned.m16n8k16.row.col.f32.f16.f16.f32 "
        "{%0,%1,%2,%3},{%4,%5,%6,%7},{%8,%9},{%0,%1,%2,%3};\n"
        : "+f"(d[0]), "+f"(d[1]), "+f"(d[2]), "+f"(d[3])
        : "r"(a[0]), "r"(a[1]), "r"(a[2]), "r"(a[3]), "r"(b[0]), "r"(b[1]));
}
__device__ __forceinline__ void ldsm4(uint32_t r[4], uint32_t saddr) {
    asm volatile("ldmatrix.sync.aligned.m8n8.x4.shared.b16 {%0,%1,%2,%3}, [%4];"
        : "=r"(r[0]), "=r"(r[1]), "=r"(r[2]), "=r"(r[3]) : "r"(saddr));
}
__device__ __forceinline__ void cp16(uint32_t s, const void* g) {
    asm volatile("cp.async.cg.shared.global [%0], [%1], 16;\n" :: "r"(s), "l"(g));
}
__device__ __forceinline__ void cp_commit() { asm volatile("cp.async.commit_group;\n"); }
__device__ __forceinline__ void cp_wait1()  { asm volatile("cp.async.wait_group 1;\n"); }
__device__ __forceinline__ void cp_wait0()  { asm volatile("cp.async.wait_group 0;\n"); }
__device__ __forceinline__ float qmax2(float v) {
    v = fmaxf(v, __shfl_xor_sync(0xffffffffu, v, 1));
    v = fmaxf(v, __shfl_xor_sync(0xffffffffu, v, 2));
    return v;
}
__device__ __forceinline__ float qsum2(float v) {
    v += __shfl_xor_sync(0xffffffffu, v, 1);
    v += __shfl_xor_sync(0xffffffffu, v, 2);
    return v;
}
__device__ __forceinline__ uint32_t ldh2(const __half* p) { return *(const uint32_t*)p; }

// ---------------- weight preconvert kernels ---------------------------------------
// transpose + cvt: in [K][N] float -> out [N][K] half
__global__ void cvtT_kernel(const float* __restrict__ in, __half* __restrict__ out,
                            int K, int N) {
    __shared__ float tile[32][33];
    int n0 = blockIdx.x * 32, k0 = blockIdx.y * 32;
    int tx = threadIdx.x, ty0 = threadIdx.y;
    #pragma unroll
    for (int ty = ty0; ty < 32; ty += 8)
        tile[ty][tx] = in[(size_t)(k0 + ty) * N + n0 + tx];
    __syncthreads();
    #pragma unroll
    for (int ty = ty0; ty < 32; ty += 8)
        out[(size_t)(n0 + ty) * K + k0 + tx] = __float2half(tile[tx][ty]);
}
__global__ void cvtH_kernel(const float4* __restrict__ in, __half2* __restrict__ out, int n4) {
    int i = blockIdx.x * blockDim.x + threadIdx.x;
    int stride = gridDim.x * blockDim.x;
    for (; i < n4; i += stride) {
        float4 v = in[i];
        out[2 * i]     = __floats2half2_rn(v.x, v.y);
        out[2 * i + 1] = __floats2half2_rn(v.z, v.w);
    }
}
__global__ void cvt_pad_kernel(const float* __restrict__ in, __half* __restrict__ out) {
    int r = blockIdx.y;
    int c = blockIdx.x * 256 + threadIdx.x;
    if (c < LDT) out[(size_t)r * LDT + c] =
        (c < FFH) ? __float2half(in[(size_t)r * FFH + c]) : __half(0.f);
}

// ---------------- CPB: bias table over 1023 distinct relative positions ----------
__global__ void cpb_kernel(const float* __restrict__ w1, const float* __restrict__ b1,
                           const float* __restrict__ w2, const float* __restrict__ b2,
                           const float* __restrict__ w3, const float* __restrict__ b3,
                           float* __restrict__ table) {
    int ridx = blockIdx.x;
    float rf = (float)(ridx - 511);
    float sgn = (rf > 0.f) ? 1.f : ((rf < 0.f) ? -1.f : 0.f);
    float rel = sgn * logf(fabsf(rf) + 1.f);

    __shared__ float h1[CPBD];
    __shared__ float h2[CPBD];
    int t = threadIdx.x;
    {
        float z = rel * w1[t] + b1[t];
        h1[t] = z / (1.f + expf(-z));
    }
    __syncthreads();
    {
        float acc = b2[t];
        #pragma unroll 4
        for (int j = 0; j < CPBD; j++) acc += h1[j] * w2[j * CPBD + t];
        h2[t] = acc / (1.f + expf(-acc));
    }
    __syncthreads();
    int warp = t >> 5, lane = t & 31;
    float acc = 0.f;
    for (int i = lane; i < CPBD; i += 32) acc += h2[i] * w3[i * HEADS + warp];
    #pragma unroll
    for (int off = 16; off; off >>= 1) acc += __shfl_down_sync(0xffffffffu, acc, off);
    if (lane == 0) table[warp * 1023 + ridx] = acc + b3[warp];
}

// ---------------- sequence-axis LayerNorm (fp32 stats, half out) ------------------
__global__ void seqln_kernel(const float* __restrict__ x, const float* __restrict__ g,
                             __half* __restrict__ xn) {
    int d = blockIdx.x * blockDim.x + threadIdx.x;
    int b = blockIdx.y;
    const float* xb = x + (size_t)b * SEQ * DIMV;
    float s = 0.f, ss = 0.f;
    for (int n = 0; n < SEQ; n++) { float v = xb[n * DIMV + d]; s += v; ss += v * v; }
    float mean = s * (1.f / SEQ);
    float var  = ss * (1.f / SEQ) - mean * mean;
    float inv  = rsqrtf(fmaxf(var, EPSV)) * g[d];
    __half* ob = xn + (size_t)b * SEQ * DIMV;
    for (int n = 0; n < SEQ; n++) ob[n * DIMV + d] = __float2half((xb[n * DIMV + d] - mean) * inv);
}

// ---------------- fused flash attention (fp16 mma, fp32 online softmax) -----------
#define FA_ST  72
#define FA_QS  0
#define FA_KS  (FA_QS + 128*FA_ST)
#define FA_VS  (FA_KS + 2*64*FA_ST)
#define FA_PS  (FA_VS + 2*64*FA_ST)
#define FA_HEND (FA_PS + 8*16*FA_ST)
#define FA_BYTES (FA_HEND*2 + 1024*4)

__global__ __launch_bounds__(256, 1)
void flash_kernel(const __half* __restrict__ q, const __half* __restrict__ k,
                  const __half* __restrict__ v, const float* __restrict__ table,
                  __half* __restrict__ o) {
    extern __shared__ char smraw[];
    __half* smh = (__half*)smraw;
    float*  Bi  = (float*)(smraw + FA_HEND * 2);

    const int qt = blockIdx.x;
    const int z  = blockIdx.y;
    const int h  = z & (HEADS - 1);
    const int b  = z >> 4;
    const int qbase = qt * 128;
    const int tid = threadIdx.x;
    const int w = tid >> 5, lane = tid & 31;
    const int gid = lane >> 2, tg = lane & 3;

    const __half* qz = q + (size_t)z * SEQ * DHEAD;
    const __half* kz = k + (size_t)z * SEQ * DHEAD;
    const __half* vz = v + (size_t)z * SEQ * DHEAD;

    const uint32_t sbase = (uint32_t)__cvta_generic_to_shared(smh);

    #pragma unroll
    for (int c = tid; c < 128 * 8; c += 256) {
        int m = c >> 3, kc = c & 7;
        cp16(sbase + (uint32_t)((FA_QS + m * FA_ST + kc * 8) * 2),
             qz + (qbase + m) * DHEAD + kc * 8);
    }
    for (int i = tid; i < 1023; i += 256) Bi[i] = table[h * 1023 + i];

    auto stage_kv = [&](int buf, int jt) {
        int kb = jt * 64;
        #pragma unroll
        for (int c = tid; c < 64 * 8; c += 256) {
            int r = c >> 3, kc = c & 7;
            cp16(sbase + (uint32_t)((FA_KS + buf * 64 * FA_ST + r * FA_ST + kc * 8) * 2),
                 kz + (kb + r) * DHEAD + kc * 8);
            cp16(sbase + (uint32_t)((FA_VS + buf * 64 * FA_ST + r * FA_ST + kc * 8) * 2),
                 vz + (kb + r) * DHEAD + kc * 8);
        }
    };

    stage_kv(0, 0);
    cp_commit();

    float m_row[2] = {-1e30f, -1e30f};
    float l_row[2] = {0.f, 0.f};
    float oacc[8][4];
    #pragma unroll
    for (int j = 0; j < 8; j++)
        #pragma unroll
        for (int e = 0; e < 4; e++) oacc[j][e] = 0.f;

    const __half* Qs = smh + FA_QS;
    __half* Ps = smh + FA_PS + w * 16 * FA_ST;

    int buf = 0;
    for (int jt = 0; jt < 8; jt++) {
        if (jt + 1 < 8) { stage_kv(buf ^ 1, jt + 1); cp_commit(); cp_wait1(); }
        else cp_wait0();
        __syncthreads();

        const __half* Ks = smh + FA_KS + buf * 64 * FA_ST;
        const __half* Vs = smh + FA_VS + buf * 64 * FA_ST;
        const int kb = jt * 64;

        float s[8][4];
        #pragma unroll
        for (int j = 0; j < 8; j++)
            #pragma unroll
            for (int e = 0; e < 4; e++) s[j][e] = 0.f;
        #pragma unroll
        for (int ks = 0; ks < 64; ks += 16) {
            uint32_t a[4];
            int mb = w * 16 + gid;
            a[0] = ldh2(&Qs[mb * FA_ST + ks + 2 * tg]);
            a[1] = ldh2(&Qs[(mb + 8) * FA_ST + ks + 2 * tg]);
            a[2] = ldh2(&Qs[mb * FA_ST + ks + 2 * tg + 8]);
            a[3] = ldh2(&Qs[(mb + 8) * FA_ST + ks + 2 * tg + 8]);
            #pragma unroll
            for (int j = 0; j < 8; j++) {
                uint32_t bfr[2];
                int nb = j * 8 + gid;
                bfr[0] = ldh2(&Ks[nb * FA_ST + ks + 2 * tg]);
                bfr[1] = ldh2(&Ks[nb * FA_ST + ks + 2 * tg + 8]);
                mma_f16(s[j], a, bfr);
            }
        }

        int qi0 = qbase + w * 16 + gid;
        float mx0 = -1e30f, mx1 = -1e30f;
        #pragma unroll
        for (int j = 0; j < 8; j++) {
            int kj = kb + j * 8 + 2 * tg;
            s[j][0] = s[j][0] * 0.125f + Bi[qi0 - kj + 511];
            s[j][1] = s[j][1] * 0.125f + Bi[qi0 - kj + 510];
            s[j][2] = s[j][2] * 0.125f + Bi[qi0 + 8 - kj + 511];
            s[j][3] = s[j][3] * 0.125f + Bi[qi0 + 8 - kj + 510];
            mx0 = fmaxf(mx0, fmaxf(s[j][0], s[j][1]));
            mx1 = fmaxf(mx1, fmaxf(s[j][2], s[j][3]));
        }
        mx0 = qmax2(mx0); mx1 = qmax2(mx1);
        float mn0 = fmaxf(m_row[0], mx0), mn1 = fmaxf(m_row[1], mx1);
        float sc0 = __expf(m_row[0] - mn0), sc1 = __expf(m_row[1] - mn1);
        float rs0 = 0.f, rs1 = 0.f;
        #pragma unroll
        for (int j = 0; j < 8; j++) {
            s[j][0] = __expf(s[j][0] - mn0);
            s[j][1] = __expf(s[j][1] - mn0);
            s[j][2] = __expf(s[j][2] - mn1);
            s[j][3] = __expf(s[j][3] - mn1);
            rs0 += s[j][0] + s[j][1];
            rs1 += s[j][2] + s[j][3];
        }
        rs0 = qsum2(rs0); rs1 = qsum2(rs1);
        l_row[0] = l_row[0] * sc0 + rs0;
        l_row[1] = l_row[1] * sc1 + rs1;
        m_row[0] = mn0; m_row[1] = mn1;
        #pragma unroll
        for (int j = 0; j < 8; j++) {
            oacc[j][0] *= sc0; oacc[j][1] *= sc0;
            oacc[j][2] *= sc1; oacc[j][3] *= sc1;
        }

        #pragma unroll
        for (int j = 0; j < 8; j++) {
            *(__half2*)&Ps[gid * FA_ST + j * 8 + 2 * tg]       = __floats2half2_rn(s[j][0], s[j][1]);
            *(__half2*)&Ps[(gid + 8) * FA_ST + j * 8 + 2 * tg] = __floats2half2_rn(s[j][2], s[j][3]);
        }
        __syncwarp();

        #pragma unroll
        for (int ks = 0; ks < 64; ks += 16) {
            uint32_t a[4];
            a[0] = ldh2(&Ps[gid * FA_ST + ks + 2 * tg]);
            a[1] = ldh2(&Ps[(gid + 8) * FA_ST + ks + 2 * tg]);
            a[2] = ldh2(&Ps[gid * FA_ST + ks + 2 * tg + 8]);
            a[3] = ldh2(&Ps[(gid + 8) * FA_ST + ks + 2 * tg + 8]);
            #pragma unroll
            for (int j = 0; j < 8; j++) {
                int nb = j * 8 + gid;
                __half2 b0, b1;
                b0.x = Vs[(ks + 2 * tg) * FA_ST + nb];
                b0.y = Vs[(ks + 2 * tg + 1) * FA_ST + nb];
                b1.x = Vs[(ks + 2 * tg + 8) * FA_ST + nb];
                b1.y = Vs[(ks + 2 * tg + 9) * FA_ST + nb];
                uint32_t bfr[2] = { *(uint32_t*)&b0, *(uint32_t*)&b1 };
                mma_f16(oacc[j], a, bfr);
            }
        }
        __syncwarp();
        __syncthreads();
        buf ^= 1;
    }

    float inv0 = 1.f / l_row[0], inv1 = 1.f / l_row[1];
    int qi = qbase + w * 16 + gid;
    #pragma unroll
    for (int j = 0; j < 8; j++) {
        int d = j * 8 + 2 * tg;
        size_t r0 = ((size_t)(b * SEQ + qi) * INNERV) + h * DHEAD + d;
        size_t r1 = ((size_t)(b * SEQ + qi + 8) * INNERV) + h * DHEAD + d;
        *(__half2*)&o[r0] = __floats2half2_rn(oacc[j][0] * inv0, oacc[j][1] * inv0);
        *(__half2*)&o[r1] = __floats2half2_rn(oacc[j][2] * inv1, oacc[j][3] * inv1);
    }
}

// ---------------- channel LayerNorm over FFH per token (half in/out, fp32 stats) --
__global__ void chanln_kernel(__half* __restrict__ tb, const float* __restrict__ gg) {
    int m = blockIdx.x;
    __half* row = tb + (size_t)m * LDT;
    int t = threadIdx.x;
    float s = 0.f, ss = 0.f;
    for (int j = t; j < FFH; j += 256) { float v = __half2float(row[j]); s += v; ss += v * v; }
    __shared__ float r1[256], r2[256];
    r1[t] = s; r2[t] = ss; __syncthreads();
    for (int k = 128; k; k >>= 1) { if (t < k) { r1[t] += r1[t + k]; r2[t] += r2[t + k]; } __syncthreads(); }
    float mean = r1[0] * (1.f / FFH);
    float var  = r2[0] * (1.f / FFH) - mean * mean;
    float inv  = rsqrtf(fmaxf(var, EPSV));
    for (int j = t; j < FFH; j += 256)
        row[j] = __float2half((__half2float(row[j]) - mean) * inv * gg[j]);
    if (t < LDT - FFH) row[FFH + t] = __half(0.f);
}

// ---------------- fp16 tensor-core GEMM, NT, ldmatrix, 3-stage cp.async -----------
// A [M][K] half row-major; B [N][K] half row-major. fp32 accum.
// EPI: 1 = Cf = v + R (float); 2 = merged-qkv head-split half store (Ch = qkv base);
//      4 = y float + yh half
template<int BM, int BN, int BK, int WM, int WN, int EPI>
__global__ __launch_bounds__(256, 1)
void hgemm(const __half* __restrict__ A, const __half* __restrict__ B,
           float* __restrict__ Cf, __half* __restrict__ Ch, const float* __restrict__ R,
           int M, int Nn, int K, int lda, int ldb, int ldc) {
    constexpr int WARPS_N = BN / WN;
    constexpr int MT = WM / 16, NT = WN / 8;
    constexpr int AST = BK + 8;
    constexpr int BST = BK + 8;
    constexpr int ABUF = BM * AST;
    constexpr int BBUF = BN * BST;

    extern __shared__ char smraw[];
    __half* Asm = (__half*)smraw;
    __half* Bsm = Asm + 3 * ABUF;

    const int m0 = blockIdx.y * BM;
    const int n0 = blockIdx.x * BN;
    const int tid = threadIdx.x;
    const int warp = tid >> 5, lane = tid & 31;
    const int wr = warp / WARPS_N, wc = warp % WARPS_N;
    const int gid = lane >> 2, tg = lane & 3;

    const uint32_t sAb = (uint32_t)__cvta_generic_to_shared(Asm);
    const uint32_t sBb = (uint32_t)__cvta_generic_to_shared(Bsm);

    // ldmatrix lane geometry
    const int aRow  = wr * WM + (lane & 15);
    const int aKoff = (lane & 16) >> 1;                      // 0 or 8
    const int bRow  = wc * WN + ((lane >> 4) & 1) * 8 + (lane & 7);
    const int bKoff = ((lane >> 3) & 1) * 8;

    float acc[MT][NT][4];
    #pragma unroll
    for (int i = 0; i < MT; i++)
        #pragma unroll
        for (int j = 0; j < NT; j++)
            #pragma unroll
            for (int e = 0; e < 4; e++) acc[i][j][e] = 0.f;

    const int NIT = K / BK;

    auto stage = [&](int b, int k0) {
        constexpr int ACH = BK / 8;
        #pragma unroll
        for (int c = tid; c < BM * ACH; c += 256) {
            int m = c / ACH, kc = c % ACH;
            cp16(sAb + (uint32_t)((b * ABUF + m * AST + kc * 8) * 2),
                 A + (size_t)(m0 + m) * lda + k0 + kc * 8);
        }
        constexpr int BCH = BK / 8;
        #pragma unroll
        for (int c = tid; c < BN * BCH; c += 256) {
            int n = c / BCH, kc = c % BCH;
            cp16(sBb + (uint32_t)((b * BBUF + n * BST + kc * 8) * 2),
                 B + (size_t)(n0 + n) * ldb + k0 + kc * 8);
        }
    };

    stage(0, 0);      cp_commit();
    stage(1, BK);     cp_commit();
    for (int it = 0; it < NIT; it++) {
        if (it + 2 < NIT) cp_wait1(); else cp_wait0();
        __syncthreads();
        if (it + 2 < NIT) { stage((it + 2) % 3, (it + 2) * BK); cp_commit(); }

        const int buf = it % 3;
        const uint32_t aB = sAb + (uint32_t)((buf * ABUF + aRow * AST + aKoff) * 2);
        const uint32_t bB = sBb + (uint32_t)((buf * BBUF + bRow * BST + bKoff) * 2);
        #pragma unroll
        for (int ks = 0; ks < BK; ks += 16) {
            uint32_t af[MT][4];
            uint32_t bf[NT][4];   // pairs packed: [2jj..2jj+1]
            #pragma unroll
            for (int i = 0; i < MT; i++)
                ldsm4(af[i], aB + (uint32_t)((i * 16 * AST + ks) * 2));
            #pragma unroll
            for (int jj = 0; jj < NT / 2; jj++)
                ldsm4(bf[jj], bB + (uint32_t)((jj * 16 * BST + ks) * 2));
            #pragma unroll
            for (int i = 0; i < MT; i++)
                #pragma unroll
                for (int jj = 0; jj < NT / 2; jj++) {
                    mma_f16(acc[i][2 * jj],     af[i], &bf[jj][0]);
                    mma_f16(acc[i][2 * jj + 1], af[i], &bf[jj][2]);
                }
        }
    }

    #pragma unroll
    for (int i = 0; i < MT; i++) {
        #pragma unroll
        for (int j = 0; j < NT; j++) {
            #pragma unroll
            for (int e = 0; e < 4; e++) {
                int m = m0 + wr * WM + i * 16 + gid + ((e >= 2) ? 8 : 0);
                int n = n0 + wc * WN + j * 8 + 2 * tg + (e & 1);
                if (m < M && n < Nn) {
                    float v = acc[i][j][e];
                    if (EPI == 1) {
                        Cf[(size_t)m * ldc + n] = v + R[(size_t)m * ldc + n];
                    } else if (EPI == 2) {
                        int which = n >> 10;            // 0=q 1=k 2=v
                        int nn2 = n & 1023;
                        int h = nn2 >> 6, d = nn2 & (DHEAD - 1);
                        int b = m >> 9, sq = m & (SEQ - 1);
                        Ch[(size_t)which * MROWS * INNERV +
                           ((((size_t)b * HEADS + h) * SEQ + sq) << 6) + d] = __float2half(v);
                    } else { // EPI == 4
                        float r = v + R[(size_t)m * ldc + n];
                        Cf[(size_t)m * ldc + n] = r;
                        Ch[(size_t)m * ldc + n] = __float2half(r);
                    }
                }
            }
        }
    }
}

// ---------------- fp16 GEGLU GEMM (two NT B tiles), ldmatrix, 3-stage -------------
template<int BM, int BN, int BK, int WM, int WN>
__global__ __launch_bounds__(256, 1)
void hgemm_geglu(const __half* __restrict__ A, const __half* __restrict__ B,
                 __half* __restrict__ C, int M, int Nn, int K, int ldb, int ldc) {
    constexpr int WARPS_N = BN / WN;
    constexpr int MT = WM / 16, NT = WN / 8;
    constexpr int AST = BK + 8;
    constexpr int BST = BK + 8;
    constexpr int ABUF = BM * AST;
    constexpr int BBUF = BN * BST;

    extern __shared__ char smraw[];
    __half* Asm = (__half*)smraw;
    __half* B1m = Asm + 3 * ABUF;
    __half* B2m = B1m + 3 * BBUF;

    const int m0 = blockIdx.y * BM;
    const int n0 = blockIdx.x * BN;
    const int tid = threadIdx.x;
    const int warp = tid >> 5, lane = tid & 31;
    const int wr = warp / WARPS_N, wc = warp % WARPS_N;
    const int gid = lane >> 2, tg = lane & 3;

    const uint32_t sAb = (uint32_t)__cvta_generic_to_shared(Asm);
    const uint32_t sB1 = (uint32_t)__cvta_generic_to_shared(B1m);
    const uint32_t sB2 = (uint32_t)__cvta_generic_to_shared(B2m);

    const int aRow  = wr * WM + (lane & 15);
    const int aKoff = (lane & 16) >> 1;
    const int bRow  = wc * WN + ((lane >> 4) & 1) * 8 + (lane & 7);
    const int bKoff = ((lane >> 3) & 1) * 8;

    float a1[MT][NT][4], a2[MT][NT][4];
    #pragma unroll
    for (int i = 0; i < MT; i++)
        #pragma unroll
        for (int j = 0; j < NT; j++)
            #pragma unroll
            for (int e = 0; e < 4; e++) { a1[i][j][e] = 0.f; a2[i][j][e] = 0.f; }

    const int NIT = K / BK;

    auto stage = [&](int b, int k0) {
        constexpr int ACH = BK / 8;
        #pragma unroll
        for (int c = tid; c < BM * ACH; c += 256) {
            int m = c / ACH, kc = c % ACH;
            cp16(sAb + (uint32_t)((b * ABUF + m * AST + kc * 8) * 2),
                 A + (size_t)(m0 + m) * K + k0 + kc * 8);
        }
        constexpr int BCH = BK / 8;
        #pragma unroll
        for (int c = tid; c < BN * BCH; c += 256) {
            int n = c / BCH, kc = c % BCH;
            int gn = n0 + n; if (gn > FFH - 1) gn = FFH - 1;
            uint32_t off = (uint32_t)((b * BBUF + n * BST + kc * 8) * 2);
            cp16(sB1 + off, B + (size_t)gn * ldb + k0 + kc * 8);
            cp16(sB2 + off, B + (size_t)(gn + FFH) * ldb + k0 + kc * 8);
        }
    };

    stage(0, 0);   cp_commit();
    stage(1, BK);  cp_commit();
    for (int it = 0; it < NIT; it++) {
        if (it + 2 < NIT) cp_wait1(); else cp_wait0();
        __syncthreads();
        if (it + 2 < NIT) { stage((it + 2) % 3, (it + 2) * BK); cp_commit(); }

        const int buf = it % 3;
        const uint32_t aB  = sAb + (uint32_t)((buf * ABUF + aRow * AST + aKoff) * 2);
        const uint32_t bB1 = sB1 + (uint32_t)((buf * BBUF + bRow * BST + bKoff) * 2);
        const uint32_t bB2 = sB2 + (uint32_t)((buf * BBUF + bRow * BST + bKoff) * 2);
        #pragma unroll
        for (int ks = 0; ks < BK; ks += 16) {
            uint32_t af[MT][4];
            uint32_t bf1[NT / 2][4], bf2[NT / 2][4];
            #pragma unroll
            for (int i = 0; i < MT; i++)
                ldsm4(af[i], aB + (uint32_t)((i * 16 * AST + ks) * 2));
            #pragma unroll
            for (int jj = 0; jj < NT / 2; jj++) {
                ldsm4(bf1[jj], bB1 + (uint32_t)((jj * 16 * BST + ks) * 2));
                ldsm4(bf2[jj], bB2 + (uint32_t)((jj * 16 * BST + ks) * 2));
            }
            #pragma unroll
            for (int i = 0; i < MT; i++)
                #pragma unroll
                for (int jj = 0; jj < NT / 2; jj++) {
                    mma_f16(a1[i][2 * jj],     af[i], &bf1[jj][0]);
                    mma_f16(a1[i][2 * jj + 1], af[i], &bf1[jj][2]);
                    mma_f16(a2[i][2 * jj],     af[i], &bf2[jj][0]);
                    mma_f16(a2[i][2 * jj + 1], af[i], &bf2[jj][2]);
                }
        }
    }

    #pragma unroll
    for (int i = 0; i < MT; i++) {
        #pragma unroll
        for (int j = 0; j < NT; j++) {
            #pragma unroll
            for (int e = 0; e < 4; e++) {
                int m = m0 + wr * WM + i * 16 + gid + ((e >= 2) ? 8 : 0);
                int n = n0 + wc * WN + j * 8 + 2 * tg + (e & 1);
                if (m < M && n < Nn) {
                    float g  = a2[i][j][e];
                    float ge = 0.5f * g * (1.f + erff(g * 0.70710678118654752f));
                    C[(size_t)m * ldc + n] = __float2half(a1[i][j][e] * ge);
                }
            }
        }
    }
}

// ---------------- launch ---------------------------------------------------------
extern "C" void kernel_launch(void* const* d_in, const int* in_sizes, int n_in,
                              void* d_out, int out_size) {
    const float* x      = (const float*)d_in[0];
    const float* g_ln   = (const float*)d_in[1];
    const float* Wq     = (const float*)d_in[2];
    const float* Wkv    = (const float*)d_in[3];
    const float* Wo     = (const float*)d_in[4];
    const float* cpb_w1 = (const float*)d_in[5];
    const float* cpb_b1 = (const float*)d_in[6];
    const float* cpb_w2 = (const float*)d_in[7];
    const float* cpb_b2 = (const float*)d_in[8];
    const float* cpb_w3 = (const float*)d_in[9];
    const float* cpb_b3 = (const float*)d_in[10];
    const float* ff_w_in  = (const float*)d_in[11];
    const float* ff_g     = (const float*)d_in[12];
    const float* ff_w_out = (const float*)d_in[13];
    float* out = (float*)d_out;

    float *bias, *y;
    __half *xn, *qkv, *o, *yh, *t;
    __half *cWqkvT, *cWoT, *cWin, *cWoutP;
    cudaGetSymbolAddress((void**)&bias, g_bias);
    cudaGetSymbolAddress((void**)&xn,  g_xn);
    cudaGetSymbolAddress((void**)&qkv, g_qkv);
    cudaGetSymbolAddress((void**)&o,   g_o);
    cudaGetSymbolAddress((void**)&y,   g_y);
    cudaGetSymbolAddress((void**)&yh,  g_yh);
    cudaGetSymbolAddress((void**)&t,   g_t);
    cudaGetSymbolAddress((void**)&cWqkvT, g_cWqkvT);
    cudaGetSymbolAddress((void**)&cWoT,   g_cWoT);
    cudaGetSymbolAddress((void**)&cWin,   g_cWin);
    cudaGetSymbolAddress((void**)&cWoutP, g_cWoutP);

    auto T_QKV = hgemm<256,128,32,64,64,2>;
    auto T_OP  = hgemm<256,128,32,64,64,4>;
    auto T_FFO = hgemm<256,128,32,64,64,1>;
    auto T_GG  = hgemm_geglu<256,64,32,64,32>;

    const int SM_G  = (3*256*40 + 3*128*40) * 2;     // 92160 B
    const int SM_GG = (3*256*40 + 6*64*40)  * 2;     // 92160 B

    cudaFuncSetAttribute(T_QKV, cudaFuncAttributeMaxDynamicSharedMemorySize, SM_G);
    cudaFuncSetAttribute(T_OP,  cudaFuncAttributeMaxDynamicSharedMemorySize, SM_G);
    cudaFuncSetAttribute(T_FFO, cudaFuncAttributeMaxDynamicSharedMemorySize, SM_G);
    cudaFuncSetAttribute(T_GG,  cudaFuncAttributeMaxDynamicSharedMemorySize, SM_GG);
    cudaFuncSetAttribute(flash_kernel, cudaFuncAttributeMaxDynamicSharedMemorySize, FA_BYTES);

    // 0) weight preconversion: Wq/Wkv transposed into one combined [3072][1024] buffer
    cvtT_kernel<<<dim3(32,32), dim3(32,8)>>>(Wq,  cWqkvT,                      DIMV, INNERV);
    cvtT_kernel<<<dim3(64,32), dim3(32,8)>>>(Wkv, cWqkvT + (size_t)INNERV*DIMV, DIMV, 2*INNERV);
    cvtT_kernel<<<dim3(32,32), dim3(32,8)>>>(Wo,  cWoT,  INNERV, DIMV);
    cvtH_kernel<<<512, 256>>>((const float4*)ff_w_in, (__half2*)cWin, 2*FFH*DIMV/4);
    cvt_pad_kernel<<<dim3((LDT+255)/256, DIMV), 256>>>(ff_w_out, cWoutP);

    // 1) CPB bias table
    cpb_kernel<<<1023, 512>>>(cpb_w1, cpb_b1, cpb_w2, cpb_b2, cpb_w3, cpb_b3, bias);

    // 2) sequence-axis LayerNorm (half out)
    seqln_kernel<<<dim3(DIMV / 256, BATCH), 256>>>(x, g_ln, xn);

    // 3) merged Q/K/V projection (N=3072), head-split half stores into g_qkv
    T_QKV<<<dim3(24,32),256,SM_G>>>(xn, cWqkvT, nullptr, qkv, nullptr,
        MROWS, 3*INNERV, DIMV, DIMV, DIMV, 0);

    // 4-6) fused flash attention
    flash_kernel<<<dim3(SEQ/128, BATCH*HEADS), 256, FA_BYTES>>>(
        qkv, qkv + (size_t)MROWS*INNERV, qkv + (size_t)2*MROWS*INNERV, bias, o);

    // 7) y = O @ Wo + x  (float y + half mirror)
    T_OP<<<dim3(8,32),256,SM_G>>>(o, cWoT, y, yh, x,
        MROWS, DIMV, INNERV, INNERV, INNERV, DIMV);

    // 8) FF-in + fused GEGLU (half out)
    T_GG<<<dim3((FFH+63)/64, 32),256,SM_GG>>>(yh, cWin, t,
        MROWS, FFH, DIMV, DIMV, LDT);

    // 9) channel LayerNorm (half, fp32 stats)
    chanln_kernel<<<MROWS, 256>>>(t, ff_g);

    // 10) out = t @ cWoutP^T + y  (fp32 residual add)
    T_FFO<<<dim3(8,32),256,SM_G>>>(t, cWoutP, out, nullptr, y,
        MROWS, DIMV, LDT, LDT, LDT, DIMV);
}

// round 12
// speedup vs baseline: 15.1169x; 1.0452x over previous
#include <cuda_runtime.h>
#include <cuda_fp16.h>
#include <math.h>
#include <stdint.h>

#define DIMV 1024
#define HEADS 16
#define DHEAD 64
#define BATCH 16
#define SEQ 512
#define INNERV 1024
#define CPBD 512
#define FFH 2730
#define LDT 2752            /* padded leading dim for t / cWout (halfs) */
#define MROWS (BATCH*SEQ)   /* 8192 */
#define EPSV 1e-5f

// ---------------- scratch (static device arrays; no allocations) ----------------
__device__ float  g_bias[HEADS * 1023];
__device__ __half g_xn[(size_t)MROWS * DIMV];
__device__ __half g_qkv[(size_t)3 * MROWS * INNERV];   // q | k | v  ([b,h,n,d] each)
__device__ __half g_o[(size_t)MROWS * INNERV];
__device__ float  g_y[(size_t)MROWS * DIMV];           // fp32 residual copy
__device__ __half g_yh[(size_t)MROWS * DIMV];          // half mirror
__device__ __half g_t[(size_t)MROWS * LDT];
// half-preconverted weights ([n][k] layouts)
__device__ __half g_cWqkvT[(size_t)3 * INNERV * DIMV];
__device__ __half g_cWoT[(size_t)DIMV * INNERV];
__device__ __half g_cWin[(size_t)2 * FFH * DIMV];
__device__ __half g_cWoutP[(size_t)DIMV * LDT];

// ---------------- helpers ---------------------------------------------------------
__device__ __forceinline__ void mma_f16(float d[4], const uint32_t a[4], const uint32_t b[2]) {
    asm volatile(
        "mma.sync.aligned.m16n8k16.row.col.f32.f16.f16.f32 "
        "{%0,%1,%2,%3},{%4,%5,%6,%7},{%8,%9},{%0,%1,%2,%3};\n"
        : "+f"(d[0]), "+f"(d[1]), "+f"(d[2]), "+f"(d[3])
        : "r"(a[0]), "r"(a[1]), "r"(a[2]), "r"(a[3]), "r"(b[0]), "r"(b[1]));
}
__device__ __forceinline__ void ldsm4(uint32_t r[4], uint32_t saddr) {
    asm volatile("ldmatrix.sync.aligned.m8n8.x4.shared.b16 {%0,%1,%2,%3}, [%4];"
        : "=r"(r[0]), "=r"(r[1]), "=r"(r[2]), "=r"(r[3]) : "r"(saddr));
}
__device__ __forceinline__ void ldsm4t(uint32_t r[4], uint32_t saddr) {
    asm volatile("ldmatrix.sync.aligned.m8n8.x4.trans.shared.b16 {%0,%1,%2,%3}, [%4];"
        : "=r"(r[0]), "=r"(r[1]), "=r"(r[2]), "=r"(r[3]) : "r"(saddr));
}
__device__ __forceinline__ void cp16(uint32_t s, const void* g) {
    asm volatile("cp.async.cg.shared.global [%0], [%1], 16;\n" :: "r"(s), "l"(g));
}
__device__ __forceinline__ void cp_commit() { asm volatile("cp.async.commit_group;\n"); }
__device__ __forceinline__ void cp_wait1()  { asm volatile("cp.async.wait_group 1;\n"); }
__device__ __forceinline__ void cp_wait0()  { asm volatile("cp.async.wait_group 0;\n"); }
__device__ __forceinline__ float qmax2(float v) {
    v = fmaxf(v, __shfl_xor_sync(0xffffffffu, v, 1));
    v = fmaxf(v, __shfl_xor_sync(0xffffffffu, v, 2));
    return v;
}
__device__ __forceinline__ float qsum2(float v) {
    v += __shfl_xor_sync(0xffffffffu, v, 1);
    v += __shfl_xor_sync(0xffffffffu, v, 2);
    return v;
}

// ---------------- weight preconvert kernels ---------------------------------------
__global__ void cvtT_kernel(const float* __restrict__ in, __half* __restrict__ out,
                            int K, int N) {
    __shared__ float tile[32][33];
    int n0 = blockIdx.x * 32, k0 = blockIdx.y * 32;
    int tx = threadIdx.x, ty0 = threadIdx.y;
    #pragma unroll
    for (int ty = ty0; ty < 32; ty += 8)
        tile[ty][tx] = in[(size_t)(k0 + ty) * N + n0 + tx];
    __syncthreads();
    #pragma unroll
    for (int ty = ty0; ty < 32; ty += 8)
        out[(size_t)(n0 + ty) * K + k0 + tx] = __float2half(tile[tx][ty]);
}
__global__ void cvtH_kernel(const float4* __restrict__ in, __half2* __restrict__ out, int n4) {
    int i = blockIdx.x * blockDim.x + threadIdx.x;
    int stride = gridDim.x * blockDim.x;
    for (; i < n4; i += stride) {
        float4 v = in[i];
        out[2 * i]     = __floats2half2_rn(v.x, v.y);
        out[2 * i + 1] = __floats2half2_rn(v.z, v.w);
    }
}
__global__ void cvt_pad_kernel(const float* __restrict__ in, __half* __restrict__ out) {
    int r = blockIdx.y;
    int c = blockIdx.x * 256 + threadIdx.x;
    if (c < LDT) out[(size_t)r * LDT + c] =
        (c < FFH) ? __float2half(in[(size_t)r * FFH + c]) : __half(0.f);
}

// ---------------- CPB: 8 rel-positions per block (amortized w2 traffic) ----------
#define CPB_R 8
__global__ void cpb_kernel(const float* __restrict__ w1, const float* __restrict__ b1,
                           const float* __restrict__ w2, const float* __restrict__ b2,
                           const float* __restrict__ w3, const float* __restrict__ b3,
                           float* __restrict__ table) {
    __shared__ float h1[CPB_R][CPBD];
    __shared__ float h2[CPB_R][CPBD];
    int t = threadIdx.x;                   // 512
    int r0 = blockIdx.x * CPB_R;           // grid 128 -> rows 0..1023 (1023 guarded)
    #pragma unroll
    for (int r = 0; r < CPB_R; r++) {
        int ridx = r0 + r;
        float rf = (float)(ridx - 511);
        float sgn = (rf > 0.f) ? 1.f : ((rf < 0.f) ? -1.f : 0.f);
        float rel = sgn * logf(fabsf(rf) + 1.f);
        float z = rel * w1[t] + b1[t];
        h1[r][t] = z / (1.f + expf(-z));
    }
    __syncthreads();
    float acc[CPB_R];
    #pragma unroll
    for (int r = 0; r < CPB_R; r++) acc[r] = b2[t];
    for (int j = 0; j < CPBD; j++) {
        float wv = w2[j * CPBD + t];
        #pragma unroll
        for (int r = 0; r < CPB_R; r++) acc[r] += h1[r][j] * wv;
    }
    #pragma unroll
    for (int r = 0; r < CPB_R; r++) {
        float z = acc[r];
        h2[r][t] = z / (1.f + expf(-z));
    }
    __syncthreads();
    int w = t >> 5, lane = t & 31;         // warp w -> head w (16 warps = 16 heads)
    #pragma unroll
    for (int r = 0; r < CPB_R; r++) {
        float a2 = 0.f;
        #pragma unroll 4
        for (int i = lane; i < CPBD; i += 32) a2 += h2[r][i] * w3[i * HEADS + w];
        #pragma unroll
        for (int off = 16; off; off >>= 1) a2 += __shfl_down_sync(0xffffffffu, a2, off);
        int ridx = r0 + r;
        if (lane == 0 && ridx < 1023) table[w * 1023 + ridx] = a2 + b3[w];
    }
}

// ---------------- sequence-axis LayerNorm (fp32 stats, half out) ------------------
__global__ void seqln_kernel(const float* __restrict__ x, const float* __restrict__ g,
                             __half* __restrict__ xn) {
    int d = blockIdx.x * blockDim.x + threadIdx.x;
    int b = blockIdx.y;
    const float* xb = x + (size_t)b * SEQ * DIMV;
    float s = 0.f, ss = 0.f;
    for (int n = 0; n < SEQ; n++) { float v = xb[n * DIMV + d]; s += v; ss += v * v; }
    float mean = s * (1.f / SEQ);
    float var  = ss * (1.f / SEQ) - mean * mean;
    float inv  = rsqrtf(fmaxf(var, EPSV)) * g[d];
    __half* ob = xn + (size_t)b * SEQ * DIMV;
    for (int n = 0; n < SEQ; n++) ob[n * DIMV + d] = __float2half((xb[n * DIMV + d] - mean) * inv);
}

// ---------------- fused flash attention (fp16 mma + ldmatrix, fp32 softmax) -------
#define FA_ST  72
#define FA_QS  0
#define FA_KS  (FA_QS + 128*FA_ST)
#define FA_VS  (FA_KS + 2*64*FA_ST)
#define FA_PS  (FA_VS + 2*64*FA_ST)
#define FA_HEND (FA_PS + 8*16*FA_ST)
#define FA_BYTES (FA_HEND*2 + 1024*4)

__global__ __launch_bounds__(256, 1)
void flash_kernel(const __half* __restrict__ q, const __half* __restrict__ k,
                  const __half* __restrict__ v, const float* __restrict__ table,
                  __half* __restrict__ o) {
    extern __shared__ char smraw[];
    __half* smh = (__half*)smraw;
    float*  Bi  = (float*)(smraw + FA_HEND * 2);

    const int qt = blockIdx.x;
    const int z  = blockIdx.y;
    const int h  = z & (HEADS - 1);
    const int b  = z >> 4;
    const int qbase = qt * 128;
    const int tid = threadIdx.x;
    const int w = tid >> 5, lane = tid & 31;
    const int gid = lane >> 2, tg = lane & 3;

    const __half* qz = q + (size_t)z * SEQ * DHEAD;
    const __half* kz = k + (size_t)z * SEQ * DHEAD;
    const __half* vz = v + (size_t)z * SEQ * DHEAD;

    const uint32_t sbase = (uint32_t)__cvta_generic_to_shared(smh);

    // ldmatrix lane geometry
    const int aRowOff = ((lane & 15) * FA_ST) + (lane >> 4) * 8;                  // A frags (Q, P)
    const int kRowOff = (((lane & 7) + ((lane >> 4) & 1) * 8) * FA_ST) + ((lane >> 3) & 1) * 8; // B frags (K)
    const int vRowOff = (((lane & 7) + ((lane >> 3) & 1) * 8) * FA_ST) + ((lane >> 4) & 1) * 8; // V trans

    #pragma unroll
    for (int c = tid; c < 128 * 8; c += 256) {
        int m = c >> 3, kc = c & 7;
        cp16(sbase + (uint32_t)((FA_QS + m * FA_ST + kc * 8) * 2),
             qz + (qbase + m) * DHEAD + kc * 8);
    }
    for (int i = tid; i < 1023; i += 256) Bi[i] = table[h * 1023 + i];

    auto stage_kv = [&](int buf, int jt) {
        int kb = jt * 64;
        #pragma unroll
        for (int c = tid; c < 64 * 8; c += 256) {
            int r = c >> 3, kc = c & 7;
            cp16(sbase + (uint32_t)((FA_KS + buf * 64 * FA_ST + r * FA_ST + kc * 8) * 2),
                 kz + (kb + r) * DHEAD + kc * 8);
            cp16(sbase + (uint32_t)((FA_VS + buf * 64 * FA_ST + r * FA_ST + kc * 8) * 2),
                 vz + (kb + r) * DHEAD + kc * 8);
        }
    };

    stage_kv(0, 0);
    cp_commit();

    float m_row[2] = {-1e30f, -1e30f};
    float l_row[2] = {0.f, 0.f};
    float oacc[8][4];
    #pragma unroll
    for (int j = 0; j < 8; j++)
        #pragma unroll
        for (int e = 0; e < 4; e++) oacc[j][e] = 0.f;

    __half* Ps = smh + FA_PS + w * 16 * FA_ST;
    const uint32_t qA = sbase + (uint32_t)((FA_QS + w * 16 * FA_ST + aRowOff) * 2);
    const uint32_t pA = sbase + (uint32_t)((FA_PS + w * 16 * FA_ST + aRowOff) * 2);

    int buf = 0;
    for (int jt = 0; jt < 8; jt++) {
        if (jt + 1 < 8) { stage_kv(buf ^ 1, jt + 1); cp_commit(); cp_wait1(); }
        else cp_wait0();
        __syncthreads();

        const uint32_t kB = sbase + (uint32_t)((FA_KS + buf * 64 * FA_ST + kRowOff) * 2);
        const uint32_t vB = sbase + (uint32_t)((FA_VS + buf * 64 * FA_ST + vRowOff) * 2);
        const int kb = jt * 64;

        // ---- S = Q K^T ----
        float s[8][4];
        #pragma unroll
        for (int j = 0; j < 8; j++)
            #pragma unroll
            for (int e = 0; e < 4; e++) s[j][e] = 0.f;
        #pragma unroll
        for (int ks = 0; ks < 64; ks += 16) {
            uint32_t a[4];
            ldsm4(a, qA + (uint32_t)(ks * 2));
            #pragma unroll
            for (int jj = 0; jj < 4; jj++) {
                uint32_t bk[4];
                ldsm4(bk, kB + (uint32_t)((jj * 16 * FA_ST + ks) * 2));
                mma_f16(s[2 * jj],     a, &bk[0]);
                mma_f16(s[2 * jj + 1], a, &bk[2]);
            }
        }

        // ---- scale + bias, online softmax ----
        int qi0 = qbase + w * 16 + gid;
        float mx0 = -1e30f, mx1 = -1e30f;
        #pragma unroll
        for (int j = 0; j < 8; j++) {
            int kj = kb + j * 8 + 2 * tg;
            s[j][0] = s[j][0] * 0.125f + Bi[qi0 - kj + 511];
            s[j][1] = s[j][1] * 0.125f + Bi[qi0 - kj + 510];
            s[j][2] = s[j][2] * 0.125f + Bi[qi0 + 8 - kj + 511];
            s[j][3] = s[j][3] * 0.125f + Bi[qi0 + 8 - kj + 510];
            mx0 = fmaxf(mx0, fmaxf(s[j][0], s[j][1]));
            mx1 = fmaxf(mx1, fmaxf(s[j][2], s[j][3]));
        }
        mx0 = qmax2(mx0); mx1 = qmax2(mx1);
        float mn0 = fmaxf(m_row[0], mx0), mn1 = fmaxf(m_row[1], mx1);
        float sc0 = __expf(m_row[0] - mn0), sc1 = __expf(m_row[1] - mn1);
        float rs0 = 0.f, rs1 = 0.f;
        #pragma unroll
        for (int j = 0; j < 8; j++) {
            s[j][0] = __expf(s[j][0] - mn0);
            s[j][1] = __expf(s[j][1] - mn0);
            s[j][2] = __expf(s[j][2] - mn1);
            s[j][3] = __expf(s[j][3] - mn1);
            rs0 += s[j][0] + s[j][1];
            rs1 += s[j][2] + s[j][3];
        }
        rs0 = qsum2(rs0); rs1 = qsum2(rs1);
        l_row[0] = l_row[0] * sc0 + rs0;
        l_row[1] = l_row[1] * sc1 + rs1;
        m_row[0] = mn0; m_row[1] = mn1;
        #pragma unroll
        for (int j = 0; j < 8; j++) {
            oacc[j][0] *= sc0; oacc[j][1] *= sc0;
            oacc[j][2] *= sc1; oacc[j][3] *= sc1;
        }

        // ---- store P (half) to warp-private smem ----
        #pragma unroll
        for (int j = 0; j < 8; j++) {
            *(__half2*)&Ps[gid * FA_ST + j * 8 + 2 * tg]       = __floats2half2_rn(s[j][0], s[j][1]);
            *(__half2*)&Ps[(gid + 8) * FA_ST + j * 8 + 2 * tg] = __floats2half2_rn(s[j][2], s[j][3]);
        }
        __syncwarp();

        // ---- O += P V (V B-frags via ldmatrix.trans) ----
        #pragma unroll
        for (int ks = 0; ks < 64; ks += 16) {
            uint32_t a[4];
            ldsm4(a, pA + (uint32_t)(ks * 2));
            #pragma unroll
            for (int jj = 0; jj < 4; jj++) {
                uint32_t bv[4];
                ldsm4t(bv, vB + (uint32_t)((ks * FA_ST + jj * 16) * 2));
                mma_f16(oacc[2 * jj],     a, &bv[0]);
                mma_f16(oacc[2 * jj + 1], a, &bv[2]);
            }
        }
        __syncwarp();
        __syncthreads();
        buf ^= 1;
    }

    float inv0 = 1.f / l_row[0], inv1 = 1.f / l_row[1];
    int qi = qbase + w * 16 + gid;
    #pragma unroll
    for (int j = 0; j < 8; j++) {
        int d = j * 8 + 2 * tg;
        size_t r0 = ((size_t)(b * SEQ + qi) * INNERV) + h * DHEAD + d;
        size_t r1 = ((size_t)(b * SEQ + qi + 8) * INNERV) + h * DHEAD + d;
        *(__half2*)&o[r0] = __floats2half2_rn(oacc[j][0] * inv0, oacc[j][1] * inv0);
        *(__half2*)&o[r1] = __floats2half2_rn(oacc[j][2] * inv1, oacc[j][3] * inv1);
    }
}

// ---------------- channel LayerNorm over FFH per token (half in/out, fp32 stats) --
__global__ void chanln_kernel(__half* __restrict__ tb, const float* __restrict__ gg) {
    int m = blockIdx.x;
    __half* row = tb + (size_t)m * LDT;
    int t = threadIdx.x;
    float s = 0.f, ss = 0.f;
    for (int j = t; j < FFH; j += 256) { float v = __half2float(row[j]); s += v; ss += v * v; }
    __shared__ float r1[256], r2[256];
    r1[t] = s; r2[t] = ss; __syncthreads();
    for (int k = 128; k; k >>= 1) { if (t < k) { r1[t] += r1[t + k]; r2[t] += r2[t + k]; } __syncthreads(); }
    float mean = r1[0] * (1.f / FFH);
    float var  = r2[0] * (1.f / FFH) - mean * mean;
    float inv  = rsqrtf(fmaxf(var, EPSV));
    for (int j = t; j < FFH; j += 256)
        row[j] = __float2half((__half2float(row[j]) - mean) * inv * gg[j]);
    if (t < LDT - FFH) row[FFH + t] = __half(0.f);
}

// ---------------- fp16 tensor-core GEMM, NT, ldmatrix, 3-stage cp.async -----------
// EPI: 1 = Cf = v + R (float); 2 = merged-qkv head-split half store;
//      4 = y float + yh half
template<int BM, int BN, int BK, int WM, int WN, int EPI>
__global__ __launch_bounds__(256, 1)
void hgemm(const __half* __restrict__ A, const __half* __restrict__ B,
           float* __restrict__ Cf, __half* __restrict__ Ch, const float* __restrict__ R,
           int M, int Nn, int K, int lda, int ldb, int ldc) {
    constexpr int WARPS_N = BN / WN;
    constexpr int MT = WM / 16, NT = WN / 8;
    constexpr int AST = BK + 8;
    constexpr int BST = BK + 8;
    constexpr int ABUF = BM * AST;
    constexpr int BBUF = BN * BST;

    extern __shared__ char smraw[];
    __half* Asm = (__half*)smraw;
    __half* Bsm = Asm + 3 * ABUF;

    const int m0 = blockIdx.y * BM;
    const int n0 = blockIdx.x * BN;
    const int tid = threadIdx.x;
    const int warp = tid >> 5, lane = tid & 31;
    const int wr = warp / WARPS_N, wc = warp % WARPS_N;
    const int gid = lane >> 2, tg = lane & 3;

    const uint32_t sAb = (uint32_t)__cvta_generic_to_shared(Asm);
    const uint32_t sBb = (uint32_t)__cvta_generic_to_shared(Bsm);

    const int aRow  = wr * WM + (lane & 15);
    const int aKoff = (lane & 16) >> 1;
    const int bRow  = wc * WN + ((lane >> 4) & 1) * 8 + (lane & 7);
    const int bKoff = ((lane >> 3) & 1) * 8;

    float acc[MT][NT][4];
    #pragma unroll
    for (int i = 0; i < MT; i++)
        #pragma unroll
        for (int j = 0; j < NT; j++)
            #pragma unroll
            for (int e = 0; e < 4; e++) acc[i][j][e] = 0.f;

    const int NIT = K / BK;

    auto stage = [&](int b, int k0) {
        constexpr int ACH = BK / 8;
        #pragma unroll
        for (int c = tid; c < BM * ACH; c += 256) {
            int m = c / ACH, kc = c % ACH;
            cp16(sAb + (uint32_t)((b * ABUF + m * AST + kc * 8) * 2),
                 A + (size_t)(m0 + m) * lda + k0 + kc * 8);
        }
        constexpr int BCH = BK / 8;
        #pragma unroll
        for (int c = tid; c < BN * BCH; c += 256) {
            int n = c / BCH, kc = c % BCH;
            cp16(sBb + (uint32_t)((b * BBUF + n * BST + kc * 8) * 2),
                 B + (size_t)(n0 + n) * ldb + k0 + kc * 8);
        }
    };

    stage(0, 0);      cp_commit();
    stage(1, BK);     cp_commit();
    for (int it = 0; it < NIT; it++) {
        if (it + 2 < NIT) cp_wait1(); else cp_wait0();
        __syncthreads();
        if (it + 2 < NIT) { stage((it + 2) % 3, (it + 2) * BK); cp_commit(); }

        const int buf = it % 3;
        const uint32_t aB = sAb + (uint32_t)((buf * ABUF + aRow * AST + aKoff) * 2);
        const uint32_t bB = sBb + (uint32_t)((buf * BBUF + bRow * BST + bKoff) * 2);
        #pragma unroll
        for (int ks = 0; ks < BK; ks += 16) {
            uint32_t af[MT][4];
            uint32_t bf[NT][4];
            #pragma unroll
            for (int i = 0; i < MT; i++)
                ldsm4(af[i], aB + (uint32_t)((i * 16 * AST + ks) * 2));
            #pragma unroll
            for (int jj = 0; jj < NT / 2; jj++)
                ldsm4(bf[jj], bB + (uint32_t)((jj * 16 * BST + ks) * 2));
            #pragma unroll
            for (int i = 0; i < MT; i++)
                #pragma unroll
                for (int jj = 0; jj < NT / 2; jj++) {
                    mma_f16(acc[i][2 * jj],     af[i], &bf[jj][0]);
                    mma_f16(acc[i][2 * jj + 1], af[i], &bf[jj][2]);
                }
        }
    }

    #pragma unroll
    for (int i = 0; i < MT; i++) {
        #pragma unroll
        for (int j = 0; j < NT; j++) {
            int m_lo = m0 + wr * WM + i * 16 + gid;
            int n_e  = n0 + wc * WN + j * 8 + 2 * tg;
            if (EPI == 2) {
                // paired half2 stores (n, n+1 are d, d+1 in same head)
                #pragma unroll
                for (int half_i = 0; half_i < 2; half_i++) {
                    int m = m_lo + half_i * 8;
                    if (m < M && n_e + 1 < Nn) {
                        int which = n_e >> 10;
                        int nn2 = n_e & 1023;
                        int hh = nn2 >> 6, d = nn2 & (DHEAD - 1);
                        int bb = m >> 9, sq = m & (SEQ - 1);
                        __half2 hv = __floats2half2_rn(acc[i][j][2 * half_i], acc[i][j][2 * half_i + 1]);
                        *(__half2*)&Ch[(size_t)which * MROWS * INNERV +
                                       ((((size_t)bb * HEADS + hh) * SEQ + sq) << 6) + d] = hv;
                    }
                }
            } else {
                #pragma unroll
                for (int e = 0; e < 4; e++) {
                    int m = m_lo + ((e >= 2) ? 8 : 0);
                    int n = n_e + (e & 1);
                    if (m < M && n < Nn) {
                        float v = acc[i][j][e];
                        if (EPI == 1) {
                            Cf[(size_t)m * ldc + n] = v + R[(size_t)m * ldc + n];
                        } else { // EPI == 4
                            float r = v + R[(size_t)m * ldc + n];
                            Cf[(size_t)m * ldc + n] = r;
                            Ch[(size_t)m * ldc + n] = __float2half(r);
                        }
                    }
                }
            }
        }
    }
}

// ---------------- fp16 GEGLU GEMM (two NT B tiles), ldmatrix, 3-stage -------------
template<int BM, int BN, int BK, int WM, int WN>
__global__ __launch_bounds__(256, 1)
void hgemm_geglu(const __half* __restrict__ A, const __half* __restrict__ B,
                 __half* __restrict__ C, int M, int Nn, int K, int ldb, int ldc) {
    constexpr int WARPS_N = BN / WN;
    constexpr int MT = WM / 16, NT = WN / 8;
    constexpr int AST = BK + 8;
    constexpr int BST = BK + 8;
    constexpr int ABUF = BM * AST;
    constexpr int BBUF = BN * BST;

    extern __shared__ char smraw[];
    __half* Asm = (__half*)smraw;
    __half* B1m = Asm + 3 * ABUF;
    __half* B2m = B1m + 3 * BBUF;

    const int m0 = blockIdx.y * BM;
    const int n0 = blockIdx.x * BN;
    const int tid = threadIdx.x;
    const int warp = tid >> 5, lane = tid & 31;
    const int wr = warp / WARPS_N, wc = warp % WARPS_N;
    const int gid = lane >> 2, tg = lane & 3;

    const uint32_t sAb = (uint32_t)__cvta_generic_to_shared(Asm);
    const uint32_t sB1 = (uint32_t)__cvta_generic_to_shared(B1m);
    const uint32_t sB2 = (uint32_t)__cvta_generic_to_shared(B2m);

    const int aRow  = wr * WM + (lane & 15);
    const int aKoff = (lane & 16) >> 1;
    const int bRow  = wc * WN + ((lane >> 4) & 1) * 8 + (lane & 7);
    const int bKoff = ((lane >> 3) & 1) * 8;

    float a1[MT][NT][4], a2[MT][NT][4];
    #pragma unroll
    for (int i = 0; i < MT; i++)
        #pragma unroll
        for (int j = 0; j < NT; j++)
            #pragma unroll
            for (int e = 0; e < 4; e++) { a1[i][j][e] = 0.f; a2[i][j][e] = 0.f; }

    const int NIT = K / BK;

    auto stage = [&](int b, int k0) {
        constexpr int ACH = BK / 8;
        #pragma unroll
        for (int c = tid; c < BM * ACH; c += 256) {
            int m = c / ACH, kc = c % ACH;
            cp16(sAb + (uint32_t)((b * ABUF + m * AST + kc * 8) * 2),
                 A + (size_t)(m0 + m) * K + k0 + kc * 8);
        }
        constexpr int BCH = BK / 8;
        #pragma unroll
        for (int c = tid; c < BN * BCH; c += 256) {
            int n = c / BCH, kc = c % BCH;
            int gn = n0 + n; if (gn > FFH - 1) gn = FFH - 1;
            uint32_t off = (uint32_t)((b * BBUF + n * BST + kc * 8) * 2);
            cp16(sB1 + off, B + (size_t)gn * ldb + k0 + kc * 8);
            cp16(sB2 + off, B + (size_t)(gn + FFH) * ldb + k0 + kc * 8);
        }
    };

    stage(0, 0);   cp_commit();
    stage(1, BK);  cp_commit();
    for (int it = 0; it < NIT; it++) {
        if (it + 2 < NIT) cp_wait1(); else cp_wait0();
        __syncthreads();
        if (it + 2 < NIT) { stage((it + 2) % 3, (it + 2) * BK); cp_commit(); }

        const int buf = it % 3;
        const uint32_t aB  = sAb + (uint32_t)((buf * ABUF + aRow * AST + aKoff) * 2);
        const uint32_t bB1 = sB1 + (uint32_t)((buf * BBUF + bRow * BST + bKoff) * 2);
        const uint32_t bB2 = sB2 + (uint32_t)((buf * BBUF + bRow * BST + bKoff) * 2);
        #pragma unroll
        for (int ks = 0; ks < BK; ks += 16) {
            uint32_t af[MT][4];
            uint32_t bf1[NT / 2][4], bf2[NT / 2][4];
            #pragma unroll
            for (int i = 0; i < MT; i++)
                ldsm4(af[i], aB + (uint32_t)((i * 16 * AST + ks) * 2));
            #pragma unroll
            for (int jj = 0; jj < NT / 2; jj++) {
                ldsm4(bf1[jj], bB1 + (uint32_t)((jj * 16 * BST + ks) * 2));
                ldsm4(bf2[jj], bB2 + (uint32_t)((jj * 16 * BST + ks) * 2));
            }
            #pragma unroll
            for (int i = 0; i < MT; i++)
                #pragma unroll
                for (int jj = 0; jj < NT / 2; jj++) {
                    mma_f16(a1[i][2 * jj],     af[i], &bf1[jj][0]);
                    mma_f16(a1[i][2 * jj + 1], af[i], &bf1[jj][2]);
                    mma_f16(a2[i][2 * jj],     af[i], &bf2[jj][0]);
                    mma_f16(a2[i][2 * jj + 1], af[i], &bf2[jj][2]);
                }
        }
    }

    #pragma unroll
    for (int i = 0; i < MT; i++) {
        #pragma unroll
        for (int j = 0; j < NT; j++) {
            #pragma unroll
            for (int e = 0; e < 4; e++) {
                int m = m0 + wr * WM + i * 16 + gid + ((e >= 2) ? 8 : 0);
                int n = n0 + wc * WN + j * 8 + 2 * tg + (e & 1);
                if (m < M && n < Nn) {
                    float g  = a2[i][j][e];
                    float ge = 0.5f * g * (1.f + erff(g * 0.70710678118654752f));
                    C[(size_t)m * ldc + n] = __float2half(a1[i][j][e] * ge);
                }
            }
        }
    }
}

// ---------------- launch ---------------------------------------------------------
extern "C" void kernel_launch(void* const* d_in, const int* in_sizes, int n_in,
                              void* d_out, int out_size) {
    const float* x      = (const float*)d_in[0];
    const float* g_ln   = (const float*)d_in[1];
    const float* Wq     = (const float*)d_in[2];
    const float* Wkv    = (const float*)d_in[3];
    const float* Wo     = (const float*)d_in[4];
    const float* cpb_w1 = (const float*)d_in[5];
    const float* cpb_b1 = (const float*)d_in[6];
    const float* cpb_w2 = (const float*)d_in[7];
    const float* cpb_b2 = (const float*)d_in[8];
    const float* cpb_w3 = (const float*)d_in[9];
    const float* cpb_b3 = (const float*)d_in[10];
    const float* ff_w_in  = (const float*)d_in[11];
    const float* ff_g     = (const float*)d_in[12];
    const float* ff_w_out = (const float*)d_in[13];
    float* out = (float*)d_out;

    float *bias, *y;
    __half *xn, *qkv, *o, *yh, *t;
    __half *cWqkvT, *cWoT, *cWin, *cWoutP;
    cudaGetSymbolAddress((void**)&bias, g_bias);
    cudaGetSymbolAddress((void**)&xn,  g_xn);
    cudaGetSymbolAddress((void**)&qkv, g_qkv);
    cudaGetSymbolAddress((void**)&o,   g_o);
    cudaGetSymbolAddress((void**)&y,   g_y);
    cudaGetSymbolAddress((void**)&yh,  g_yh);
    cudaGetSymbolAddress((void**)&t,   g_t);
    cudaGetSymbolAddress((void**)&cWqkvT, g_cWqkvT);
    cudaGetSymbolAddress((void**)&cWoT,   g_cWoT);
    cudaGetSymbolAddress((void**)&cWin,   g_cWin);
    cudaGetSymbolAddress((void**)&cWoutP, g_cWoutP);

    auto T_QKV = hgemm<256,128,32,64,64,2>;
    auto T_OP  = hgemm<256,128,32,64,64,4>;
    auto T_FFO = hgemm<256,128,32,64,64,1>;
    auto T_GG  = hgemm_geglu<256,64,32,64,32>;

    const int SM_G  = (3*256*40 + 3*128*40) * 2;     // 92160 B
    const int SM_GG = (3*256*40 + 6*64*40)  * 2;     // 92160 B

    cudaFuncSetAttribute(T_QKV, cudaFuncAttributeMaxDynamicSharedMemorySize, SM_G);
    cudaFuncSetAttribute(T_OP,  cudaFuncAttributeMaxDynamicSharedMemorySize, SM_G);
    cudaFuncSetAttribute(T_FFO, cudaFuncAttributeMaxDynamicSharedMemorySize, SM_G);
    cudaFuncSetAttribute(T_GG,  cudaFuncAttributeMaxDynamicSharedMemorySize, SM_GG);
    cudaFuncSetAttribute(flash_kernel, cudaFuncAttributeMaxDynamicSharedMemorySize, FA_BYTES);

    // 0) weight preconversion
    cvtT_kernel<<<dim3(32,32), dim3(32,8)>>>(Wq,  cWqkvT,                       DIMV, INNERV);
    cvtT_kernel<<<dim3(64,32), dim3(32,8)>>>(Wkv, cWqkvT + (size_t)INNERV*DIMV, DIMV, 2*INNERV);
    cvtT_kernel<<<dim3(32,32), dim3(32,8)>>>(Wo,  cWoT,  INNERV, DIMV);
    cvtH_kernel<<<512, 256>>>((const float4*)ff_w_in, (__half2*)cWin, 2*FFH*DIMV/4);
    cvt_pad_kernel<<<dim3((LDT+255)/256, DIMV), 256>>>(ff_w_out, cWoutP);

    // 1) CPB bias table (8 rel-positions per block)
    cpb_kernel<<<128, 512>>>(cpb_w1, cpb_b1, cpb_w2, cpb_b2, cpb_w3, cpb_b3, bias);

    // 2) sequence-axis LayerNorm (half out)
    seqln_kernel<<<dim3(DIMV / 256, BATCH), 256>>>(x, g_ln, xn);

    // 3) merged Q/K/V projection (N=3072)
    T_QKV<<<dim3(24,32),256,SM_G>>>(xn, cWqkvT, nullptr, qkv, nullptr,
        MROWS, 3*INNERV, DIMV, DIMV, DIMV, 0);

    // 4-6) fused flash attention
    flash_kernel<<<dim3(SEQ/128, BATCH*HEADS), 256, FA_BYTES>>>(
        qkv, qkv + (size_t)MROWS*INNERV, qkv + (size_t)2*MROWS*INNERV, bias, o);

    // 7) y = O @ Wo + x  (float y + half mirror)
    T_OP<<<dim3(8,32),256,SM_G>>>(o, cWoT, y, yh, x,
        MROWS, DIMV, INNERV, INNERV, INNERV, DIMV);

    // 8) FF-in + fused GEGLU (half out)
    T_GG<<<dim3((FFH+63)/64, 32),256,SM_GG>>>(yh, cWin, t,
        MROWS, FFH, DIMV, DIMV, LDT);

    // 9) channel LayerNorm (half, fp32 stats)
    chanln_kernel<<<MROWS, 256>>>(t, ff_g);

    // 10) out = t @ cWoutP^T + y  (fp32 residual add)
    T_FFO<<<dim3(8,32),256,SM_G>>>(t, cWoutP, out, nullptr, y,
        MROWS, DIMV, LDT, LDT, LDT, DIMV);
}

// round 15
// speedup vs baseline: 17.6951x; 1.1705x over previous
#include <cuda_runtime.h>
#include <cuda_fp16.h>
#include <math.h>
#include <stdint.h>

#define DIMV 1024
#define HEADS 16
#define DHEAD 64
#define BATCH 16
#define SEQ 512
#define INNERV 1024
#define CPBD 512
#define FFH 2730
#define LDT 2752            /* padded leading dim for t / cWout (halfs) */
#define MROWS (BATCH*SEQ)   /* 8192 */
#define EPSV 1e-5f

// ---------------- scratch (static device arrays; no allocations) ----------------
__device__ float  g_bias[HEADS * 1023];
__device__ __half g_xn[(size_t)MROWS * DIMV];
__device__ __half g_qkv[(size_t)3 * MROWS * INNERV];   // q | k | v  ([b,h,n,d] each)
__device__ __half g_o[(size_t)MROWS * INNERV];
__device__ float  g_y[(size_t)MROWS * DIMV];           // fp32 residual copy
__device__ __half g_yh[(size_t)MROWS * DIMV];          // half mirror
__device__ __half g_t[(size_t)MROWS * LDT];
// half-preconverted weights ([n][k] layouts)
__device__ __half g_cWqkvT[(size_t)3 * INNERV * DIMV];
__device__ __half g_cWoT[(size_t)DIMV * INNERV];
__device__ __half g_cWin[(size_t)2 * FFH * DIMV];
__device__ __half g_cWoutP[(size_t)DIMV * LDT];

// ---------------- helpers ---------------------------------------------------------
__device__ __forceinline__ void mma_f16(float d[4], const uint32_t a[4], const uint32_t b[2]) {
    asm volatile(
        "mma.sync.aligned.m16n8k16.row.col.f32.f16.f16.f32 "
        "{%0,%1,%2,%3},{%4,%5,%6,%7},{%8,%9},{%0,%1,%2,%3};\n"
        : "+f"(d[0]), "+f"(d[1]), "+f"(d[2]), "+f"(d[3])
        : "r"(a[0]), "r"(a[1]), "r"(a[2]), "r"(a[3]), "r"(b[0]), "r"(b[1]));
}
__device__ __forceinline__ void ldsm4(uint32_t r[4], uint32_t saddr) {
    asm volatile("ldmatrix.sync.aligned.m8n8.x4.shared.b16 {%0,%1,%2,%3}, [%4];"
        : "=r"(r[0]), "=r"(r[1]), "=r"(r[2]), "=r"(r[3]) : "r"(saddr));
}
__device__ __forceinline__ void ldsm4t(uint32_t r[4], uint32_t saddr) {
    asm volatile("ldmatrix.sync.aligned.m8n8.x4.trans.shared.b16 {%0,%1,%2,%3}, [%4];"
        : "=r"(r[0]), "=r"(r[1]), "=r"(r[2]), "=r"(r[3]) : "r"(saddr));
}
__device__ __forceinline__ void cp16(uint32_t s, const void* g) {
    asm volatile("cp.async.cg.shared.global [%0], [%1], 16;\n" :: "r"(s), "l"(g));
}
__device__ __forceinline__ void cp_commit() { asm volatile("cp.async.commit_group;\n"); }
__device__ __forceinline__ void cp_wait1()  { asm volatile("cp.async.wait_group 1;\n"); }
__device__ __forceinline__ void cp_wait0()  { asm volatile("cp.async.wait_group 0;\n"); }
__device__ __forceinline__ float qmax2(float v) {
    v = fmaxf(v, __shfl_xor_sync(0xffffffffu, v, 1));
    v = fmaxf(v, __shfl_xor_sync(0xffffffffu, v, 2));
    return v;
}
__device__ __forceinline__ float qsum2(float v) {
    v += __shfl_xor_sync(0xffffffffu, v, 1);
    v += __shfl_xor_sync(0xffffffffu, v, 2);
    return v;
}

// ---------------- weight preconvert kernels ---------------------------------------
__global__ void cvtT_kernel(const float* __restrict__ in, __half* __restrict__ out,
                            int K, int N) {
    __shared__ float tile[32][33];
    int n0 = blockIdx.x * 32, k0 = blockIdx.y * 32;
    int tx = threadIdx.x, ty0 = threadIdx.y;
    #pragma unroll
    for (int ty = ty0; ty < 32; ty += 8)
        tile[ty][tx] = in[(size_t)(k0 + ty) * N + n0 + tx];
    __syncthreads();
    #pragma unroll
    for (int ty = ty0; ty < 32; ty += 8)
        out[(size_t)(n0 + ty) * K + k0 + tx] = __float2half(tile[tx][ty]);
}
__global__ void cvtH_kernel(const float4* __restrict__ in, __half2* __restrict__ out, int n4) {
    int i = blockIdx.x * blockDim.x + threadIdx.x;
    int stride = gridDim.x * blockDim.x;
    for (; i < n4; i += stride) {
        float4 v = in[i];
        out[2 * i]     = __floats2half2_rn(v.x, v.y);
        out[2 * i + 1] = __floats2half2_rn(v.z, v.w);
    }
}
__global__ void cvt_pad_kernel(const float* __restrict__ in, __half* __restrict__ out) {
    int r = blockIdx.y;
    int c = blockIdx.x * 256 + threadIdx.x;
    if (c < LDT) out[(size_t)r * LDT + c] =
        (c < FFH) ? __float2half(in[(size_t)r * FFH + c]) : __half(0.f);
}

// ---------------- CPB: 8 rel-positions per block ----------------------------------
#define CPB_R 8
__global__ void cpb_kernel(const float* __restrict__ w1, const float* __restrict__ b1,
                           const float* __restrict__ w2, const float* __restrict__ b2,
                           const float* __restrict__ w3, const float* __restrict__ b3,
                           float* __restrict__ table) {
    __shared__ float h1[CPB_R][CPBD];
    __shared__ float h2[CPB_R][CPBD];
    int t = threadIdx.x;
    int r0 = blockIdx.x * CPB_R;
    #pragma unroll
    for (int r = 0; r < CPB_R; r++) {
        int ridx = r0 + r;
        float rf = (float)(ridx - 511);
        float sgn = (rf > 0.f) ? 1.f : ((rf < 0.f) ? -1.f : 0.f);
        float rel = sgn * logf(fabsf(rf) + 1.f);
        float z = rel * w1[t] + b1[t];
        h1[r][t] = z / (1.f + expf(-z));
    }
    __syncthreads();
    float acc[CPB_R];
    #pragma unroll
    for (int r = 0; r < CPB_R; r++) acc[r] = b2[t];
    for (int j = 0; j < CPBD; j++) {
        float wv = w2[j * CPBD + t];
        #pragma unroll
        for (int r = 0; r < CPB_R; r++) acc[r] += h1[r][j] * wv;
    }
    #pragma unroll
    for (int r = 0; r < CPB_R; r++) {
        float z = acc[r];
        h2[r][t] = z / (1.f + expf(-z));
    }
    __syncthreads();
    int w = t >> 5, lane = t & 31;
    #pragma unroll
    for (int r = 0; r < CPB_R; r++) {
        float a2 = 0.f;
        #pragma unroll 4
        for (int i = lane; i < CPBD; i += 32) a2 += h2[r][i] * w3[i * HEADS + w];
        #pragma unroll
        for (int off = 16; off; off >>= 1) a2 += __shfl_down_sync(0xffffffffu, a2, off);
        int ridx = r0 + r;
        if (lane == 0 && ridx < 1023) table[w * 1023 + ridx] = a2 + b3[w];
    }
}

// ---------------- sequence-axis LayerNorm (fp32 stats, half out) ------------------
__global__ void seqln_kernel(const float* __restrict__ x, const float* __restrict__ g,
                             __half* __restrict__ xn) {
    int d = blockIdx.x * blockDim.x + threadIdx.x;
    int b = blockIdx.y;
    const float* xb = x + (size_t)b * SEQ * DIMV;
    float s = 0.f, ss = 0.f;
    for (int n = 0; n < SEQ; n++) { float v = xb[n * DIMV + d]; s += v; ss += v * v; }
    float mean = s * (1.f / SEQ);
    float var  = ss * (1.f / SEQ) - mean * mean;
    float inv  = rsqrtf(fmaxf(var, EPSV)) * g[d];
    __half* ob = xn + (size_t)b * SEQ * DIMV;
    for (int n = 0; n < SEQ; n++) ob[n * DIMV + d] = __float2half((xb[n * DIMV + d] - mean) * inv);
}

// ---------------- fused flash attention (fp16 mma + ldmatrix, fp32 softmax) -------
#define FA_ST  72
#define FA_QS  0
#define FA_KS  (FA_QS + 128*FA_ST)
#define FA_VS  (FA_KS + 2*64*FA_ST)
#define FA_PS  (FA_VS + 2*64*FA_ST)
#define FA_HEND (FA_PS + 8*16*FA_ST)
#define FA_BYTES (FA_HEND*2 + 1024*4)

__global__ __launch_bounds__(256, 1)
void flash_kernel(const __half* __restrict__ q, const __half* __restrict__ k,
                  const __half* __restrict__ v, const float* __restrict__ table,
                  __half* __restrict__ o) {
    extern __shared__ char smraw[];
    __half* smh = (__half*)smraw;
    float*  Bi  = (float*)(smraw + FA_HEND * 2);

    const int qt = blockIdx.x;
    const int z  = blockIdx.y;
    const int h  = z & (HEADS - 1);
    const int b  = z >> 4;
    const int qbase = qt * 128;
    const int tid = threadIdx.x;
    const int w = tid >> 5, lane = tid & 31;
    const int gid = lane >> 2, tg = lane & 3;

    const __half* qz = q + (size_t)z * SEQ * DHEAD;
    const __half* kz = k + (size_t)z * SEQ * DHEAD;
    const __half* vz = v + (size_t)z * SEQ * DHEAD;

    const uint32_t sbase = (uint32_t)__cvta_generic_to_shared(smh);

    const int aRowOff = ((lane & 15) * FA_ST) + (lane >> 4) * 8;
    const int kRowOff = (((lane & 7) + ((lane >> 4) & 1) * 8) * FA_ST) + ((lane >> 3) & 1) * 8;
    const int vRowOff = (((lane & 7) + ((lane >> 3) & 1) * 8) * FA_ST) + ((lane >> 4) & 1) * 8;

    #pragma unroll
    for (int c = tid; c < 128 * 8; c += 256) {
        int m = c >> 3, kc = c & 7;
        cp16(sbase + (uint32_t)((FA_QS + m * FA_ST + kc * 8) * 2),
             qz + (qbase + m) * DHEAD + kc * 8);
    }
    for (int i = tid; i < 1023; i += 256) Bi[i] = table[h * 1023 + i];

    auto stage_kv = [&](int buf, int jt) {
        int kb = jt * 64;
        #pragma unroll
        for (int c = tid; c < 64 * 8; c += 256) {
            int r = c >> 3, kc = c & 7;
            cp16(sbase + (uint32_t)((FA_KS + buf * 64 * FA_ST + r * FA_ST + kc * 8) * 2),
                 kz + (kb + r) * DHEAD + kc * 8);
            cp16(sbase + (uint32_t)((FA_VS + buf * 64 * FA_ST + r * FA_ST + kc * 8) * 2),
                 vz + (kb + r) * DHEAD + kc * 8);
        }
    };

    stage_kv(0, 0);
    cp_commit();

    float m_row[2] = {-1e30f, -1e30f};
    float l_row[2] = {0.f, 0.f};
    float oacc[8][4];
    #pragma unroll
    for (int j = 0; j < 8; j++)
        #pragma unroll
        for (int e = 0; e < 4; e++) oacc[j][e] = 0.f;

    __half* Ps = smh + FA_PS + w * 16 * FA_ST;
    const uint32_t qA = sbase + (uint32_t)((FA_QS + w * 16 * FA_ST + aRowOff) * 2);
    const uint32_t pA = sbase + (uint32_t)((FA_PS + w * 16 * FA_ST + aRowOff) * 2);

    int buf = 0;
    for (int jt = 0; jt < 8; jt++) {
        if (jt + 1 < 8) { stage_kv(buf ^ 1, jt + 1); cp_commit(); cp_wait1(); }
        else cp_wait0();
        __syncthreads();

        const uint32_t kB = sbase + (uint32_t)((FA_KS + buf * 64 * FA_ST + kRowOff) * 2);
        const uint32_t vB = sbase + (uint32_t)((FA_VS + buf * 64 * FA_ST + vRowOff) * 2);
        const int kb = jt * 64;

        float s[8][4];
        #pragma unroll
        for (int j = 0; j < 8; j++)
            #pragma unroll
            for (int e = 0; e < 4; e++) s[j][e] = 0.f;
        #pragma unroll
        for (int ks = 0; ks < 64; ks += 16) {
            uint32_t a[4];
            ldsm4(a, qA + (uint32_t)(ks * 2));
            #pragma unroll
            for (int jj = 0; jj < 4; jj++) {
                uint32_t bk[4];
                ldsm4(bk, kB + (uint32_t)((jj * 16 * FA_ST + ks) * 2));
                mma_f16(s[2 * jj],     a, &bk[0]);
                mma_f16(s[2 * jj + 1], a, &bk[2]);
            }
        }

        int qi0 = qbase + w * 16 + gid;
        float mx0 = -1e30f, mx1 = -1e30f;
        #pragma unroll
        for (int j = 0; j < 8; j++) {
            int kj = kb + j * 8 + 2 * tg;
            s[j][0] = s[j][0] * 0.125f + Bi[qi0 - kj + 511];
            s[j][1] = s[j][1] * 0.125f + Bi[qi0 - kj + 510];
            s[j][2] = s[j][2] * 0.125f + Bi[qi0 + 8 - kj + 511];
            s[j][3] = s[j][3] * 0.125f + Bi[qi0 + 8 - kj + 510];
            mx0 = fmaxf(mx0, fmaxf(s[j][0], s[j][1]));
            mx1 = fmaxf(mx1, fmaxf(s[j][2], s[j][3]));
        }
        mx0 = qmax2(mx0); mx1 = qmax2(mx1);
        float mn0 = fmaxf(m_row[0], mx0), mn1 = fmaxf(m_row[1], mx1);
        float sc0 = __expf(m_row[0] - mn0), sc1 = __expf(m_row[1] - mn1);
        float rs0 = 0.f, rs1 = 0.f;
        #pragma unroll
        for (int j = 0; j < 8; j++) {
            s[j][0] = __expf(s[j][0] - mn0);
            s[j][1] = __expf(s[j][1] - mn0);
            s[j][2] = __expf(s[j][2] - mn1);
            s[j][3] = __expf(s[j][3] - mn1);
            rs0 += s[j][0] + s[j][1];
            rs1 += s[j][2] + s[j][3];
        }
        rs0 = qsum2(rs0); rs1 = qsum2(rs1);
        l_row[0] = l_row[0] * sc0 + rs0;
        l_row[1] = l_row[1] * sc1 + rs1;
        m_row[0] = mn0; m_row[1] = mn1;
        #pragma unroll
        for (int j = 0; j < 8; j++) {
            oacc[j][0] *= sc0; oacc[j][1] *= sc0;
            oacc[j][2] *= sc1; oacc[j][3] *= sc1;
        }

        #pragma unroll
        for (int j = 0; j < 8; j++) {
            *(__half2*)&Ps[gid * FA_ST + j * 8 + 2 * tg]       = __floats2half2_rn(s[j][0], s[j][1]);
            *(__half2*)&Ps[(gid + 8) * FA_ST + j * 8 + 2 * tg] = __floats2half2_rn(s[j][2], s[j][3]);
        }
        __syncwarp();

        #pragma unroll
        for (int ks = 0; ks < 64; ks += 16) {
            uint32_t a[4];
            ldsm4(a, pA + (uint32_t)(ks * 2));
            #pragma unroll
            for (int jj = 0; jj < 4; jj++) {
                uint32_t bv[4];
                ldsm4t(bv, vB + (uint32_t)((ks * FA_ST + jj * 16) * 2));
                mma_f16(oacc[2 * jj],     a, &bv[0]);
                mma_f16(oacc[2 * jj + 1], a, &bv[2]);
            }
        }
        __syncwarp();
        __syncthreads();
        buf ^= 1;
    }

    float inv0 = 1.f / l_row[0], inv1 = 1.f / l_row[1];
    int qi = qbase + w * 16 + gid;
    #pragma unroll
    for (int j = 0; j < 8; j++) {
        int d = j * 8 + 2 * tg;
        size_t r0 = ((size_t)(b * SEQ + qi) * INNERV) + h * DHEAD + d;
        size_t r1 = ((size_t)(b * SEQ + qi + 8) * INNERV) + h * DHEAD + d;
        *(__half2*)&o[r0] = __floats2half2_rn(oacc[j][0] * inv0, oacc[j][1] * inv0);
        *(__half2*)&o[r1] = __floats2half2_rn(oacc[j][2] * inv1, oacc[j][3] * inv1);
    }
}

// ---------------- channel LayerNorm over FFH per token ----------------------------
__global__ void chanln_kernel(__half* __restrict__ tb, const float* __restrict__ gg) {
    int m = blockIdx.x;
    __half* row = tb + (size_t)m * LDT;
    int t = threadIdx.x;
    float s = 0.f, ss = 0.f;
    for (int j = t; j < FFH; j += 256) { float v = __half2float(row[j]); s += v; ss += v * v; }
    __shared__ float r1[256], r2[256];
    r1[t] = s; r2[t] = ss; __syncthreads();
    for (int k = 128; k; k >>= 1) { if (t < k) { r1[t] += r1[t + k]; r2[t] += r2[t + k]; } __syncthreads(); }
    float mean = r1[0] * (1.f / FFH);
    float var  = r2[0] * (1.f / FFH) - mean * mean;
    float inv  = rsqrtf(fmaxf(var, EPSV));
    for (int j = t; j < FFH; j += 256)
        row[j] = __float2half((__half2float(row[j]) - mean) * inv * gg[j]);
    if (t < LDT - FFH) row[FFH + t] = __half(0.f);
}

// ---------------- fp16 tensor-core GEMM, NT, ldmatrix, 3-stage, 2 CTAs/SM ---------
// EPI: 1 = Cf = v + R (float); 2 = merged-qkv head-split half store;
//      4 = y float + yh half
template<int BM, int BN, int BK, int WM, int WN, int EPI>
__global__ __launch_bounds__(256, 2)
void hgemm(const __half* __restrict__ A, const __half* __restrict__ B,
           float* __restrict__ Cf, __half* __restrict__ Ch, const float* __restrict__ R,
           int M, int Nn, int K, int lda, int ldb, int ldc) {
    constexpr int WARPS_N = BN / WN;
    constexpr int MT = WM / 16, NT = WN / 8;
    constexpr int AST = BK + 8;
    constexpr int BST = BK + 8;
    constexpr int ABUF = BM * AST;
    constexpr int BBUF = BN * BST;

    extern __shared__ char smraw[];
    __half* Asm = (__half*)smraw;
    __half* Bsm = Asm + 3 * ABUF;

    const int m0 = blockIdx.y * BM;
    const int n0 = blockIdx.x * BN;
    const int tid = threadIdx.x;
    const int warp = tid >> 5, lane = tid & 31;
    const int wr = warp / WARPS_N, wc = warp % WARPS_N;
    const int gid = lane >> 2, tg = lane & 3;

    const uint32_t sAb = (uint32_t)__cvta_generic_to_shared(Asm);
    const uint32_t sBb = (uint32_t)__cvta_generic_to_shared(Bsm);

    const int aRow  = wr * WM + (lane & 15);
    const int aKoff = (lane & 16) >> 1;
    const int bRow  = wc * WN + ((lane >> 4) & 1) * 8 + (lane & 7);
    const int bKoff = ((lane >> 3) & 1) * 8;

    float acc[MT][NT][4];
    #pragma unroll
    for (int i = 0; i < MT; i++)
        #pragma unroll
        for (int j = 0; j < NT; j++)
            #pragma unroll
            for (int e = 0; e < 4; e++) acc[i][j][e] = 0.f;

    const int NIT = K / BK;

    auto stage = [&](int b, int k0) {
        constexpr int ACH = BK / 8;
        #pragma unroll
        for (int c = tid; c < BM * ACH; c += 256) {
            int m = c / ACH, kc = c % ACH;
            cp16(sAb + (uint32_t)((b * ABUF + m * AST + kc * 8) * 2),
                 A + (size_t)(m0 + m) * lda + k0 + kc * 8);
        }
        constexpr int BCH = BK / 8;
        #pragma unroll
        for (int c = tid; c < BN * BCH; c += 256) {
            int n = c / BCH, kc = c % BCH;
            cp16(sBb + (uint32_t)((b * BBUF + n * BST + kc * 8) * 2),
                 B + (size_t)(n0 + n) * ldb + k0 + kc * 8);
        }
    };

    stage(0, 0);      cp_commit();
    stage(1, BK);     cp_commit();
    for (int it = 0; it < NIT; it++) {
        if (it + 2 < NIT) cp_wait1(); else cp_wait0();
        __syncthreads();
        if (it + 2 < NIT) { stage((it + 2) % 3, (it + 2) * BK); cp_commit(); }

        const int buf = it % 3;
        const uint32_t aB = sAb + (uint32_t)((buf * ABUF + aRow * AST + aKoff) * 2);
        const uint32_t bB = sBb + (uint32_t)((buf * BBUF + bRow * BST + bKoff) * 2);
        #pragma unroll
        for (int ks = 0; ks < BK; ks += 16) {
            uint32_t af[MT][4];
            uint32_t bf[NT / 2][4];
            #pragma unroll
            for (int i = 0; i < MT; i++)
                ldsm4(af[i], aB + (uint32_t)((i * 16 * AST + ks) * 2));
            #pragma unroll
            for (int jj = 0; jj < NT / 2; jj++)
                ldsm4(bf[jj], bB + (uint32_t)((jj * 16 * BST + ks) * 2));
            #pragma unroll
            for (int i = 0; i < MT; i++)
                #pragma unroll
                for (int jj = 0; jj < NT / 2; jj++) {
                    mma_f16(acc[i][2 * jj],     af[i], &bf[jj][0]);
                    mma_f16(acc[i][2 * jj + 1], af[i], &bf[jj][2]);
                }
        }
    }

    #pragma unroll
    for (int i = 0; i < MT; i++) {
        #pragma unroll
        for (int j = 0; j < NT; j++) {
            int m_lo = m0 + wr * WM + i * 16 + gid;
            int n_e  = n0 + wc * WN + j * 8 + 2 * tg;
            if (EPI == 2) {
                #pragma unroll
                for (int half_i = 0; half_i < 2; half_i++) {
                    int m = m_lo + half_i * 8;
                    if (m < M && n_e + 1 < Nn) {
                        int which = n_e >> 10;
                        int nn2 = n_e & 1023;
                        int hh = nn2 >> 6, d = nn2 & (DHEAD - 1);
                        int bb = m >> 9, sq = m & (SEQ - 1);
                        __half2 hv = __floats2half2_rn(acc[i][j][2 * half_i], acc[i][j][2 * half_i + 1]);
                        *(__half2*)&Ch[(size_t)which * MROWS * INNERV +
                                       ((((size_t)bb * HEADS + hh) * SEQ + sq) << 6) + d] = hv;
                    }
                }
            } else {
                #pragma unroll
                for (int e = 0; e < 4; e++) {
                    int m = m_lo + ((e >= 2) ? 8 : 0);
                    int n = n_e + (e & 1);
                    if (m < M && n < Nn) {
                        float v = acc[i][j][e];
                        if (EPI == 1) {
                            Cf[(size_t)m * ldc + n] = v + R[(size_t)m * ldc + n];
                        } else { // EPI == 4
                            float r = v + R[(size_t)m * ldc + n];
                            Cf[(size_t)m * ldc + n] = r;
                            Ch[(size_t)m * ldc + n] = __float2half(r);
                        }
                    }
                }
            }
        }
    }
}

// ---------------- fp16 GEGLU GEMM (two NT B tiles), ldmatrix, 3-stage, 2 CTA ------
template<int BM, int BN, int BK, int WM, int WN>
__global__ __launch_bounds__(256, 2)
void hgemm_geglu(const __half* __restrict__ A, const __half* __restrict__ B,
                 __half* __restrict__ C, int M, int Nn, int K, int ldb, int ldc) {
    constexpr int WARPS_N = BN / WN;
    constexpr int MT = WM / 16, NT = WN / 8;
    constexpr int AST = BK + 8;
    constexpr int BST = BK + 8;
    constexpr int ABUF = BM * AST;
    constexpr int BBUF = BN * BST;

    extern __shared__ char smraw[];
    __half* Asm = (__half*)smraw;
    __half* B1m = Asm + 3 * ABUF;
    __half* B2m = B1m + 3 * BBUF;

    const int m0 = blockIdx.y * BM;
    const int n0 = blockIdx.x * BN;
    const int tid = threadIdx.x;
    const int warp = tid >> 5, lane = tid & 31;
    const int wr = warp / WARPS_N, wc = warp % WARPS_N;
    const int gid = lane >> 2, tg = lane & 3;

    const uint32_t sAb = (uint32_t)__cvta_generic_to_shared(Asm);
    const uint32_t sB1 = (uint32_t)__cvta_generic_to_shared(B1m);
    const uint32_t sB2 = (uint32_t)__cvta_generic_to_shared(B2m);

    const int aRow  = wr * WM + (lane & 15);
    const int aKoff = (lane & 16) >> 1;
    const int bRow  = wc * WN + ((lane >> 4) & 1) * 8 + (lane & 7);
    const int bKoff = ((lane >> 3) & 1) * 8;

    float a1[MT][NT][4], a2[MT][NT][4];
    #pragma unroll
    for (int i = 0; i < MT; i++)
        #pragma unroll
        for (int j = 0; j < NT; j++)
            #pragma unroll
            for (int e = 0; e < 4; e++) { a1[i][j][e] = 0.f; a2[i][j][e] = 0.f; }

    const int NIT = K / BK;

    auto stage = [&](int b, int k0) {
        constexpr int ACH = BK / 8;
        #pragma unroll
        for (int c = tid; c < BM * ACH; c += 256) {
            int m = c / ACH, kc = c % ACH;
            cp16(sAb + (uint32_t)((b * ABUF + m * AST + kc * 8) * 2),
                 A + (size_t)(m0 + m) * K + k0 + kc * 8);
        }
        constexpr int BCH = BK / 8;
        #pragma unroll
        for (int c = tid; c < BN * BCH; c += 256) {
            int n = c / BCH, kc = c % BCH;
            int gn = n0 + n; if (gn > FFH - 1) gn = FFH - 1;
            uint32_t off = (uint32_t)((b * BBUF + n * BST + kc * 8) * 2);
            cp16(sB1 + off, B + (size_t)gn * ldb + k0 + kc * 8);
            cp16(sB2 + off, B + (size_t)(gn + FFH) * ldb + k0 + kc * 8);
        }
    };

    stage(0, 0);   cp_commit();
    stage(1, BK);  cp_commit();
    for (int it = 0; it < NIT; it++) {
        if (it + 2 < NIT) cp_wait1(); else cp_wait0();
        __syncthreads();
        if (it + 2 < NIT) { stage((it + 2) % 3, (it + 2) * BK); cp_commit(); }

        const int buf = it % 3;
        const uint32_t aB  = sAb + (uint32_t)((buf * ABUF + aRow * AST + aKoff) * 2);
        const uint32_t bB1 = sB1 + (uint32_t)((buf * BBUF + bRow * BST + bKoff) * 2);
        const uint32_t bB2 = sB2 + (uint32_t)((buf * BBUF + bRow * BST + bKoff) * 2);
        #pragma unroll
        for (int ks = 0; ks < BK; ks += 16) {
            uint32_t af[MT][4];
            uint32_t bf1[NT / 2][4], bf2[NT / 2][4];
            #pragma unroll
            for (int i = 0; i < MT; i++)
                ldsm4(af[i], aB + (uint32_t)((i * 16 * AST + ks) * 2));
            #pragma unroll
            for (int jj = 0; jj < NT / 2; jj++) {
                ldsm4(bf1[jj], bB1 + (uint32_t)((jj * 16 * BST + ks) * 2));
                ldsm4(bf2[jj], bB2 + (uint32_t)((jj * 16 * BST + ks) * 2));
            }
            #pragma unroll
            for (int i = 0; i < MT; i++)
                #pragma unroll
                for (int jj = 0; jj < NT / 2; jj++) {
                    mma_f16(a1[i][2 * jj],     af[i], &bf1[jj][0]);
                    mma_f16(a1[i][2 * jj + 1], af[i], &bf1[jj][2]);
                    mma_f16(a2[i][2 * jj],     af[i], &bf2[jj][0]);
                    mma_f16(a2[i][2 * jj + 1], af[i], &bf2[jj][2]);
                }
        }
    }

    #pragma unroll
    for (int i = 0; i < MT; i++) {
        #pragma unroll
        for (int j = 0; j < NT; j++) {
            #pragma unroll
            for (int e = 0; e < 4; e++) {
                int m = m0 + wr * WM + i * 16 + gid + ((e >= 2) ? 8 : 0);
                int n = n0 + wc * WN + j * 8 + 2 * tg + (e & 1);
                if (m < M && n < Nn) {
                    float g  = a2[i][j][e];
                    float ge = 0.5f * g * (1.f + erff(g * 0.70710678118654752f));
                    C[(size_t)m * ldc + n] = __float2half(a1[i][j][e] * ge);
                }
            }
        }
    }
}

// ---------------- launch ---------------------------------------------------------
extern "C" void kernel_launch(void* const* d_in, const int* in_sizes, int n_in,
                              void* d_out, int out_size) {
    const float* x      = (const float*)d_in[0];
    const float* g_ln   = (const float*)d_in[1];
    const float* Wq     = (const float*)d_in[2];
    const float* Wkv    = (const float*)d_in[3];
    const float* Wo     = (const float*)d_in[4];
    const float* cpb_w1 = (const float*)d_in[5];
    const float* cpb_b1 = (const float*)d_in[6];
    const float* cpb_w2 = (const float*)d_in[7];
    const float* cpb_b2 = (const float*)d_in[8];
    const float* cpb_w3 = (const float*)d_in[9];
    const float* cpb_b3 = (const float*)d_in[10];
    const float* ff_w_in  = (const float*)d_in[11];
    const float* ff_g     = (const float*)d_in[12];
    const float* ff_w_out = (const float*)d_in[13];
    float* out = (float*)d_out;

    float *bias, *y;
    __half *xn, *qkv, *o, *yh, *t;
    __half *cWqkvT, *cWoT, *cWin, *cWoutP;
    cudaGetSymbolAddress((void**)&bias, g_bias);
    cudaGetSymbolAddress((void**)&xn,  g_xn);
    cudaGetSymbolAddress((void**)&qkv, g_qkv);
    cudaGetSymbolAddress((void**)&o,   g_o);
    cudaGetSymbolAddress((void**)&y,   g_y);
    cudaGetSymbolAddress((void**)&yh,  g_yh);
    cudaGetSymbolAddress((void**)&t,   g_t);
    cudaGetSymbolAddress((void**)&cWqkvT, g_cWqkvT);
    cudaGetSymbolAddress((void**)&cWoT,   g_cWoT);
    cudaGetSymbolAddress((void**)&cWin,   g_cWin);
    cudaGetSymbolAddress((void**)&cWoutP, g_cWoutP);

    auto T_QKV = hgemm<128,128,32,64,32,2>;
    auto T_OP  = hgemm<128,128,32,64,32,4>;
    auto T_FFO = hgemm<128,128,32,64,32,1>;
    auto T_GG  = hgemm_geglu<128,64,32,64,16>;

    const int SM_G  = (3*128*40 + 3*128*40) * 2;     // 61440 B  (2 CTAs/SM)
    const int SM_GG = (3*128*40 + 6*64*40)  * 2;     // 61440 B

    cudaFuncSetAttribute(T_QKV, cudaFuncAttributeMaxDynamicSharedMemorySize, SM_G);
    cudaFuncSetAttribute(T_OP,  cudaFuncAttributeMaxDynamicSharedMemorySize, SM_G);
    cudaFuncSetAttribute(T_FFO, cudaFuncAttributeMaxDynamicSharedMemorySize, SM_G);
    cudaFuncSetAttribute(T_GG,  cudaFuncAttributeMaxDynamicSharedMemorySize, SM_GG);
    cudaFuncSetAttribute(flash_kernel, cudaFuncAttributeMaxDynamicSharedMemorySize, FA_BYTES);

    // 0) weight preconversion
    cvtT_kernel<<<dim3(32,32), dim3(32,8)>>>(Wq,  cWqkvT,                       DIMV, INNERV);
    cvtT_kernel<<<dim3(64,32), dim3(32,8)>>>(Wkv, cWqkvT + (size_t)INNERV*DIMV, DIMV, 2*INNERV);
    cvtT_kernel<<<dim3(32,32), dim3(32,8)>>>(Wo,  cWoT,  INNERV, DIMV);
    cvtH_kernel<<<512, 256>>>((const float4*)ff_w_in, (__half2*)cWin, 2*FFH*DIMV/4);
    cvt_pad_kernel<<<dim3((LDT+255)/256, DIMV), 256>>>(ff_w_out, cWoutP);

    // 1) CPB bias table (8 rel-positions per block)
    cpb_kernel<<<128, 512>>>(cpb_w1, cpb_b1, cpb_w2, cpb_b2, cpb_w3, cpb_b3, bias);

    // 2) sequence-axis LayerNorm (half out)
    seqln_kernel<<<dim3(DIMV / 256, BATCH), 256>>>(x, g_ln, xn);

    // 3) merged Q/K/V projection (N=3072)
    T_QKV<<<dim3(24,64),256,SM_G>>>(xn, cWqkvT, nullptr, qkv, nullptr,
        MROWS, 3*INNERV, DIMV, DIMV, DIMV, 0);

    // 4-6) fused flash attention
    flash_kernel<<<dim3(SEQ/128, BATCH*HEADS), 256, FA_BYTES>>>(
        qkv, qkv + (size_t)MROWS*INNERV, qkv + (size_t)2*MROWS*INNERV, bias, o);

    // 7) y = O @ Wo + x  (float y + half mirror)
    T_OP<<<dim3(8,64),256,SM_G>>>(o, cWoT, y, yh, x,
        MROWS, DIMV, INNERV, INNERV, INNERV, DIMV);

    // 8) FF-in + fused GEGLU (half out)
    T_GG<<<dim3((FFH+63)/64, 64),256,SM_GG>>>(yh, cWin, t,
        MROWS, FFH, DIMV, DIMV, LDT);

    // 9) channel LayerNorm (half, fp32 stats)
    chanln_kernel<<<MROWS, 256>>>(t, ff_g);

    // 10) out = t @ cWoutP^T + y  (fp32 residual add)
    T_FFO<<<dim3(8,64),256,SM_G>>>(t, cWoutP, out, nullptr, y,
        MROWS, DIMV, LDT, LDT, LDT, DIMV);
}

// round 16
// speedup vs baseline: 18.9907x; 1.0732x over previous
#include <cuda_runtime.h>
#include <cuda_fp16.h>
#include <math.h>
#include <stdint.h>

#define DIMV 1024
#define HEADS 16
#define DHEAD 64
#define BATCH 16
#define SEQ 512
#define INNERV 1024
#define CPBD 512
#define FFH 2730
#define LDT 2752            /* padded leading dim for t / cWout (halfs): 43*64 */
#define MROWS (BATCH*SEQ)   /* 8192 */
#define EPSV 1e-5f

// ---------------- scratch (static device arrays; no allocations) ----------------
__device__ float  g_bias[HEADS * 1023];
__device__ __half g_xn[(size_t)MROWS * DIMV];
__device__ __half g_qkv[(size_t)3 * MROWS * INNERV];   // q | k | v  ([b,h,n,d] each)
__device__ __half g_o[(size_t)MROWS * INNERV];
__device__ float  g_y[(size_t)MROWS * DIMV];           // fp32 residual copy
__device__ __half g_yh[(size_t)MROWS * DIMV];          // half mirror
__device__ __half g_t[(size_t)MROWS * LDT];
// half-preconverted weights ([n][k] layouts)
__device__ __half g_cWqkvT[(size_t)3 * INNERV * DIMV];
__device__ __half g_cWoT[(size_t)DIMV * INNERV];
__device__ __half g_cWin[(size_t)2 * FFH * DIMV];
__device__ __half g_cWoutP[(size_t)DIMV * LDT];

// ---------------- helpers ---------------------------------------------------------
__device__ __forceinline__ void mma_f16(float d[4], const uint32_t a[4], const uint32_t b[2]) {
    asm volatile(
        "mma.sync.aligned.m16n8k16.row.col.f32.f16.f16.f32 "
        "{%0,%1,%2,%3},{%4,%5,%6,%7},{%8,%9},{%0,%1,%2,%3};\n"
        : "+f"(d[0]), "+f"(d[1]), "+f"(d[2]), "+f"(d[3])
        : "r"(a[0]), "r"(a[1]), "r"(a[2]), "r"(a[3]), "r"(b[0]), "r"(b[1]));
}
__device__ __forceinline__ void ldsm4(uint32_t r[4], uint32_t saddr) {
    asm volatile("ldmatrix.sync.aligned.m8n8.x4.shared.b16 {%0,%1,%2,%3}, [%4];"
        : "=r"(r[0]), "=r"(r[1]), "=r"(r[2]), "=r"(r[3]) : "r"(saddr));
}
__device__ __forceinline__ void ldsm4t(uint32_t r[4], uint32_t saddr) {
    asm volatile("ldmatrix.sync.aligned.m8n8.x4.trans.shared.b16 {%0,%1,%2,%3}, [%4];"
        : "=r"(r[0]), "=r"(r[1]), "=r"(r[2]), "=r"(r[3]) : "r"(saddr));
}
__device__ __forceinline__ void cp16(uint32_t s, const void* g) {
    asm volatile("cp.async.cg.shared.global [%0], [%1], 16;\n" :: "r"(s), "l"(g));
}
__device__ __forceinline__ void cp_commit() { asm volatile("cp.async.commit_group;\n"); }
__device__ __forceinline__ void cp_wait1()  { asm volatile("cp.async.wait_group 1;\n"); }
__device__ __forceinline__ void cp_wait0()  { asm volatile("cp.async.wait_group 0;\n"); }
__device__ __forceinline__ float qmax2(float v) {
    v = fmaxf(v, __shfl_xor_sync(0xffffffffu, v, 1));
    v = fmaxf(v, __shfl_xor_sync(0xffffffffu, v, 2));
    return v;
}
__device__ __forceinline__ float qsum2(float v) {
    v += __shfl_xor_sync(0xffffffffu, v, 1);
    v += __shfl_xor_sync(0xffffffffu, v, 2);
    return v;
}

// ---------------- weight preconvert kernels ---------------------------------------
__global__ void cvtT_kernel(const float* __restrict__ in, __half* __restrict__ out,
                            int K, int N) {
    __shared__ float tile[32][33];
    int n0 = blockIdx.x * 32, k0 = blockIdx.y * 32;
    int tx = threadIdx.x, ty0 = threadIdx.y;
    #pragma unroll
    for (int ty = ty0; ty < 32; ty += 8)
        tile[ty][tx] = in[(size_t)(k0 + ty) * N + n0 + tx];
    __syncthreads();
    #pragma unroll
    for (int ty = ty0; ty < 32; ty += 8)
        out[(size_t)(n0 + ty) * K + k0 + tx] = __float2half(tile[tx][ty]);
}
__global__ void cvtH_kernel(const float4* __restrict__ in, __half2* __restrict__ out, int n4) {
    int i = blockIdx.x * blockDim.x + threadIdx.x;
    int stride = gridDim.x * blockDim.x;
    for (; i < n4; i += stride) {
        float4 v = in[i];
        out[2 * i]     = __floats2half2_rn(v.x, v.y);
        out[2 * i + 1] = __floats2half2_rn(v.z, v.w);
    }
}
__global__ void cvt_pad_kernel(const float* __restrict__ in, __half* __restrict__ out) {
    int r = blockIdx.y;
    int c = blockIdx.x * 256 + threadIdx.x;
    if (c < LDT) out[(size_t)r * LDT + c] =
        (c < FFH) ? __float2half(in[(size_t)r * FFH + c]) : __half(0.f);
}

// ---------------- CPB: 8 rel-positions per block ----------------------------------
#define CPB_R 8
__global__ void cpb_kernel(const float* __restrict__ w1, const float* __restrict__ b1,
                           const float* __restrict__ w2, const float* __restrict__ b2,
                           const float* __restrict__ w3, const float* __restrict__ b3,
                           float* __restrict__ table) {
    __shared__ float h1[CPB_R][CPBD];
    __shared__ float h2[CPB_R][CPBD];
    int t = threadIdx.x;
    int r0 = blockIdx.x * CPB_R;
    #pragma unroll
    for (int r = 0; r < CPB_R; r++) {
        int ridx = r0 + r;
        float rf = (float)(ridx - 511);
        float sgn = (rf > 0.f) ? 1.f : ((rf < 0.f) ? -1.f : 0.f);
        float rel = sgn * logf(fabsf(rf) + 1.f);
        float z = rel * w1[t] + b1[t];
        h1[r][t] = z / (1.f + expf(-z));
    }
    __syncthreads();
    float acc[CPB_R];
    #pragma unroll
    for (int r = 0; r < CPB_R; r++) acc[r] = b2[t];
    for (int j = 0; j < CPBD; j++) {
        float wv = w2[j * CPBD + t];
        #pragma unroll
        for (int r = 0; r < CPB_R; r++) acc[r] += h1[r][j] * wv;
    }
    #pragma unroll
    for (int r = 0; r < CPB_R; r++) {
        float z = acc[r];
        h2[r][t] = z / (1.f + expf(-z));
    }
    __syncthreads();
    int w = t >> 5, lane = t & 31;
    #pragma unroll
    for (int r = 0; r < CPB_R; r++) {
        float a2 = 0.f;
        #pragma unroll 4
        for (int i = lane; i < CPBD; i += 32) a2 += h2[r][i] * w3[i * HEADS + w];
        #pragma unroll
        for (int off = 16; off; off >>= 1) a2 += __shfl_down_sync(0xffffffffu, a2, off);
        int ridx = r0 + r;
        if (lane == 0 && ridx < 1023) table[w * 1023 + ridx] = a2 + b3[w];
    }
}

// ---------------- sequence-axis LayerNorm (fp32 stats, half out) ------------------
__global__ void seqln_kernel(const float* __restrict__ x, const float* __restrict__ g,
                             __half* __restrict__ xn) {
    int d = blockIdx.x * blockDim.x + threadIdx.x;
    int b = blockIdx.y;
    const float* xb = x + (size_t)b * SEQ * DIMV;
    float s = 0.f, ss = 0.f;
    for (int n = 0; n < SEQ; n++) { float v = xb[n * DIMV + d]; s += v; ss += v * v; }
    float mean = s * (1.f / SEQ);
    float var  = ss * (1.f / SEQ) - mean * mean;
    float inv  = rsqrtf(fmaxf(var, EPSV)) * g[d];
    __half* ob = xn + (size_t)b * SEQ * DIMV;
    for (int n = 0; n < SEQ; n++) ob[n * DIMV + d] = __float2half((xb[n * DIMV + d] - mean) * inv);
}

// ---------------- fused flash attention (fp16 mma + ldmatrix, fp32 softmax) -------
#define FA_ST  72
#define FA_QS  0
#define FA_KS  (FA_QS + 128*FA_ST)
#define FA_VS  (FA_KS + 2*64*FA_ST)
#define FA_PS  (FA_VS + 2*64*FA_ST)
#define FA_HEND (FA_PS + 8*16*FA_ST)
#define FA_BYTES (FA_HEND*2 + 1024*4)

__global__ __launch_bounds__(256, 2)
void flash_kernel(const __half* __restrict__ q, const __half* __restrict__ k,
                  const __half* __restrict__ v, const float* __restrict__ table,
                  __half* __restrict__ o) {
    extern __shared__ char smraw[];
    __half* smh = (__half*)smraw;
    float*  Bi  = (float*)(smraw + FA_HEND * 2);

    const int qt = blockIdx.x;
    const int z  = blockIdx.y;
    const int h  = z & (HEADS - 1);
    const int b  = z >> 4;
    const int qbase = qt * 128;
    const int tid = threadIdx.x;
    const int w = tid >> 5, lane = tid & 31;
    const int gid = lane >> 2, tg = lane & 3;

    const __half* qz = q + (size_t)z * SEQ * DHEAD;
    const __half* kz = k + (size_t)z * SEQ * DHEAD;
    const __half* vz = v + (size_t)z * SEQ * DHEAD;

    const uint32_t sbase = (uint32_t)__cvta_generic_to_shared(smh);

    const int aRowOff = ((lane & 15) * FA_ST) + (lane >> 4) * 8;
    const int kRowOff = (((lane & 7) + ((lane >> 4) & 1) * 8) * FA_ST) + ((lane >> 3) & 1) * 8;
    const int vRowOff = (((lane & 7) + ((lane >> 3) & 1) * 8) * FA_ST) + ((lane >> 4) & 1) * 8;

    #pragma unroll
    for (int c = tid; c < 128 * 8; c += 256) {
        int m = c >> 3, kc = c & 7;
        cp16(sbase + (uint32_t)((FA_QS + m * FA_ST + kc * 8) * 2),
             qz + (qbase + m) * DHEAD + kc * 8);
    }
    for (int i = tid; i < 1023; i += 256) Bi[i] = table[h * 1023 + i];

    auto stage_kv = [&](int buf, int jt) {
        int kb = jt * 64;
        #pragma unroll
        for (int c = tid; c < 64 * 8; c += 256) {
            int r = c >> 3, kc = c & 7;
            cp16(sbase + (uint32_t)((FA_KS + buf * 64 * FA_ST + r * FA_ST + kc * 8) * 2),
                 kz + (kb + r) * DHEAD + kc * 8);
            cp16(sbase + (uint32_t)((FA_VS + buf * 64 * FA_ST + r * FA_ST + kc * 8) * 2),
                 vz + (kb + r) * DHEAD + kc * 8);
        }
    };

    stage_kv(0, 0);
    cp_commit();

    float m_row[2] = {-1e30f, -1e30f};
    float l_row[2] = {0.f, 0.f};
    float oacc[8][4];
    #pragma unroll
    for (int j = 0; j < 8; j++)
        #pragma unroll
        for (int e = 0; e < 4; e++) oacc[j][e] = 0.f;

    __half* Ps = smh + FA_PS + w * 16 * FA_ST;
    const uint32_t qA = sbase + (uint32_t)((FA_QS + w * 16 * FA_ST + aRowOff) * 2);
    const uint32_t pA = sbase + (uint32_t)((FA_PS + w * 16 * FA_ST + aRowOff) * 2);

    int buf = 0;
    for (int jt = 0; jt < 8; jt++) {
        if (jt + 1 < 8) { stage_kv(buf ^ 1, jt + 1); cp_commit(); cp_wait1(); }
        else cp_wait0();
        __syncthreads();

        const uint32_t kB = sbase + (uint32_t)((FA_KS + buf * 64 * FA_ST + kRowOff) * 2);
        const uint32_t vB = sbase + (uint32_t)((FA_VS + buf * 64 * FA_ST + vRowOff) * 2);
        const int kb = jt * 64;

        float s[8][4];
        #pragma unroll
        for (int j = 0; j < 8; j++)
            #pragma unroll
            for (int e = 0; e < 4; e++) s[j][e] = 0.f;
        #pragma unroll
        for (int ks = 0; ks < 64; ks += 16) {
            uint32_t a[4];
            ldsm4(a, qA + (uint32_t)(ks * 2));
            #pragma unroll
            for (int jj = 0; jj < 4; jj++) {
                uint32_t bk[4];
                ldsm4(bk, kB + (uint32_t)((jj * 16 * FA_ST + ks) * 2));
                mma_f16(s[2 * jj],     a, &bk[0]);
                mma_f16(s[2 * jj + 1], a, &bk[2]);
            }
        }

        int qi0 = qbase + w * 16 + gid;
        float mx0 = -1e30f, mx1 = -1e30f;
        #pragma unroll
        for (int j = 0; j < 8; j++) {
            int kj = kb + j * 8 + 2 * tg;
            s[j][0] = s[j][0] * 0.125f + Bi[qi0 - kj + 511];
            s[j][1] = s[j][1] * 0.125f + Bi[qi0 - kj + 510];
            s[j][2] = s[j][2] * 0.125f + Bi[qi0 + 8 - kj + 511];
            s[j][3] = s[j][3] * 0.125f + Bi[qi0 + 8 - kj + 510];
            mx0 = fmaxf(mx0, fmaxf(s[j][0], s[j][1]));
            mx1 = fmaxf(mx1, fmaxf(s[j][2], s[j][3]));
        }
        mx0 = qmax2(mx0); mx1 = qmax2(mx1);
        float mn0 = fmaxf(m_row[0], mx0), mn1 = fmaxf(m_row[1], mx1);
        float sc0 = __expf(m_row[0] - mn0), sc1 = __expf(m_row[1] - mn1);
        float rs0 = 0.f, rs1 = 0.f;
        #pragma unroll
        for (int j = 0; j < 8; j++) {
            s[j][0] = __expf(s[j][0] - mn0);
            s[j][1] = __expf(s[j][1] - mn0);
            s[j][2] = __expf(s[j][2] - mn1);
            s[j][3] = __expf(s[j][3] - mn1);
            rs0 += s[j][0] + s[j][1];
            rs1 += s[j][2] + s[j][3];
        }
        rs0 = qsum2(rs0); rs1 = qsum2(rs1);
        l_row[0] = l_row[0] * sc0 + rs0;
        l_row[1] = l_row[1] * sc1 + rs1;
        m_row[0] = mn0; m_row[1] = mn1;
        #pragma unroll
        for (int j = 0; j < 8; j++) {
            oacc[j][0] *= sc0; oacc[j][1] *= sc0;
            oacc[j][2] *= sc1; oacc[j][3] *= sc1;
        }

        #pragma unroll
        for (int j = 0; j < 8; j++) {
            *(__half2*)&Ps[gid * FA_ST + j * 8 + 2 * tg]       = __floats2half2_rn(s[j][0], s[j][1]);
            *(__half2*)&Ps[(gid + 8) * FA_ST + j * 8 + 2 * tg] = __floats2half2_rn(s[j][2], s[j][3]);
        }
        __syncwarp();

        #pragma unroll
        for (int ks = 0; ks < 64; ks += 16) {
            uint32_t a[4];
            ldsm4(a, pA + (uint32_t)(ks * 2));
            #pragma unroll
            for (int jj = 0; jj < 4; jj++) {
                uint32_t bv[4];
                ldsm4t(bv, vB + (uint32_t)((ks * FA_ST + jj * 16) * 2));
                mma_f16(oacc[2 * jj],     a, &bv[0]);
                mma_f16(oacc[2 * jj + 1], a, &bv[2]);
            }
        }
        __syncwarp();
        __syncthreads();
        buf ^= 1;
    }

    float inv0 = 1.f / l_row[0], inv1 = 1.f / l_row[1];
    int qi = qbase + w * 16 + gid;
    #pragma unroll
    for (int j = 0; j < 8; j++) {
        int d = j * 8 + 2 * tg;
        size_t r0 = ((size_t)(b * SEQ + qi) * INNERV) + h * DHEAD + d;
        size_t r1 = ((size_t)(b * SEQ + qi + 8) * INNERV) + h * DHEAD + d;
        *(__half2*)&o[r0] = __floats2half2_rn(oacc[j][0] * inv0, oacc[j][1] * inv0);
        *(__half2*)&o[r1] = __floats2half2_rn(oacc[j][2] * inv1, oacc[j][3] * inv1);
    }
}

// ---------------- channel LayerNorm over FFH per token ----------------------------
__global__ void chanln_kernel(__half* __restrict__ tb, const float* __restrict__ gg) {
    int m = blockIdx.x;
    __half* row = tb + (size_t)m * LDT;
    int t = threadIdx.x;
    float s = 0.f, ss = 0.f;
    for (int j = t; j < FFH; j += 256) { float v = __half2float(row[j]); s += v; ss += v * v; }
    __shared__ float r1[256], r2[256];
    r1[t] = s; r2[t] = ss; __syncthreads();
    for (int k = 128; k; k >>= 1) { if (t < k) { r1[t] += r1[t + k]; r2[t] += r2[t + k]; } __syncthreads(); }
    float mean = r1[0] * (1.f / FFH);
    float var  = r2[0] * (1.f / FFH) - mean * mean;
    float inv  = rsqrtf(fmaxf(var, EPSV));
    for (int j = t; j < FFH; j += 256)
        row[j] = __float2half((__half2float(row[j]) - mean) * inv * gg[j]);
    if (t < LDT - FFH) row[FFH + t] = __half(0.f);
}

// ---------------- fp16 tensor-core GEMM, NT, ldmatrix, BK=64 dbl-buf, 2 CTA/SM ----
// EPI: 1 = Cf = v + R (float); 2 = merged-qkv head-split half store;
//      4 = y float + yh half
template<int BM, int BN, int BK, int WM, int WN, int EPI>
__global__ __launch_bounds__(256, 2)
void hgemm(const __half* __restrict__ A, const __half* __restrict__ B,
           float* __restrict__ Cf, __half* __restrict__ Ch, const float* __restrict__ R,
           int M, int Nn, int K, int lda, int ldb, int ldc) {
    constexpr int WARPS_N = BN / WN;
    constexpr int MT = WM / 16, NT = WN / 8;
    constexpr int AST = BK + 8;
    constexpr int BST = BK + 8;
    constexpr int ABUF = BM * AST;
    constexpr int BBUF = BN * BST;

    extern __shared__ char smraw[];
    __half* Asm = (__half*)smraw;
    __half* Bsm = Asm + 2 * ABUF;

    const int m0 = blockIdx.y * BM;
    const int n0 = blockIdx.x * BN;
    const int tid = threadIdx.x;
    const int warp = tid >> 5, lane = tid & 31;
    const int wr = warp / WARPS_N, wc = warp % WARPS_N;
    const int gid = lane >> 2, tg = lane & 3;

    const uint32_t sAb = (uint32_t)__cvta_generic_to_shared(Asm);
    const uint32_t sBb = (uint32_t)__cvta_generic_to_shared(Bsm);

    const int aRow  = wr * WM + (lane & 15);
    const int aKoff = (lane & 16) >> 1;
    const int bRow  = wc * WN + ((lane >> 4) & 1) * 8 + (lane & 7);
    const int bKoff = ((lane >> 3) & 1) * 8;

    float acc[MT][NT][4];
    #pragma unroll
    for (int i = 0; i < MT; i++)
        #pragma unroll
        for (int j = 0; j < NT; j++)
            #pragma unroll
            for (int e = 0; e < 4; e++) acc[i][j][e] = 0.f;

    const int NIT = K / BK;

    auto stage = [&](int b, int k0) {
        constexpr int ACH = BK / 8;
        #pragma unroll
        for (int c = tid; c < BM * ACH; c += 256) {
            int m = c / ACH, kc = c % ACH;
            cp16(sAb + (uint32_t)((b * ABUF + m * AST + kc * 8) * 2),
                 A + (size_t)(m0 + m) * lda + k0 + kc * 8);
        }
        constexpr int BCH = BK / 8;
        #pragma unroll
        for (int c = tid; c < BN * BCH; c += 256) {
            int n = c / BCH, kc = c % BCH;
            cp16(sBb + (uint32_t)((b * BBUF + n * BST + kc * 8) * 2),
                 B + (size_t)(n0 + n) * ldb + k0 + kc * 8);
        }
    };

    stage(0, 0);
    cp_commit();
    int buf = 0;
    for (int it = 0; it < NIT; it++) {
        if (it + 1 < NIT) { stage(buf ^ 1, (it + 1) * BK); cp_commit(); cp_wait1(); }
        else cp_wait0();
        __syncthreads();

        const uint32_t aB = sAb + (uint32_t)((buf * ABUF + aRow * AST + aKoff) * 2);
        const uint32_t bB = sBb + (uint32_t)((buf * BBUF + bRow * BST + bKoff) * 2);
        #pragma unroll
        for (int ks = 0; ks < BK; ks += 16) {
            uint32_t af[MT][4];
            uint32_t bf[NT / 2][4];
            #pragma unroll
            for (int i = 0; i < MT; i++)
                ldsm4(af[i], aB + (uint32_t)((i * 16 * AST + ks) * 2));
            #pragma unroll
            for (int jj = 0; jj < NT / 2; jj++)
                ldsm4(bf[jj], bB + (uint32_t)((jj * 16 * BST + ks) * 2));
            #pragma unroll
            for (int i = 0; i < MT; i++)
                #pragma unroll
                for (int jj = 0; jj < NT / 2; jj++) {
                    mma_f16(acc[i][2 * jj],     af[i], &bf[jj][0]);
                    mma_f16(acc[i][2 * jj + 1], af[i], &bf[jj][2]);
                }
        }
        __syncthreads();
        buf ^= 1;
    }

    #pragma unroll
    for (int i = 0; i < MT; i++) {
        #pragma unroll
        for (int j = 0; j < NT; j++) {
            int m_lo = m0 + wr * WM + i * 16 + gid;
            int n_e  = n0 + wc * WN + j * 8 + 2 * tg;
            if (EPI == 2) {
                #pragma unroll
                for (int half_i = 0; half_i < 2; half_i++) {
                    int m = m_lo + half_i * 8;
                    if (m < M && n_e + 1 < Nn) {
                        int which = n_e >> 10;
                        int nn2 = n_e & 1023;
                        int hh = nn2 >> 6, d = nn2 & (DHEAD - 1);
                        int bb = m >> 9, sq = m & (SEQ - 1);
                        __half2 hv = __floats2half2_rn(acc[i][j][2 * half_i], acc[i][j][2 * half_i + 1]);
                        *(__half2*)&Ch[(size_t)which * MROWS * INNERV +
                                       ((((size_t)bb * HEADS + hh) * SEQ + sq) << 6) + d] = hv;
                    }
                }
            } else {
                #pragma unroll
                for (int e = 0; e < 4; e++) {
                    int m = m_lo + ((e >= 2) ? 8 : 0);
                    int n = n_e + (e & 1);
                    if (m < M && n < Nn) {
                        float v = acc[i][j][e];
                        if (EPI == 1) {
                            Cf[(size_t)m * ldc + n] = v + R[(size_t)m * ldc + n];
                        } else { // EPI == 4
                            float r = v + R[(size_t)m * ldc + n];
                            Cf[(size_t)m * ldc + n] = r;
                            Ch[(size_t)m * ldc + n] = __float2half(r);
                        }
                    }
                }
            }
        }
    }
}

// ---------------- fp16 GEGLU GEMM (two NT B tiles), BK=64 dbl-buf, 2 CTA/SM -------
template<int BM, int BN, int BK, int WM, int WN>
__global__ __launch_bounds__(256, 2)
void hgemm_geglu(const __half* __restrict__ A, const __half* __restrict__ B,
                 __half* __restrict__ C, int M, int Nn, int K, int ldb, int ldc) {
    constexpr int WARPS_N = BN / WN;
    constexpr int MT = WM / 16, NT = WN / 8;
    constexpr int AST = BK + 8;
    constexpr int BST = BK + 8;
    constexpr int ABUF = BM * AST;
    constexpr int BBUF = BN * BST;

    extern __shared__ char smraw[];
    __half* Asm = (__half*)smraw;
    __half* B1m = Asm + 2 * ABUF;
    __half* B2m = B1m + 2 * BBUF;

    const int m0 = blockIdx.y * BM;
    const int n0 = blockIdx.x * BN;
    const int tid = threadIdx.x;
    const int warp = tid >> 5, lane = tid & 31;
    const int wr = warp / WARPS_N, wc = warp % WARPS_N;
    const int gid = lane >> 2, tg = lane & 3;

    const uint32_t sAb = (uint32_t)__cvta_generic_to_shared(Asm);
    const uint32_t sB1 = (uint32_t)__cvta_generic_to_shared(B1m);
    const uint32_t sB2 = (uint32_t)__cvta_generic_to_shared(B2m);

    const int aRow  = wr * WM + (lane & 15);
    const int aKoff = (lane & 16) >> 1;
    const int bRow  = wc * WN + ((lane >> 4) & 1) * 8 + (lane & 7);
    const int bKoff = ((lane >> 3) & 1) * 8;

    float a1[MT][NT][4], a2[MT][NT][4];
    #pragma unroll
    for (int i = 0; i < MT; i++)
        #pragma unroll
        for (int j = 0; j < NT; j++)
            #pragma unroll
            for (int e = 0; e < 4; e++) { a1[i][j][e] = 0.f; a2[i][j][e] = 0.f; }

    const int NIT = K / BK;

    auto stage = [&](int b, int k0) {
        constexpr int ACH = BK / 8;
        #pragma unroll
        for (int c = tid; c < BM * ACH; c += 256) {
            int m = c / ACH, kc = c % ACH;
            cp16(sAb + (uint32_t)((b * ABUF + m * AST + kc * 8) * 2),
                 A + (size_t)(m0 + m) * K + k0 + kc * 8);
        }
        constexpr int BCH = BK / 8;
        #pragma unroll
        for (int c = tid; c < BN * BCH; c += 256) {
            int n = c / BCH, kc = c % BCH;
            int gn = n0 + n; if (gn > FFH - 1) gn = FFH - 1;
            uint32_t off = (uint32_t)((b * BBUF + n * BST + kc * 8) * 2);
            cp16(sB1 + off, B + (size_t)gn * ldb + k0 + kc * 8);
            cp16(sB2 + off, B + (size_t)(gn + FFH) * ldb + k0 + kc * 8);
        }
    };

    stage(0, 0);
    cp_commit();
    int buf = 0;
    for (int it = 0; it < NIT; it++) {
        if (it + 1 < NIT) { stage(buf ^ 1, (it + 1) * BK); cp_commit(); cp_wait1(); }
        else cp_wait0();
        __syncthreads();

        const uint32_t aB  = sAb + (uint32_t)((buf * ABUF + aRow * AST + aKoff) * 2);
        const uint32_t bB1 = sB1 + (uint32_t)((buf * BBUF + bRow * BST + bKoff) * 2);
        const uint32_t bB2 = sB2 + (uint32_t)((buf * BBUF + bRow * BST + bKoff) * 2);
        #pragma unroll
        for (int ks = 0; ks < BK; ks += 16) {
            uint32_t af[MT][4];
            uint32_t bf1[NT / 2][4], bf2[NT / 2][4];
            #pragma unroll
            for (int i = 0; i < MT; i++)
                ldsm4(af[i], aB + (uint32_t)((i * 16 * AST + ks) * 2));
            #pragma unroll
            for (int jj = 0; jj < NT / 2; jj++) {
                ldsm4(bf1[jj], bB1 + (uint32_t)((jj * 16 * BST + ks) * 2));
                ldsm4(bf2[jj], bB2 + (uint32_t)((jj * 16 * BST + ks) * 2));
            }
            #pragma unroll
            for (int i = 0; i < MT; i++)
                #pragma unroll
                for (int jj = 0; jj < NT / 2; jj++) {
                    mma_f16(a1[i][2 * jj],     af[i], &bf1[jj][0]);
                    mma_f16(a1[i][2 * jj + 1], af[i], &bf1[jj][2]);
                    mma_f16(a2[i][2 * jj],     af[i], &bf2[jj][0]);
                    mma_f16(a2[i][2 * jj + 1], af[i], &bf2[jj][2]);
                }
        }
        __syncthreads();
        buf ^= 1;
    }

    #pragma unroll
    for (int i = 0; i < MT; i++) {
        #pragma unroll
        for (int j = 0; j < NT; j++) {
            #pragma unroll
            for (int e = 0; e < 4; e++) {
                int m = m0 + wr * WM + i * 16 + gid + ((e >= 2) ? 8 : 0);
                int n = n0 + wc * WN + j * 8 + 2 * tg + (e & 1);
                if (m < M && n < Nn) {
                    float g  = a2[i][j][e];
                    float ge = 0.5f * g * (1.f + erff(g * 0.70710678118654752f));
                    C[(size_t)m * ldc + n] = __float2half(a1[i][j][e] * ge);
                }
            }
        }
    }
}

// ---------------- launch ---------------------------------------------------------
extern "C" void kernel_launch(void* const* d_in, const int* in_sizes, int n_in,
                              void* d_out, int out_size) {
    const float* x      = (const float*)d_in[0];
    const float* g_ln   = (const float*)d_in[1];
    const float* Wq     = (const float*)d_in[2];
    const float* Wkv    = (const float*)d_in[3];
    const float* Wo     = (const float*)d_in[4];
    const float* cpb_w1 = (const float*)d_in[5];
    const float* cpb_b1 = (const float*)d_in[6];
    const float* cpb_w2 = (const float*)d_in[7];
    const float* cpb_b2 = (const float*)d_in[8];
    const float* cpb_w3 = (const float*)d_in[9];
    const float* cpb_b3 = (const float*)d_in[10];
    const float* ff_w_in  = (const float*)d_in[11];
    const float* ff_g     = (const float*)d_in[12];
    const float* ff_w_out = (const float*)d_in[13];
    float* out = (float*)d_out;

    float *bias, *y;
    __half *xn, *qkv, *o, *yh, *t;
    __half *cWqkvT, *cWoT, *cWin, *cWoutP;
    cudaGetSymbolAddress((void**)&bias, g_bias);
    cudaGetSymbolAddress((void**)&xn,  g_xn);
    cudaGetSymbolAddress((void**)&qkv, g_qkv);
    cudaGetSymbolAddress((void**)&o,   g_o);
    cudaGetSymbolAddress((void**)&y,   g_y);
    cudaGetSymbolAddress((void**)&yh,  g_yh);
    cudaGetSymbolAddress((void**)&t,   g_t);
    cudaGetSymbolAddress((void**)&cWqkvT, g_cWqkvT);
    cudaGetSymbolAddress((void**)&cWoT,   g_cWoT);
    cudaGetSymbolAddress((void**)&cWin,   g_cWin);
    cudaGetSymbolAddress((void**)&cWoutP, g_cWoutP);

    auto T_QKV = hgemm<128,128,64,64,32,2>;
    auto T_OP  = hgemm<128,128,64,64,32,4>;
    auto T_FFO = hgemm<128,128,64,64,32,1>;
    auto T_GG  = hgemm_geglu<128,64,64,64,16>;

    const int SM_G  = (2*128*72 + 2*128*72) * 2;     // 73728 B (2 CTAs/SM = 147 KB)
    const int SM_GG = (2*128*72 + 4*64*72)  * 2;     // 73728 B

    cudaFuncSetAttribute(T_QKV, cudaFuncAttributeMaxDynamicSharedMemorySize, SM_G);
    cudaFuncSetAttribute(T_OP,  cudaFuncAttributeMaxDynamicSharedMemorySize, SM_G);
    cudaFuncSetAttribute(T_FFO, cudaFuncAttributeMaxDynamicSharedMemorySize, SM_G);
    cudaFuncSetAttribute(T_GG,  cudaFuncAttributeMaxDynamicSharedMemorySize, SM_GG);
    cudaFuncSetAttribute(flash_kernel, cudaFuncAttributeMaxDynamicSharedMemorySize, FA_BYTES);

    // 0) weight preconversion
    cvtT_kernel<<<dim3(32,32), dim3(32,8)>>>(Wq,  cWqkvT,                       DIMV, INNERV);
    cvtT_kernel<<<dim3(64,32), dim3(32,8)>>>(Wkv, cWqkvT + (size_t)INNERV*DIMV, DIMV, 2*INNERV);
    cvtT_kernel<<<dim3(32,32), dim3(32,8)>>>(Wo,  cWoT,  INNERV, DIMV);
    cvtH_kernel<<<512, 256>>>((const float4*)ff_w_in, (__half2*)cWin, 2*FFH*DIMV/4);
    cvt_pad_kernel<<<dim3((LDT+255)/256, DIMV), 256>>>(ff_w_out, cWoutP);

    // 1) CPB bias table (8 rel-positions per block)
    cpb_kernel<<<128, 512>>>(cpb_w1, cpb_b1, cpb_w2, cpb_b2, cpb_w3, cpb_b3, bias);

    // 2) sequence-axis LayerNorm (half out)
    seqln_kernel<<<dim3(DIMV / 256, BATCH), 256>>>(x, g_ln, xn);

    // 3) merged Q/K/V projection (N=3072)
    T_QKV<<<dim3(24,64),256,SM_G>>>(xn, cWqkvT, nullptr, qkv, nullptr,
        MROWS, 3*INNERV, DIMV, DIMV, DIMV, 0);

    // 4-6) fused flash attention (2 CTAs/SM)
    flash_kernel<<<dim3(SEQ/128, BATCH*HEADS), 256, FA_BYTES>>>(
        qkv, qkv + (size_t)MROWS*INNERV, qkv + (size_t)2*MROWS*INNERV, bias, o);

    // 7) y = O @ Wo + x  (float y + half mirror)
    T_OP<<<dim3(8,64),256,SM_G>>>(o, cWoT, y, yh, x,
        MROWS, DIMV, INNERV, INNERV, INNERV, DIMV);

    // 8) FF-in + fused GEGLU (half out)
    T_GG<<<dim3((FFH+63)/64, 64),256,SM_GG>>>(yh, cWin, t,
        MROWS, FFH, DIMV, DIMV, LDT);

    // 9) channel LayerNorm (half, fp32 stats)
    chanln_kernel<<<MROWS, 256>>>(t, ff_g);

    // 10) out = t @ cWoutP^T + y  (fp32 residual add)
    T_FFO<<<dim3(8,64),256,SM_G>>>(t, cWoutP, out, nullptr, y,
        MROWS, DIMV, LDT, LDT, LDT, DIMV);
}